// round 8
// baseline (speedup 1.0000x reference)
#include <cuda_runtime.h>
#include <cuda_bf16.h>
#include <cstdint>
#include <cstddef>

// Problem dims
constexpr int BB = 16, CC = 24, SS = 128, EE = 256, HH = 8, PP = 32;
constexpr int NTOT  = BB * CC * SS * EE;     // 12,582,912
constexpr int NROWS = BB * CC * SS;          // 49,152
constexpr int WELEMS = CC * EE * EE;         // 1,572,864 per weight
constexpr int NW = 10;
constexpr float LN_EPS = 1e-6f;
constexpr float INV_SQRT_P = 0.17677669529663687f;

// ---------------------------------------------------------------------------
// Device scratch.  The six former fp32 q/k/v buffers are re-used as bf16
// hi/lo PAIRS (hi at [0,NTOT), lo at [NTOT,2*NTOT) bf16 elements) — same bytes.
// ---------------------------------------------------------------------------
__device__ __align__(16) float g_qs[NTOT], g_ks[NTOT], g_vs[NTOT];
__device__ __align__(16) float g_qt[NTOT], g_kt[NTOT], g_vt[NTOT];
__device__ float g_spat[NTOT], g_temp[NTOT], g_attn[NTOT], g_ffo[NTOT];
__device__ __align__(16) __nv_bfloat16 g_xh[NTOT], g_xl[NTOT];
__device__ __align__(16) __nv_bfloat16 g_ah[NTOT], g_al[NTOT];   // spatial-out / attn pair
__device__ __align__(16) __nv_bfloat16 g_hh[NTOT], g_hl[NTOT];   // temporal-out / ff hidden pair
__device__ __align__(16) __nv_bfloat16 g_wh[NW * WELEMS], g_wl[NW * WELEMS];

// ---------------------------------------------------------------------------
// PTX helpers (baseline ISA only)
// ---------------------------------------------------------------------------
__device__ __forceinline__ uint32_t smem_u32(const void* p) {
    uint32_t a;
    asm("{ .reg .u64 t; cvta.to.shared.u64 t, %1; cvt.u32.u64 %0, t; }"
        : "=r"(a) : "l"(p));
    return a;
}
__device__ __forceinline__ void cp_async16(uint32_t smem, const void* gmem) {
    asm volatile("cp.async.cg.shared.global [%0], [%1], 16;"
                 :: "r"(smem), "l"(gmem));
}
__device__ __forceinline__ void cp_commit() {
    asm volatile("cp.async.commit_group;");
}
template <int N>
__device__ __forceinline__ void cp_wait() {
    asm volatile("cp.async.wait_group %0;" :: "n"(N) : "memory");
}
__device__ __forceinline__ void ldsm_x4(uint32_t& r0, uint32_t& r1,
                                        uint32_t& r2, uint32_t& r3, uint32_t addr) {
    asm volatile("ldmatrix.sync.aligned.m8n8.x4.shared.b16 {%0,%1,%2,%3}, [%4];"
                 : "=r"(r0), "=r"(r1), "=r"(r2), "=r"(r3) : "r"(addr));
}
__device__ __forceinline__ void mma_bf16(float* d, const uint32_t* a,
                                         uint32_t b0, uint32_t b1) {
    asm volatile(
        "mma.sync.aligned.m16n8k16.row.col.f32.bf16.bf16.f32 "
        "{%0,%1,%2,%3}, {%4,%5,%6,%7}, {%8,%9}, {%0,%1,%2,%3};"
        : "+f"(d[0]), "+f"(d[1]), "+f"(d[2]), "+f"(d[3])
        : "r"(a[0]), "r"(a[1]), "r"(a[2]), "r"(a[3]), "r"(b0), "r"(b1));
}
// packed f32x2
__device__ __forceinline__ unsigned long long pack2(float v) {
    unsigned long long r;
    asm("mov.b64 %0, {%1, %1};" : "=l"(r) : "f"(v));
    return r;
}
__device__ __forceinline__ void fma2(unsigned long long& d,
                                     unsigned long long a, unsigned long long b) {
    asm("fma.rn.f32x2 %0, %1, %2, %0;" : "+l"(d) : "l"(a), "l"(b));
}
__device__ __forceinline__ float2 unpack2(unsigned long long v) {
    float2 f;
    asm("mov.b64 {%0, %1}, %2;" : "=f"(f.x), "=f"(f.y) : "l"(v));
    return f;
}

// ---------------------------------------------------------------------------
// bf16 hi/lo split helpers
// ---------------------------------------------------------------------------
__device__ __forceinline__ void split_bf16(float x, __nv_bfloat16& h, __nv_bfloat16& l) {
    h = __float2bfloat16_rn(x);
    l = __float2bfloat16_rn(x - __bfloat162float(h));
}
// reconstruct 8 floats from hi/lo uint4 pair
__device__ __forceinline__ void pair_to_f32x8(uint4 h, uint4 l, float* o) {
    const __nv_bfloat162* hp = (const __nv_bfloat162*)&h;
    const __nv_bfloat162* lp = (const __nv_bfloat162*)&l;
#pragma unroll
    for (int i = 0; i < 4; ++i) {
        float2 hf = __bfloat1622float2(hp[i]);
        float2 lf = __bfloat1622float2(lp[i]);
        o[i * 2 + 0] = hf.x + lf.x;
        o[i * 2 + 1] = hf.y + lf.y;
    }
}

__global__ __launch_bounds__(256) void split_f32_kernel(
    const float* __restrict__ src, __nv_bfloat16* __restrict__ hi,
    __nv_bfloat16* __restrict__ lo, int n4)
{
    int i = blockIdx.x * 256 + threadIdx.x;
    if (i >= n4) return;
    float4 v = ((const float4*)src)[i];
    float vv[4] = {v.x, v.y, v.z, v.w};
    __nv_bfloat16 h[4], l[4];
#pragma unroll
    for (int j = 0; j < 4; ++j) split_bf16(vv[j], h[j], l[j]);
    __nv_bfloat162* hp = (__nv_bfloat162*)hi;
    __nv_bfloat162* lp = (__nv_bfloat162*)lo;
    hp[i * 2 + 0] = __halves2bfloat162(h[0], h[1]);
    hp[i * 2 + 1] = __halves2bfloat162(h[2], h[3]);
    lp[i * 2 + 0] = __halves2bfloat162(l[0], l[1]);
    lp[i * 2 + 1] = __halves2bfloat162(l[2], l[3]);
}

// ---------------------------------------------------------------------------
// Weight conversion, coalesced: 32x32 (e,f) tiles via smem transpose.
// ---------------------------------------------------------------------------
struct WPtrs { const float* p[NW]; };

__global__ __launch_bounds__(256) void convert_weights_t(
    WPtrs wp, __nv_bfloat16* __restrict__ wh, __nv_bfloat16* __restrict__ wl)
{
    __shared__ float tile[32][33];
    const int w = blockIdx.z, c = blockIdx.y;
    const int eb = blockIdx.x & 7, fb = blockIdx.x >> 3;
    const int mode = (w == 3 || w >= 7) ? 0 : (w == 0 ? 1 : (w <= 2 ? 2 : 3));
    const int t = threadIdx.x;
    const int col = t & 31, r0 = t >> 5;
    const float* W = wp.p[w];

#pragma unroll
    for (int i = 0; i < 4; ++i) {
        const int row = r0 + i * 8;
        float v;
        if (mode == 0) {
            const int e = eb * 32 + row, f = fb * 32 + col;
            v = W[((size_t)c * EE + e) * EE + f];
        } else if (mode == 1) {
            const int f = fb * 32 + row, e = eb * 32 + col;
            const int h = fb, p = f & 31;
            v = W[(((size_t)h * CC + c) * PP + p) * EE + e];
        } else if (mode == 2) {
            const int e = eb * 32 + row, p = col, h = fb;
            v = W[((size_t)h * EE + e) * PP + p];
        } else {
            const int e = eb * 32 + row, p = col, h = fb;
            v = W[(((size_t)h * CC + c) * EE + e) * PP + p];
        }
        tile[row][col] = v;
    }
    __syncthreads();

#pragma unroll
    for (int i = 0; i < 4; ++i) {
        const int fr = r0 + i * 8;
        const int f = fb * 32 + fr;
        const int e = eb * 32 + col;
        const float v = (mode == 1) ? tile[fr][col] : tile[col][fr];
        __nv_bfloat16 hi, lo;
        split_bf16(v, hi, lo);
        const size_t o = (size_t)w * WELEMS + ((size_t)c << 16) + (size_t)f * EE + e;
        wh[o] = hi;
        wl[o] = lo;
    }
}

// ---------------------------------------------------------------------------
// Fused QKVx6 GEMM (A resident, 48 streamed B stages, triple-buffered).
// Outputs bf16 hi/lo PAIRS.
// ---------------------------------------------------------------------------
constexpr int AP = 528;
constexpr int QA_HI = 0;
constexpr int QA_LO = 128 * AP;
constexpr int QB0   = 2 * 128 * AP;
constexpr int QB_STG = 20480;
constexpr int QKV_SMEM = QB0 + 3 * QB_STG;

constexpr int GP = 80;

struct Out6 { __nv_bfloat16 *h[6], *l[6]; };

__global__ __launch_bounds__(256) void gemm_qkv6(
    const __nv_bfloat16* __restrict__ xh, const __nv_bfloat16* __restrict__ xl,
    const __nv_bfloat16* __restrict__ whB, const __nv_bfloat16* __restrict__ wlB,
    Out6 outs)
{
    extern __shared__ __align__(16) char dsm[];
    const uint32_t sbase = smem_u32(dsm);
    const int tid = threadIdx.x;
    const int wid = tid >> 5, lane = tid & 31;
    const int b = blockIdx.x, nb = blockIdx.y, c = blockIdx.z;

    const size_t abase = ((size_t)b * CC + c) * SS * EE;

#pragma unroll
    for (int i = 0; i < 16; ++i) {
        const int t2 = tid + i * 256;
        const int row = t2 >> 5, ch = t2 & 31;
        const size_t goff = (size_t)row * EE + ch * 8;
        const uint32_t so = row * AP + ch * 16;
        cp_async16(sbase + QA_HI + so, xh + abase + goff);
        cp_async16(sbase + QA_LO + so, xl + abase + goff);
    }
    cp_commit();

    auto issueB = [&](int stage) {
        const int w = stage >> 3, kb = (stage & 7) * 32;
        const int wg = w + (w >= 3);
        const __nv_bfloat16* Wh = whB + (size_t)wg * WELEMS + ((size_t)c << 16)
                                + (size_t)nb * 128 * EE;
        const __nv_bfloat16* Wl = wlB + (size_t)wg * WELEMS + ((size_t)c << 16)
                                + (size_t)nb * 128 * EE;
        const uint32_t sb = sbase + QB0 + (stage % 3) * QB_STG;
#pragma unroll
        for (int j = 0; j < 2; ++j) {
            const int t2 = tid + j * 256;
            const int row = t2 >> 2, ch = t2 & 3;
            const size_t goff = (size_t)row * EE + kb + ch * 8;
            const uint32_t so = row * GP + ch * 16;
            cp_async16(sb + so, Wh + goff);
            cp_async16(sb + 10240 + so, Wl + goff);
        }
    };
    issueB(0); cp_commit();
    issueB(1); cp_commit();
    issueB(2); cp_commit();

    const int wm = wid & 3, wn = wid >> 2;
    const int g = lane >> 3, lr = lane & 7;

    for (int w = 0; w < 6; ++w) {
        float acc[2][8][4];
#pragma unroll
        for (int mi = 0; mi < 2; ++mi)
#pragma unroll
            for (int nj = 0; nj < 8; ++nj)
#pragma unroll
                for (int r = 0; r < 4; ++r) acc[mi][nj][r] = 0.f;

        for (int it = 0; it < 8; ++it) {
            const int stage = w * 8 + it;
            cp_wait<2>();
            __syncthreads();
            const uint32_t Bst = sbase + QB0 + (stage % 3) * QB_STG;

#pragma unroll
            for (int pass = 0; pass < 3; ++pass) {
                const uint32_t Ab = sbase + (pass == 2 ? QA_LO : QA_HI);
                const uint32_t Bb = Bst + (pass == 1 ? 10240 : 0);
#pragma unroll
                for (int k16 = 0; k16 < 2; ++k16) {
                    uint32_t afr[2][4];
#pragma unroll
                    for (int mi = 0; mi < 2; ++mi) {
                        const int row = wm * 32 + mi * 16 + ((g & 1) << 3) + lr;
                        const uint32_t addr =
                            Ab + row * AP + (it * 4 + k16 * 2 + (g >> 1)) * 16;
                        ldsm_x4(afr[mi][0], afr[mi][1], afr[mi][2], afr[mi][3], addr);
                    }
                    uint32_t bfr[4][4];
#pragma unroll
                    for (int ni = 0; ni < 4; ++ni) {
                        const int row = wn * 64 + ni * 16 + ((g >> 1) << 3) + lr;
                        const uint32_t addr = Bb + row * GP + (k16 * 2 + (g & 1)) * 16;
                        ldsm_x4(bfr[ni][0], bfr[ni][1], bfr[ni][2], bfr[ni][3], addr);
                    }
#pragma unroll
                    for (int mi = 0; mi < 2; ++mi)
#pragma unroll
                        for (int nj = 0; nj < 8; ++nj)
                            mma_bf16(acc[mi][nj], afr[mi],
                                     bfr[nj >> 1][(nj & 1) * 2],
                                     bfr[nj >> 1][(nj & 1) * 2 + 1]);
                }
            }
            __syncthreads();
            if (stage + 3 < 48) issueB(stage + 3);
            cp_commit();
        }

        // epilogue: bf16 hi/lo pair
        __nv_bfloat16* Yh = outs.h[w];
        __nv_bfloat16* Yl = outs.l[w];
#pragma unroll
        for (int mi = 0; mi < 2; ++mi)
#pragma unroll
            for (int rr = 0; rr < 2; ++rr) {
                const int m = wm * 32 + mi * 16 + (lane >> 2) + rr * 8;
                const size_t yrow = abase + (size_t)m * EE + nb * 128;
#pragma unroll
                for (int nj = 0; nj < 8; ++nj) {
                    const int colo = wn * 64 + nj * 8 + (lane & 3) * 2;
                    const float v0 = acc[mi][nj][rr * 2 + 0];
                    const float v1 = acc[mi][nj][rr * 2 + 1];
                    __nv_bfloat16 h0, l0, h1, l1;
                    split_bf16(v0, h0, l0);
                    split_bf16(v1, h1, l1);
                    *(__nv_bfloat162*)(Yh + yrow + colo) = __halves2bfloat162(h0, h1);
                    *(__nv_bfloat162*)(Yl + yrow + colo) = __halves2bfloat162(l0, l1);
                }
            }
    }
}

// ---------------------------------------------------------------------------
// Generic HMMA GEMM body: 128x128, 2-stage cp.async, 2 CTAs/SM.
// ---------------------------------------------------------------------------
constexpr int T_A_HI = 0;
constexpr int T_A_LO = 128 * GP;
constexpr int T_B_HI = 2 * 128 * GP;
constexpr int T_B_LO = 3 * 128 * GP;
constexpr int STAGE  = 4 * 128 * GP;          // 40960
constexpr int GEMM_SMEM = 2 * STAGE;          // 81920

template <int EPI>
__device__ __forceinline__ void gemm_body(
    const __nv_bfloat16* __restrict__ Ah, const __nv_bfloat16* __restrict__ Al,
    const __nv_bfloat16* __restrict__ Wh, const __nv_bfloat16* __restrict__ Wl,
    const float* __restrict__ bias,
    float* __restrict__ Yf,
    __nv_bfloat16* __restrict__ Yh, __nv_bfloat16* __restrict__ Yl,
    int b, int nb, int c, uint32_t sbase)
{
    const int tid = threadIdx.x;
    const int wid = tid >> 5, lane = tid & 31;

    const size_t abase = ((size_t)b * CC + c) * SS * EE;
    const size_t wbase = (size_t)c * EE * EE + (size_t)nb * 128 * EE;

    auto issue = [&](int stg) {
        const int kb = stg * 32;
        const uint32_t sb = sbase + (stg & 1) * STAGE;
#pragma unroll
        for (int j = 0; j < 2; ++j) {
            const int t2 = tid + j * 256;
            const int row = t2 >> 2, ch = t2 & 3;
            const size_t goff = (size_t)row * EE + kb + ch * 8;
            const uint32_t so = row * GP + ch * 16;
            cp_async16(sb + T_A_HI + so, Ah + abase + goff);
            cp_async16(sb + T_A_LO + so, Al + abase + goff);
            cp_async16(sb + T_B_HI + so, Wh + wbase + goff);
            cp_async16(sb + T_B_LO + so, Wl + wbase + goff);
        }
    };
    issue(0); cp_commit();
    issue(1); cp_commit();

    const int wm = wid & 3, wn = wid >> 2;
    const int g = lane >> 3, lr = lane & 7;

    float acc[2][8][4];
#pragma unroll
    for (int mi = 0; mi < 2; ++mi)
#pragma unroll
        for (int nj = 0; nj < 8; ++nj)
#pragma unroll
            for (int r = 0; r < 4; ++r) acc[mi][nj][r] = 0.f;

    for (int it = 0; it < 8; ++it) {
        cp_wait<1>();
        __syncthreads();
        const uint32_t st = sbase + (it & 1) * STAGE;

#pragma unroll
        for (int pass = 0; pass < 3; ++pass) {
            const uint32_t Ab = st + (pass == 2 ? T_A_LO : T_A_HI);
            const uint32_t Bb = st + (pass == 1 ? T_B_LO : T_B_HI);
#pragma unroll
            for (int k16 = 0; k16 < 2; ++k16) {
                uint32_t afr[2][4];
#pragma unroll
                for (int mi = 0; mi < 2; ++mi) {
                    const int row = wm * 32 + mi * 16 + ((g & 1) << 3) + lr;
                    const uint32_t addr = Ab + row * GP + (k16 * 2 + (g >> 1)) * 16;
                    ldsm_x4(afr[mi][0], afr[mi][1], afr[mi][2], afr[mi][3], addr);
                }
                uint32_t bfr[4][4];
#pragma unroll
                for (int ni = 0; ni < 4; ++ni) {
                    const int row = wn * 64 + ni * 16 + ((g >> 1) << 3) + lr;
                    const uint32_t addr = Bb + row * GP + (k16 * 2 + (g & 1)) * 16;
                    ldsm_x4(bfr[ni][0], bfr[ni][1], bfr[ni][2], bfr[ni][3], addr);
                }
#pragma unroll
                for (int mi = 0; mi < 2; ++mi)
#pragma unroll
                    for (int nj = 0; nj < 8; ++nj)
                        mma_bf16(acc[mi][nj], afr[mi],
                                 bfr[nj >> 1][(nj & 1) * 2],
                                 bfr[nj >> 1][(nj & 1) * 2 + 1]);
            }
        }
        __syncthreads();
        if (it + 2 < 8) issue(it + 2);
        cp_commit();
    }

#pragma unroll
    for (int mi = 0; mi < 2; ++mi) {
#pragma unroll
        for (int rr = 0; rr < 2; ++rr) {
            const int m = wm * 32 + mi * 16 + (lane >> 2) + rr * 8;
            const size_t yrow = abase + (size_t)m * EE + nb * 128;
#pragma unroll
            for (int nj = 0; nj < 8; ++nj) {
                const int col = wn * 64 + nj * 8 + (lane & 3) * 2;
                float v0 = acc[mi][nj][rr * 2 + 0];
                float v1 = acc[mi][nj][rr * 2 + 1];
                if constexpr (EPI == 0) {
                    *(float2*)(Yf + yrow + col) = make_float2(v0, v1);
                } else {
                    const float* bp = bias + (size_t)c * EE + nb * 128 + col;
                    v0 += bp[0];
                    v1 += bp[1];
                    if constexpr (EPI == 1) {
                        v0 = fmaxf(v0, 0.f);
                        v1 = fmaxf(v1, 0.f);
                        __nv_bfloat16 h0, l0, h1, l1;
                        split_bf16(v0, h0, l0);
                        split_bf16(v1, h1, l1);
                        *(__nv_bfloat162*)(Yh + yrow + col) = __halves2bfloat162(h0, h1);
                        *(__nv_bfloat162*)(Yl + yrow + col) = __halves2bfloat162(l0, l1);
                    } else {
                        *(float2*)(Yf + yrow + col) = make_float2(v0, v1);
                    }
                }
            }
        }
    }
}

template <int EPI>
__global__ __launch_bounds__(256, 2) void gemm_mma(
    const __nv_bfloat16* __restrict__ Ah, const __nv_bfloat16* __restrict__ Al,
    const __nv_bfloat16* __restrict__ Wh, const __nv_bfloat16* __restrict__ Wl,
    const float* __restrict__ bias,
    float* __restrict__ Yf,
    __nv_bfloat16* __restrict__ Yh, __nv_bfloat16* __restrict__ Yl)
{
    extern __shared__ __align__(16) char dsm[];
    gemm_body<EPI>(Ah, Al, Wh, Wl, bias, Yf, Yh, Yl,
                   blockIdx.x, blockIdx.y, blockIdx.z, smem_u32(dsm));
}

// Merged dual output-projection launch (spat and temp branches).
__global__ __launch_bounds__(256, 2) void gemm_wo_pair(
    const __nv_bfloat16* __restrict__ Ah0, const __nv_bfloat16* __restrict__ Al0,
    const __nv_bfloat16* __restrict__ Wh0, const __nv_bfloat16* __restrict__ Wl0,
    float* __restrict__ Y0,
    const __nv_bfloat16* __restrict__ Ah1, const __nv_bfloat16* __restrict__ Al1,
    const __nv_bfloat16* __restrict__ Wh1, const __nv_bfloat16* __restrict__ Wl1,
    float* __restrict__ Y1)
{
    extern __shared__ __align__(16) char dsm[];
    const int zz = blockIdx.z;
    const int br = zz >= CC;
    const int c = br ? zz - CC : zz;
    gemm_body<0>(br ? Ah1 : Ah0, br ? Al1 : Al0,
                 br ? Wh1 : Wh0, br ? Wl1 : Wl0,
                 nullptr, br ? Y1 : Y0, nullptr, nullptr,
                 blockIdx.x, blockIdx.y, c, smem_u32(dsm));
}

// ---------------------------------------------------------------------------
// Spatial attention v4: one block per (b,s,half), 4 heads each, 384 threads.
// q/k/v read as bf16 hi/lo pairs (fp32 reconstructed), o -> bf16 pair.
// ---------------------------------------------------------------------------
constexpr int SA_P = 132;                        // 128 data + 4 pad
constexpr int SA_SMEM = (3 * CC * SA_P + 4 * CC * 25) * 4;  // 47,712 B

__global__ __launch_bounds__(384, 3) void spatial_attn(
    const __nv_bfloat16* __restrict__ qh, const __nv_bfloat16* __restrict__ ql,
    const __nv_bfloat16* __restrict__ kh, const __nv_bfloat16* __restrict__ kl,
    const __nv_bfloat16* __restrict__ vh, const __nv_bfloat16* __restrict__ vl,
    __nv_bfloat16* __restrict__ oh, __nv_bfloat16* __restrict__ ol)
{
    extern __shared__ float sa[];
    float* qs = sa;
    float* ks = qs + CC * SA_P;
    float* vs = ks + CC * SA_P;
    float* sc = vs + CC * SA_P;   // [4*CC][25]

    const int s = blockIdx.x, hb = blockIdx.y, b = blockIdx.z;  // hb: head-half
    const int t = threadIdx.x;
    const int h0 = hb * 4;                       // first head of this block
    const size_t gbase = ((size_t)b * CC * SS + s) * EE + h0 * 32;
    const size_t cstride = (size_t)SS * EE;

    // ---- loads: 24 rows x 128 cols per tensor; 8 floats (one uint4 pair)/thread ----
    {
        const int row = t >> 4, c8 = (t & 15) * 8;   // 24 rows x 16 chunks
        const size_t g = gbase + row * cstride + c8;
        const int so = row * SA_P + c8;
        float f[8];
        pair_to_f32x8(*(const uint4*)(qh + g), *(const uint4*)(ql + g), f);
#pragma unroll
        for (int j = 0; j < 8; ++j) qs[so + j] = f[j];
        pair_to_f32x8(*(const uint4*)(kh + g), *(const uint4*)(kl + g), f);
#pragma unroll
        for (int j = 0; j < 8; ++j) ks[so + j] = f[j];
        pair_to_f32x8(*(const uint4*)(vh + g), *(const uint4*)(vl + g), f);
#pragma unroll
        for (int j = 0; j < 8; ++j) vs[so + j] = f[j];
    }
    __syncthreads();

    // ---- scores: per head, 96 threads = 12 ci-groups(2) x 8 di-groups(3) ----
    {
        const int h = t / 96;                    // 0..3 local head
        const int r = t - h * 96;
        const int cig = r >> 3, dig = r & 7;
        const int ci0 = cig * 2, di0 = dig * 3;
        const float* qb = qs + ci0 * SA_P + h * 32;
        const float* kb = ks + di0 * SA_P + h * 32;
        float a00 = 0.f, a01 = 0.f, a02 = 0.f;
        float a10 = 0.f, a11 = 0.f, a12 = 0.f;
#pragma unroll
        for (int p = 0; p < 32; ++p) {
            const float q0 = qb[p], q1 = qb[SA_P + p];
            const float k0 = kb[p], k1 = kb[SA_P + p], k2 = kb[2 * SA_P + p];
            a00 = fmaf(q0, k0, a00); a01 = fmaf(q0, k1, a01); a02 = fmaf(q0, k2, a02);
            a10 = fmaf(q1, k0, a10); a11 = fmaf(q1, k1, a11); a12 = fmaf(q1, k2, a12);
        }
        float* sr0 = sc + (h * CC + ci0) * 25 + di0;
        float* sr1 = sr0 + 25;
        sr0[0] = a00 * INV_SQRT_P; sr0[1] = a01 * INV_SQRT_P; sr0[2] = a02 * INV_SQRT_P;
        sr1[0] = a10 * INV_SQRT_P; sr1[1] = a11 * INV_SQRT_P; sr1[2] = a12 * INV_SQRT_P;
    }
    __syncthreads();

    // ---- softmax over di (96 rows) ----
    if (t < 4 * CC) {
        float* row = sc + t * 25;
        float mx = -1e30f;
#pragma unroll
        for (int d = 0; d < CC; ++d) mx = fmaxf(mx, row[d]);
        float sm = 0.f;
#pragma unroll
        for (int d = 0; d < CC; ++d) { float e = __expf(row[d] - mx); row[d] = e; sm += e; }
        const float inv = 1.f / sm;
#pragma unroll
        for (int d = 0; d < CC; ++d) row[d] *= inv;
    }
    __syncthreads();

    // ---- AV: thread -> 2 items of (h, cc, p-quad); 768 items total ----
#pragma unroll
    for (int i = 0; i < 2; ++i) {
        const int item = t + i * 384;            // 0..767
        const int h = item / 192;                // 0..3
        const int rr = item - h * 192;
        const int cc = rr >> 3, p4 = (rr & 7) * 4;
        const float* arow = sc + (h * CC + cc) * 25;
        const float* vb = vs + h * 32 + p4;
        float s0 = 0.f, s1 = 0.f, s2 = 0.f, s3 = 0.f;
#pragma unroll
        for (int d = 0; d < CC; ++d) {
            const float a = arow[d];
            const float4 vv = *(const float4*)(vb + d * SA_P);
            s0 = fmaf(a, vv.x, s0); s1 = fmaf(a, vv.y, s1);
            s2 = fmaf(a, vv.z, s2); s3 = fmaf(a, vv.w, s3);
        }
        const size_t g = gbase + cc * cstride + h * 32 + p4;
        __nv_bfloat16 h0_, l0_, h1_, l1_, h2_, l2_, h3_, l3_;
        split_bf16(s0, h0_, l0_); split_bf16(s1, h1_, l1_);
        split_bf16(s2, h2_, l2_); split_bf16(s3, h3_, l3_);
        *(__nv_bfloat162*)(oh + g)     = __halves2bfloat162(h0_, h1_);
        *(__nv_bfloat162*)(oh + g + 2) = __halves2bfloat162(h2_, h3_);
        *(__nv_bfloat162*)(ol + g)     = __halves2bfloat162(l0_, l1_);
        *(__nv_bfloat162*)(ol + g + 2) = __halves2bfloat162(l2_, l3_);
    }
}

// ---------------------------------------------------------------------------
// Temporal attention (f32x2 packed FMA). q/k/v as bf16 pairs, o -> bf16 pair.
// ---------------------------------------------------------------------------
constexpr int QK_PAD = 132, V_PAD = 36, SC_PAD = 129;
constexpr int TEMP_SMEM_BYTES = (2 * 32 * QK_PAD + SS * V_PAD + SS * SC_PAD) * 4;

__global__ __launch_bounds__(256) void temporal_attn(
    const __nv_bfloat16* __restrict__ qph, const __nv_bfloat16* __restrict__ qpl,
    const __nv_bfloat16* __restrict__ kph, const __nv_bfloat16* __restrict__ kpl,
    const __nv_bfloat16* __restrict__ vph, const __nv_bfloat16* __restrict__ vpl,
    __nv_bfloat16* __restrict__ oh, __nv_bfloat16* __restrict__ ol)
{
    extern __shared__ float smem[];
    float* qt = smem;
    float* kt = qt + 32 * QK_PAD;
    float* vs = kt + 32 * QK_PAD;
    float* sc = vs + SS * V_PAD;

    const int c = blockIdx.x, h = blockIdx.y, b = blockIdx.z;
    const int tid = threadIdx.x;
    const size_t base = (((size_t)b * CC + c) * SS) * EE + h * PP;

    // load: 256 threads = 128 rows x 2 halves; each thread 16 contiguous p-elems
    {
        const int s = tid >> 1, ph = (tid & 1) * 16;
        const size_t g = base + (size_t)s * EE + ph;
        float f[8];
        pair_to_f32x8(*(const uint4*)(qph + g), *(const uint4*)(qpl + g), f);
#pragma unroll
        for (int j = 0; j < 8; ++j) qt[(ph + j) * QK_PAD + s] = f[j];
        pair_to_f32x8(*(const uint4*)(qph + g + 8), *(const uint4*)(qpl + g + 8), f);
#pragma unroll
        for (int j = 0; j < 8; ++j) qt[(ph + 8 + j) * QK_PAD + s] = f[j];
        pair_to_f32x8(*(const uint4*)(kph + g), *(const uint4*)(kpl + g), f);
#pragma unroll
        for (int j = 0; j < 8; ++j) kt[(ph + j) * QK_PAD + s] = f[j];
        pair_to_f32x8(*(const uint4*)(kph + g + 8), *(const uint4*)(kpl + g + 8), f);
#pragma unroll
        for (int j = 0; j < 8; ++j) kt[(ph + 8 + j) * QK_PAD + s] = f[j];
        pair_to_f32x8(*(const uint4*)(vph + g), *(const uint4*)(vpl + g), f);
#pragma unroll
        for (int j = 0; j < 8; ++j) vs[s * V_PAD + ph + j] = f[j];
        pair_to_f32x8(*(const uint4*)(vph + g + 8), *(const uint4*)(vpl + g + 8), f);
#pragma unroll
        for (int j = 0; j < 8; ++j) vs[s * V_PAD + ph + 8 + j] = f[j];
    }
    __syncthreads();

    {
        const int tx = tid & 15, ty = tid >> 4;
        unsigned long long acc2[8][4];
#pragma unroll
        for (int i = 0; i < 8; ++i)
#pragma unroll
            for (int j = 0; j < 4; ++j) acc2[i][j] = 0ull;

#pragma unroll 4
        for (int p = 0; p < PP; ++p) {
            float4 a0 = *(const float4*)&qt[p * QK_PAD + ty * 8];
            float4 a1 = *(const float4*)&qt[p * QK_PAD + ty * 8 + 4];
            float ar[8] = {a0.x, a0.y, a0.z, a0.w, a1.x, a1.y, a1.z, a1.w};
            ulonglong2 bb01 = *(const ulonglong2*)&kt[p * QK_PAD + tx * 8];
            ulonglong2 bb23 = *(const ulonglong2*)&kt[p * QK_PAD + tx * 8 + 4];
            unsigned long long bb[4] = {bb01.x, bb01.y, bb23.x, bb23.y};
#pragma unroll
            for (int i = 0; i < 8; ++i) {
                const unsigned long long ap = pack2(ar[i]);
#pragma unroll
                for (int j = 0; j < 4; ++j) fma2(acc2[i][j], ap, bb[j]);
            }
        }
#pragma unroll
        for (int i = 0; i < 8; ++i)
#pragma unroll
            for (int j = 0; j < 4; ++j) {
                float2 u = unpack2(acc2[i][j]);
                sc[(ty * 8 + i) * SC_PAD + tx * 8 + j * 2 + 0] = u.x * INV_SQRT_P;
                sc[(ty * 8 + i) * SC_PAD + tx * 8 + j * 2 + 1] = u.y * INV_SQRT_P;
            }
    }
    __syncthreads();

    {
        const int row = tid >> 1, half = tid & 1;
        float* r = sc + row * SC_PAD + half * 64;
        float mx = -1e30f;
#pragma unroll 8
        for (int t2 = 0; t2 < 64; ++t2) mx = fmaxf(mx, r[t2]);
        mx = fmaxf(mx, __shfl_xor_sync(0xffffffffu, mx, 1));
        float ssum = 0.f;
#pragma unroll 8
        for (int t2 = 0; t2 < 64; ++t2) {
            float e = __expf(r[t2] - mx);
            r[t2] = e;
            ssum += e;
        }
        ssum += __shfl_xor_sync(0xffffffffu, ssum, 1);
        const float inv = 1.f / ssum;
#pragma unroll 8
        for (int t2 = 0; t2 < 64; ++t2) r[t2] *= inv;
    }
    __syncthreads();

    {
        const int s0 = (tid >> 3) * 4;
        const int p0 = (tid & 7) * 4;
        unsigned long long acc2[4][2];
#pragma unroll
        for (int i = 0; i < 4; ++i) { acc2[i][0] = 0ull; acc2[i][1] = 0ull; }

#pragma unroll 4
        for (int t2 = 0; t2 < SS; ++t2) {
            ulonglong2 vv = *(const ulonglong2*)&vs[t2 * V_PAD + p0];
#pragma unroll
            for (int i = 0; i < 4; ++i) {
                const unsigned long long ap = pack2(sc[(s0 + i) * SC_PAD + t2]);
                fma2(acc2[i][0], ap, vv.x);
                fma2(acc2[i][1], ap, vv.y);
            }
        }
#pragma unroll
        for (int i = 0; i < 4; ++i) {
            float2 u0 = unpack2(acc2[i][0]);
            float2 u1 = unpack2(acc2[i][1]);
            float vv[4] = {u0.x, u0.y, u1.x, u1.y};
            const size_t g = base + (size_t)(s0 + i) * EE + p0;
            __nv_bfloat16 hh[4], ll[4];
#pragma unroll
            for (int j = 0; j < 4; ++j) split_bf16(vv[j], hh[j], ll[j]);
            *(__nv_bfloat162*)(oh + g)     = __halves2bfloat162(hh[0], hh[1]);
            *(__nv_bfloat162*)(oh + g + 2) = __halves2bfloat162(hh[2], hh[3]);
            *(__nv_bfloat162*)(ol + g)     = __halves2bfloat162(ll[0], ll[1]);
            *(__nv_bfloat162*)(ol + g + 2) = __halves2bfloat162(ll[2], ll[3]);
        }
    }
}

// ---------------------------------------------------------------------------
// LayerNorm kernels
// ---------------------------------------------------------------------------
__device__ __forceinline__ float blk_sum(float v, float* scratch)
{
    __syncthreads();
    const int lane = threadIdx.x & 31, w = threadIdx.x >> 5;
#pragma unroll
    for (int off = 16; off > 0; off >>= 1)
        v += __shfl_xor_sync(0xffffffffu, v, off);
    if (lane == 0) scratch[w] = v;
    __syncthreads();
    float tot = 0.f;
#pragma unroll
    for (int i = 0; i < 8; ++i) tot += scratch[i];
    return tot;
}

__global__ __launch_bounds__(256) void dual_ln(
    const float* __restrict__ x, const float* __restrict__ a,
    const float* __restrict__ b2, const float* __restrict__ g,
    const float* __restrict__ beta, float* __restrict__ out,
    __nv_bfloat16* __restrict__ oh, __nv_bfloat16* __restrict__ ol)
{
    __shared__ float scratch[8];
    const size_t off = (size_t)blockIdx.x * EE + threadIdx.x;
    const float xv = x[off];
    const float v1 = xv + a[off];
    const float v2 = xv + b2[off];

    const float s1 = blk_sum(v1, scratch);
    const float q1 = blk_sum(v1 * v1, scratch);
    const float s2 = blk_sum(v2, scratch);
    const float q2 = blk_sum(v2 * v2, scratch);

    const float invE = 1.f / (float)EE;
    const float m1 = s1 * invE, m2 = s2 * invE;
    const float r1 = rsqrtf(fmaxf(q1 * invE - m1 * m1, 0.f) + LN_EPS);
    const float r2 = rsqrtf(fmaxf(q2 * invE - m2 * m2, 0.f) + LN_EPS);
    const float gg = g[threadIdx.x], bt = beta[threadIdx.x];
    const float o = (v1 - m1) * r1 * gg + bt + (v2 - m2) * r2 * gg + bt;
    out[off] = o;
    __nv_bfloat16 hi, lo;
    split_bf16(o, hi, lo);
    oh[off] = hi;
    ol[off] = lo;
}

__global__ __launch_bounds__(256) void final_ln(
    const float* __restrict__ a, const float* __restrict__ f,
    const float* __restrict__ g, const float* __restrict__ beta,
    float* __restrict__ out)
{
    __shared__ float scratch[8];
    const size_t off = (size_t)blockIdx.x * EE + threadIdx.x;
    const float v = a[off] + f[off];
    const float s = blk_sum(v, scratch);
    const float q = blk_sum(v * v, scratch);
    const float invE = 1.f / (float)EE;
    const float m = s * invE;
    const float r = rsqrtf(fmaxf(q * invE - m * m, 0.f) + LN_EPS);
    out[off] = (v - m) * r * g[threadIdx.x] + beta[threadIdx.x];
}

// ---------------------------------------------------------------------------
// kernel_launch
// ---------------------------------------------------------------------------
extern "C" void kernel_launch(void* const* d_in, const int* in_sizes, int n_in,
                              void* d_out, int out_size)
{
    const float* x    = (const float*)d_in[0];
    const float* ln_g = (const float*)d_in[9];
    const float* ln_b = (const float*)d_in[10];
    const float* ff_b1 = (const float*)d_in[12];
    const float* ff_b2 = (const float*)d_in[14];
    float* out = (float*)d_out;

    float *spat, *temp, *attn, *ffo;
    void *qsB, *ksB, *vsB, *qtB, *ktB, *vtB;
    __nv_bfloat16 *xh, *xl, *ah, *al, *hh, *hl, *wh, *wl;
    cudaGetSymbolAddress(&qsB, g_qs);
    cudaGetSymbolAddress(&ksB, g_ks);
    cudaGetSymbolAddress(&vsB, g_vs);
    cudaGetSymbolAddress(&qtB, g_qt);
    cudaGetSymbolAddress(&ktB, g_kt);
    cudaGetSymbolAddress(&vtB, g_vt);
    cudaGetSymbolAddress((void**)&spat, g_spat);
    cudaGetSymbolAddress((void**)&temp, g_temp);
    cudaGetSymbolAddress((void**)&attn, g_attn);
    cudaGetSymbolAddress((void**)&ffo,  g_ffo);
    cudaGetSymbolAddress((void**)&xh, g_xh);
    cudaGetSymbolAddress((void**)&xl, g_xl);
    cudaGetSymbolAddress((void**)&ah, g_ah);
    cudaGetSymbolAddress((void**)&al, g_al);
    cudaGetSymbolAddress((void**)&hh, g_hh);
    cudaGetSymbolAddress((void**)&hl, g_hl);
    cudaGetSymbolAddress((void**)&wh, g_wh);
    cudaGetSymbolAddress((void**)&wl, g_wl);

    // bf16 pair views over the former fp32 q/k/v buffers
    __nv_bfloat16* qsh = (__nv_bfloat16*)qsB;  __nv_bfloat16* qsl = qsh + NTOT;
    __nv_bfloat16* ksh = (__nv_bfloat16*)ksB;  __nv_bfloat16* ksl = ksh + NTOT;
    __nv_bfloat16* vsh = (__nv_bfloat16*)vsB;  __nv_bfloat16* vsl = vsh + NTOT;
    __nv_bfloat16* qth = (__nv_bfloat16*)qtB;  __nv_bfloat16* qtl = qth + NTOT;
    __nv_bfloat16* kth = (__nv_bfloat16*)ktB;  __nv_bfloat16* ktl = kth + NTOT;
    __nv_bfloat16* vth = (__nv_bfloat16*)vtB;  __nv_bfloat16* vtl = vth + NTOT;

    cudaFuncSetAttribute(gemm_qkv6,   cudaFuncAttributeMaxDynamicSharedMemorySize, QKV_SMEM);
    cudaFuncSetAttribute(gemm_mma<1>, cudaFuncAttributeMaxDynamicSharedMemorySize, GEMM_SMEM);
    cudaFuncSetAttribute(gemm_mma<2>, cudaFuncAttributeMaxDynamicSharedMemorySize, GEMM_SMEM);
    cudaFuncSetAttribute(gemm_wo_pair, cudaFuncAttributeMaxDynamicSharedMemorySize, GEMM_SMEM);
    cudaFuncSetAttribute(spatial_attn, cudaFuncAttributeMaxDynamicSharedMemorySize, SA_SMEM);
    cudaFuncSetAttribute(temporal_attn, cudaFuncAttributeMaxDynamicSharedMemorySize, TEMP_SMEM_BYTES);

    // ---- conversions ----
    split_f32_kernel<<<NTOT / 4 / 256, 256>>>(x, xh, xl, NTOT / 4);
    WPtrs wp;
    wp.p[0] = (const float*)d_in[1];
    wp.p[1] = (const float*)d_in[2];
    wp.p[2] = (const float*)d_in[3];
    wp.p[3] = (const float*)d_in[4];
    wp.p[4] = (const float*)d_in[5];
    wp.p[5] = (const float*)d_in[6];
    wp.p[6] = (const float*)d_in[7];
    wp.p[7] = (const float*)d_in[8];
    wp.p[8] = (const float*)d_in[11];
    wp.p[9] = (const float*)d_in[13];
    convert_weights_t<<<dim3(64, CC, NW), 256>>>(wp, wh, wl);

    // ---- fused q/k/v projections (both branches), bf16-pair outputs ----
    Out6 o6;
    o6.h[0] = qsh; o6.l[0] = qsl;
    o6.h[1] = ksh; o6.l[1] = ksl;
    o6.h[2] = vsh; o6.l[2] = vsl;
    o6.h[3] = qth; o6.l[3] = qtl;
    o6.h[4] = kth; o6.l[4] = ktl;
    o6.h[5] = vth; o6.l[5] = vtl;
    gemm_qkv6<<<dim3(BB, 2, CC), 256, QKV_SMEM>>>(xh, xl, wh, wl, o6);

    // ---- attentions ----
    spatial_attn<<<dim3(SS, 2, BB), 384, SA_SMEM>>>(qsh, qsl, ksh, ksl, vsh, vsl, ah, al);
    temporal_attn<<<dim3(CC, HH, BB), 256, TEMP_SMEM_BYTES>>>(qth, qtl, kth, ktl, vth, vtl, hh, hl);

    // ---- output projections (merged dual launch) ----
    gemm_wo_pair<<<dim3(BB, 2, 2 * CC), 256, GEMM_SMEM>>>(
        ah, al, wh + 3*(size_t)WELEMS, wl + 3*(size_t)WELEMS, spat,
        hh, hl, wh + 7*(size_t)WELEMS, wl + 7*(size_t)WELEMS, temp);

    // ---- residual + dual LN (emits attn fp32 + bf16 pair) ----
    dual_ln<<<NROWS, 256>>>(x, spat, temp, ln_g, ln_b, attn, ah, al);

    // ---- per-joint FF + final LN ----
    gemm_mma<1><<<dim3(BB, 2, CC), 256, GEMM_SMEM>>>(ah, al, wh + 8*(size_t)WELEMS, wl + 8*(size_t)WELEMS, ff_b1, nullptr, hh, hl);
    gemm_mma<2><<<dim3(BB, 2, CC), 256, GEMM_SMEM>>>(hh, hl, wh + 9*(size_t)WELEMS, wl + 9*(size_t)WELEMS, ff_b2, ffo, nullptr, nullptr);
    final_ln<<<NROWS, 256>>>(attn, ffo, ln_g, ln_b, out);
}

// round 9
// speedup vs baseline: 1.4981x; 1.4981x over previous
#include <cuda_runtime.h>
#include <cuda_bf16.h>
#include <cstdint>
#include <cstddef>

// Problem dims
constexpr int BB = 16, CC = 24, SS = 128, EE = 256, HH = 8, PP = 32;
constexpr int NTOT  = BB * CC * SS * EE;     // 12,582,912
constexpr int NROWS = BB * CC * SS;          // 49,152
constexpr int WELEMS = CC * EE * EE;         // 1,572,864 per weight
constexpr int NW = 10;
constexpr float LN_EPS = 1e-6f;
constexpr float INV_SQRT_P = 0.17677669529663687f;

// ---------------------------------------------------------------------------
// Device scratch
// ---------------------------------------------------------------------------
__device__ float g_qs[NTOT], g_ks[NTOT], g_vs[NTOT];
__device__ float g_qt[NTOT], g_kt[NTOT], g_vt[NTOT];
__device__ float g_spat[NTOT], g_temp[NTOT], g_attn[NTOT], g_ffo[NTOT];
__device__ __align__(16) __nv_bfloat16 g_xh[NTOT], g_xl[NTOT];
__device__ __align__(16) __nv_bfloat16 g_ah[NTOT], g_al[NTOT];   // spatial-out / attn pair
__device__ __align__(16) __nv_bfloat16 g_hh[NTOT], g_hl[NTOT];   // temporal-out / ff hidden pair
__device__ __align__(16) __nv_bfloat16 g_wh[NW * WELEMS], g_wl[NW * WELEMS];

// ---------------------------------------------------------------------------
// PTX helpers (baseline ISA only)
// ---------------------------------------------------------------------------
__device__ __forceinline__ uint32_t smem_u32(const void* p) {
    uint32_t a;
    asm("{ .reg .u64 t; cvta.to.shared.u64 t, %1; cvt.u32.u64 %0, t; }"
        : "=r"(a) : "l"(p));
    return a;
}
__device__ __forceinline__ void cp_async16(uint32_t smem, const void* gmem) {
    asm volatile("cp.async.cg.shared.global [%0], [%1], 16;"
                 :: "r"(smem), "l"(gmem));
}
__device__ __forceinline__ void cp_commit() {
    asm volatile("cp.async.commit_group;");
}
template <int N>
__device__ __forceinline__ void cp_wait() {
    asm volatile("cp.async.wait_group %0;" :: "n"(N) : "memory");
}
__device__ __forceinline__ void ldsm_x4(uint32_t& r0, uint32_t& r1,
                                        uint32_t& r2, uint32_t& r3, uint32_t addr) {
    asm volatile("ldmatrix.sync.aligned.m8n8.x4.shared.b16 {%0,%1,%2,%3}, [%4];"
                 : "=r"(r0), "=r"(r1), "=r"(r2), "=r"(r3) : "r"(addr));
}
__device__ __forceinline__ void mma_bf16(float* d, const uint32_t* a,
                                         uint32_t b0, uint32_t b1) {
    asm volatile(
        "mma.sync.aligned.m16n8k16.row.col.f32.bf16.bf16.f32 "
        "{%0,%1,%2,%3}, {%4,%5,%6,%7}, {%8,%9}, {%0,%1,%2,%3};"
        : "+f"(d[0]), "+f"(d[1]), "+f"(d[2]), "+f"(d[3])
        : "r"(a[0]), "r"(a[1]), "r"(a[2]), "r"(a[3]), "r"(b0), "r"(b1));
}
// packed f32x2
__device__ __forceinline__ unsigned long long pack2(float v) {
    unsigned long long r;
    asm("mov.b64 %0, {%1, %1};" : "=l"(r) : "f"(v));
    return r;
}
__device__ __forceinline__ void fma2(unsigned long long& d,
                                     unsigned long long a, unsigned long long b) {
    asm("fma.rn.f32x2 %0, %1, %2, %0;" : "+l"(d) : "l"(a), "l"(b));
}
__device__ __forceinline__ float2 unpack2(unsigned long long v) {
    float2 f;
    asm("mov.b64 {%0, %1}, %2;" : "=f"(f.x), "=f"(f.y) : "l"(v));
    return f;
}

// ---------------------------------------------------------------------------
// bf16 hi/lo split helpers
// ---------------------------------------------------------------------------
__device__ __forceinline__ void split_bf16(float x, __nv_bfloat16& h, __nv_bfloat16& l) {
    h = __float2bfloat16_rn(x);
    l = __float2bfloat16_rn(x - __bfloat162float(h));
}

__global__ __launch_bounds__(256) void split_f32_kernel(
    const float* __restrict__ src, __nv_bfloat16* __restrict__ hi,
    __nv_bfloat16* __restrict__ lo, int n4)
{
    int i = blockIdx.x * 256 + threadIdx.x;
    if (i >= n4) return;
    float4 v = ((const float4*)src)[i];
    float vv[4] = {v.x, v.y, v.z, v.w};
    __nv_bfloat16 h[4], l[4];
#pragma unroll
    for (int j = 0; j < 4; ++j) split_bf16(vv[j], h[j], l[j]);
    __nv_bfloat162* hp = (__nv_bfloat162*)hi;
    __nv_bfloat162* lp = (__nv_bfloat162*)lo;
    hp[i * 2 + 0] = __halves2bfloat162(h[0], h[1]);
    hp[i * 2 + 1] = __halves2bfloat162(h[2], h[3]);
    lp[i * 2 + 0] = __halves2bfloat162(l[0], l[1]);
    lp[i * 2 + 1] = __halves2bfloat162(l[2], l[3]);
}

// ---------------------------------------------------------------------------
// Weight conversion, coalesced: 32x32 (e,f) tiles via smem transpose.
// ---------------------------------------------------------------------------
struct WPtrs { const float* p[NW]; };

__global__ __launch_bounds__(256) void convert_weights_t(
    WPtrs wp, __nv_bfloat16* __restrict__ wh, __nv_bfloat16* __restrict__ wl)
{
    __shared__ float tile[32][33];
    const int w = blockIdx.z, c = blockIdx.y;
    const int eb = blockIdx.x & 7, fb = blockIdx.x >> 3;
    const int mode = (w == 3 || w >= 7) ? 0 : (w == 0 ? 1 : (w <= 2 ? 2 : 3));
    const int t = threadIdx.x;
    const int col = t & 31, r0 = t >> 5;
    const float* W = wp.p[w];

#pragma unroll
    for (int i = 0; i < 4; ++i) {
        const int row = r0 + i * 8;
        float v;
        if (mode == 0) {
            const int e = eb * 32 + row, f = fb * 32 + col;
            v = W[((size_t)c * EE + e) * EE + f];
        } else if (mode == 1) {
            const int f = fb * 32 + row, e = eb * 32 + col;
            const int h = fb, p = f & 31;
            v = W[(((size_t)h * CC + c) * PP + p) * EE + e];
        } else if (mode == 2) {
            const int e = eb * 32 + row, p = col, h = fb;
            v = W[((size_t)h * EE + e) * PP + p];
        } else {
            const int e = eb * 32 + row, p = col, h = fb;
            v = W[(((size_t)h * CC + c) * EE + e) * PP + p];
        }
        tile[row][col] = v;
    }
    __syncthreads();

#pragma unroll
    for (int i = 0; i < 4; ++i) {
        const int fr = r0 + i * 8;
        const int f = fb * 32 + fr;
        const int e = eb * 32 + col;
        const float v = (mode == 1) ? tile[fr][col] : tile[col][fr];
        __nv_bfloat16 hi, lo;
        split_bf16(v, hi, lo);
        const size_t o = (size_t)w * WELEMS + ((size_t)c << 16) + (size_t)f * EE + e;
        wh[o] = hi;
        wl[o] = lo;
    }
}

// ---------------------------------------------------------------------------
// Fused QKVx6 GEMM (A resident, 48 streamed B stages, triple-buffered)
// ---------------------------------------------------------------------------
constexpr int AP = 528;
constexpr int QA_HI = 0;
constexpr int QA_LO = 128 * AP;
constexpr int QB0   = 2 * 128 * AP;
constexpr int QB_STG = 20480;
constexpr int QKV_SMEM = QB0 + 3 * QB_STG;

constexpr int GP = 80;

struct Out6 { float* y[6]; };

__global__ __launch_bounds__(256) void gemm_qkv6(
    const __nv_bfloat16* __restrict__ xh, const __nv_bfloat16* __restrict__ xl,
    const __nv_bfloat16* __restrict__ whB, const __nv_bfloat16* __restrict__ wlB,
    Out6 outs)
{
    extern __shared__ __align__(16) char dsm[];
    const uint32_t sbase = smem_u32(dsm);
    const int tid = threadIdx.x;
    const int wid = tid >> 5, lane = tid & 31;
    const int b = blockIdx.x, nb = blockIdx.y, c = blockIdx.z;

    const size_t abase = ((size_t)b * CC + c) * SS * EE;

#pragma unroll
    for (int i = 0; i < 16; ++i) {
        const int t2 = tid + i * 256;
        const int row = t2 >> 5, ch = t2 & 31;
        const size_t goff = (size_t)row * EE + ch * 8;
        const uint32_t so = row * AP + ch * 16;
        cp_async16(sbase + QA_HI + so, xh + abase + goff);
        cp_async16(sbase + QA_LO + so, xl + abase + goff);
    }
    cp_commit();

    auto issueB = [&](int stage) {
        const int w = stage >> 3, kb = (stage & 7) * 32;
        const int wg = w + (w >= 3);
        const __nv_bfloat16* Wh = whB + (size_t)wg * WELEMS + ((size_t)c << 16)
                                + (size_t)nb * 128 * EE;
        const __nv_bfloat16* Wl = wlB + (size_t)wg * WELEMS + ((size_t)c << 16)
                                + (size_t)nb * 128 * EE;
        const uint32_t sb = sbase + QB0 + (stage % 3) * QB_STG;
#pragma unroll
        for (int j = 0; j < 2; ++j) {
            const int t2 = tid + j * 256;
            const int row = t2 >> 2, ch = t2 & 3;
            const size_t goff = (size_t)row * EE + kb + ch * 8;
            const uint32_t so = row * GP + ch * 16;
            cp_async16(sb + so, Wh + goff);
            cp_async16(sb + 10240 + so, Wl + goff);
        }
    };
    issueB(0); cp_commit();
    issueB(1); cp_commit();
    issueB(2); cp_commit();

    const int wm = wid & 3, wn = wid >> 2;
    const int g = lane >> 3, lr = lane & 7;

    for (int w = 0; w < 6; ++w) {
        float acc[2][8][4];
#pragma unroll
        for (int mi = 0; mi < 2; ++mi)
#pragma unroll
            for (int nj = 0; nj < 8; ++nj)
#pragma unroll
                for (int r = 0; r < 4; ++r) acc[mi][nj][r] = 0.f;

        for (int it = 0; it < 8; ++it) {
            const int stage = w * 8 + it;
            cp_wait<2>();
            __syncthreads();
            const uint32_t Bst = sbase + QB0 + (stage % 3) * QB_STG;

#pragma unroll
            for (int pass = 0; pass < 3; ++pass) {
                const uint32_t Ab = sbase + (pass == 2 ? QA_LO : QA_HI);
                const uint32_t Bb = Bst + (pass == 1 ? 10240 : 0);
#pragma unroll
                for (int k16 = 0; k16 < 2; ++k16) {
                    uint32_t afr[2][4];
#pragma unroll
                    for (int mi = 0; mi < 2; ++mi) {
                        const int row = wm * 32 + mi * 16 + ((g & 1) << 3) + lr;
                        const uint32_t addr =
                            Ab + row * AP + (it * 4 + k16 * 2 + (g >> 1)) * 16;
                        ldsm_x4(afr[mi][0], afr[mi][1], afr[mi][2], afr[mi][3], addr);
                    }
                    uint32_t bfr[4][4];
#pragma unroll
                    for (int ni = 0; ni < 4; ++ni) {
                        const int row = wn * 64 + ni * 16 + ((g >> 1) << 3) + lr;
                        const uint32_t addr = Bb + row * GP + (k16 * 2 + (g & 1)) * 16;
                        ldsm_x4(bfr[ni][0], bfr[ni][1], bfr[ni][2], bfr[ni][3], addr);
                    }
#pragma unroll
                    for (int mi = 0; mi < 2; ++mi)
#pragma unroll
                        for (int nj = 0; nj < 8; ++nj)
                            mma_bf16(acc[mi][nj], afr[mi],
                                     bfr[nj >> 1][(nj & 1) * 2],
                                     bfr[nj >> 1][(nj & 1) * 2 + 1]);
                }
            }
            __syncthreads();
            if (stage + 3 < 48) issueB(stage + 3);
            cp_commit();
        }

        float* Yf = outs.y[w];
#pragma unroll
        for (int mi = 0; mi < 2; ++mi)
#pragma unroll
            for (int rr = 0; rr < 2; ++rr) {
                const int m = wm * 32 + mi * 16 + (lane >> 2) + rr * 8;
                const size_t yrow = abase + (size_t)m * EE + nb * 128;
#pragma unroll
                for (int nj = 0; nj < 8; ++nj) {
                    const int colo = wn * 64 + nj * 8 + (lane & 3) * 2;
                    *(float2*)(Yf + yrow + colo) =
                        make_float2(acc[mi][nj][rr * 2 + 0], acc[mi][nj][rr * 2 + 1]);
                }
            }
    }
}

// ---------------------------------------------------------------------------
// Generic HMMA GEMM body: 128x128, 2-stage cp.async, 2 CTAs/SM.
// ---------------------------------------------------------------------------
constexpr int T_A_HI = 0;
constexpr int T_A_LO = 128 * GP;
constexpr int T_B_HI = 2 * 128 * GP;
constexpr int T_B_LO = 3 * 128 * GP;
constexpr int STAGE  = 4 * 128 * GP;          // 40960
constexpr int GEMM_SMEM = 2 * STAGE;          // 81920

template <int EPI>
__device__ __forceinline__ void gemm_body(
    const __nv_bfloat16* __restrict__ Ah, const __nv_bfloat16* __restrict__ Al,
    const __nv_bfloat16* __restrict__ Wh, const __nv_bfloat16* __restrict__ Wl,
    const float* __restrict__ bias,
    float* __restrict__ Yf,
    __nv_bfloat16* __restrict__ Yh, __nv_bfloat16* __restrict__ Yl,
    int b, int nb, int c, uint32_t sbase)
{
    const int tid = threadIdx.x;
    const int wid = tid >> 5, lane = tid & 31;

    const size_t abase = ((size_t)b * CC + c) * SS * EE;
    const size_t wbase = (size_t)c * EE * EE + (size_t)nb * 128 * EE;

    auto issue = [&](int stg) {
        const int kb = stg * 32;
        const uint32_t sb = sbase + (stg & 1) * STAGE;
#pragma unroll
        for (int j = 0; j < 2; ++j) {
            const int t2 = tid + j * 256;
            const int row = t2 >> 2, ch = t2 & 3;
            const size_t goff = (size_t)row * EE + kb + ch * 8;
            const uint32_t so = row * GP + ch * 16;
            cp_async16(sb + T_A_HI + so, Ah + abase + goff);
            cp_async16(sb + T_A_LO + so, Al + abase + goff);
            cp_async16(sb + T_B_HI + so, Wh + wbase + goff);
            cp_async16(sb + T_B_LO + so, Wl + wbase + goff);
        }
    };
    issue(0); cp_commit();
    issue(1); cp_commit();

    const int wm = wid & 3, wn = wid >> 2;
    const int g = lane >> 3, lr = lane & 7;

    float acc[2][8][4];
#pragma unroll
    for (int mi = 0; mi < 2; ++mi)
#pragma unroll
        for (int nj = 0; nj < 8; ++nj)
#pragma unroll
            for (int r = 0; r < 4; ++r) acc[mi][nj][r] = 0.f;

    for (int it = 0; it < 8; ++it) {
        cp_wait<1>();
        __syncthreads();
        const uint32_t st = sbase + (it & 1) * STAGE;

#pragma unroll
        for (int pass = 0; pass < 3; ++pass) {
            const uint32_t Ab = st + (pass == 2 ? T_A_LO : T_A_HI);
            const uint32_t Bb = st + (pass == 1 ? T_B_LO : T_B_HI);
#pragma unroll
            for (int k16 = 0; k16 < 2; ++k16) {
                uint32_t afr[2][4];
#pragma unroll
                for (int mi = 0; mi < 2; ++mi) {
                    const int row = wm * 32 + mi * 16 + ((g & 1) << 3) + lr;
                    const uint32_t addr = Ab + row * GP + (k16 * 2 + (g >> 1)) * 16;
                    ldsm_x4(afr[mi][0], afr[mi][1], afr[mi][2], afr[mi][3], addr);
                }
                uint32_t bfr[4][4];
#pragma unroll
                for (int ni = 0; ni < 4; ++ni) {
                    const int row = wn * 64 + ni * 16 + ((g >> 1) << 3) + lr;
                    const uint32_t addr = Bb + row * GP + (k16 * 2 + (g & 1)) * 16;
                    ldsm_x4(bfr[ni][0], bfr[ni][1], bfr[ni][2], bfr[ni][3], addr);
                }
#pragma unroll
                for (int mi = 0; mi < 2; ++mi)
#pragma unroll
                    for (int nj = 0; nj < 8; ++nj)
                        mma_bf16(acc[mi][nj], afr[mi],
                                 bfr[nj >> 1][(nj & 1) * 2],
                                 bfr[nj >> 1][(nj & 1) * 2 + 1]);
            }
        }
        __syncthreads();
        if (it + 2 < 8) issue(it + 2);
        cp_commit();
    }

#pragma unroll
    for (int mi = 0; mi < 2; ++mi) {
#pragma unroll
        for (int rr = 0; rr < 2; ++rr) {
            const int m = wm * 32 + mi * 16 + (lane >> 2) + rr * 8;
            const size_t yrow = abase + (size_t)m * EE + nb * 128;
#pragma unroll
            for (int nj = 0; nj < 8; ++nj) {
                const int col = wn * 64 + nj * 8 + (lane & 3) * 2;
                float v0 = acc[mi][nj][rr * 2 + 0];
                float v1 = acc[mi][nj][rr * 2 + 1];
                if constexpr (EPI == 0) {
                    *(float2*)(Yf + yrow + col) = make_float2(v0, v1);
                } else {
                    const float* bp = bias + (size_t)c * EE + nb * 128 + col;
                    v0 += bp[0];
                    v1 += bp[1];
                    if constexpr (EPI == 1) {
                        v0 = fmaxf(v0, 0.f);
                        v1 = fmaxf(v1, 0.f);
                        __nv_bfloat16 h0, l0, h1, l1;
                        split_bf16(v0, h0, l0);
                        split_bf16(v1, h1, l1);
                        *(__nv_bfloat162*)(Yh + yrow + col) = __halves2bfloat162(h0, h1);
                        *(__nv_bfloat162*)(Yl + yrow + col) = __halves2bfloat162(l0, l1);
                    } else {
                        *(float2*)(Yf + yrow + col) = make_float2(v0, v1);
                    }
                }
            }
        }
    }
}

template <int EPI>
__global__ __launch_bounds__(256, 2) void gemm_mma(
    const __nv_bfloat16* __restrict__ Ah, const __nv_bfloat16* __restrict__ Al,
    const __nv_bfloat16* __restrict__ Wh, const __nv_bfloat16* __restrict__ Wl,
    const float* __restrict__ bias,
    float* __restrict__ Yf,
    __nv_bfloat16* __restrict__ Yh, __nv_bfloat16* __restrict__ Yl)
{
    extern __shared__ __align__(16) char dsm[];
    gemm_body<EPI>(Ah, Al, Wh, Wl, bias, Yf, Yh, Yl,
                   blockIdx.x, blockIdx.y, blockIdx.z, smem_u32(dsm));
}

// Merged dual output-projection launch (spat and temp branches).
__global__ __launch_bounds__(256, 2) void gemm_wo_pair(
    const __nv_bfloat16* __restrict__ Ah0, const __nv_bfloat16* __restrict__ Al0,
    const __nv_bfloat16* __restrict__ Wh0, const __nv_bfloat16* __restrict__ Wl0,
    float* __restrict__ Y0,
    const __nv_bfloat16* __restrict__ Ah1, const __nv_bfloat16* __restrict__ Al1,
    const __nv_bfloat16* __restrict__ Wh1, const __nv_bfloat16* __restrict__ Wl1,
    float* __restrict__ Y1)
{
    extern __shared__ __align__(16) char dsm[];
    const int zz = blockIdx.z;
    const int br = zz >= CC;
    const int c = br ? zz - CC : zz;
    gemm_body<0>(br ? Ah1 : Ah0, br ? Al1 : Al0,
                 br ? Wh1 : Wh0, br ? Wl1 : Wl0,
                 nullptr, br ? Y1 : Y0, nullptr, nullptr,
                 blockIdx.x, blockIdx.y, c, smem_u32(dsm));
}

// ---------------------------------------------------------------------------
// Spatial attention v3 (R6 body): one block per (b,s), all 8 heads, 768 thr.
// Register-tiled score (2ci x 3di) and AV (p-quad) phases; pitch 260.
// __launch_bounds__(768, 2): cap regs at 42 so two CTAs co-reside per SM.
// ---------------------------------------------------------------------------
constexpr int SA_P = 260;
constexpr int SA_SMEM = (3 * CC * SA_P + HH * CC * 25) * 4;  // 94,080 B

__global__ __launch_bounds__(768, 2) void spatial_attn(
    const float* __restrict__ q, const float* __restrict__ k,
    const float* __restrict__ v, __nv_bfloat16* __restrict__ oh,
    __nv_bfloat16* __restrict__ ol)
{
    extern __shared__ float sa[];
    float* qs = sa;
    float* ks = qs + CC * SA_P;
    float* vs = ks + CC * SA_P;
    float* sc = vs + CC * SA_P;   // [192][25]

    const int s = blockIdx.x, b = blockIdx.y;
    const int t = threadIdx.x;
    const size_t gbase = ((size_t)b * CC * SS + s) * EE;
    const size_t cstride = (size_t)SS * EE;

    // ---- loads: float4, 24 rows x 64 float4-chunks per tensor ----
#pragma unroll
    for (int i = 0; i < 2; ++i) {
        const int idx = t + i * 768;          // 0..1535
        const int row = idx >> 6, e4 = idx & 63;
        const size_t g = gbase + row * cstride + e4 * 4;
        const int so = row * SA_P + e4 * 4;
        *(float4*)(qs + so) = *(const float4*)(q + g);
        *(float4*)(ks + so) = *(const float4*)(k + g);
        *(float4*)(vs + so) = *(const float4*)(v + g);
    }
    __syncthreads();

    // ---- scores: per h, 96 threads = 12 ci-groups(2) x 8 di-groups(3) ----
    {
        const int h = t / 96;
        const int r = t - h * 96;
        const int cig = r >> 3, dig = r & 7;
        const int ci0 = cig * 2, di0 = dig * 3;
        const float* qb = qs + ci0 * SA_P + h * 32;
        const float* kb = ks + di0 * SA_P + h * 32;
        float a00 = 0.f, a01 = 0.f, a02 = 0.f;
        float a10 = 0.f, a11 = 0.f, a12 = 0.f;
#pragma unroll
        for (int p = 0; p < 32; ++p) {
            const float q0 = qb[p], q1 = qb[SA_P + p];
            const float k0 = kb[p], k1 = kb[SA_P + p], k2 = kb[2 * SA_P + p];
            a00 = fmaf(q0, k0, a00); a01 = fmaf(q0, k1, a01); a02 = fmaf(q0, k2, a02);
            a10 = fmaf(q1, k0, a10); a11 = fmaf(q1, k1, a11); a12 = fmaf(q1, k2, a12);
        }
        float* sr0 = sc + (h * CC + ci0) * 25 + di0;
        float* sr1 = sr0 + 25;
        sr0[0] = a00 * INV_SQRT_P; sr0[1] = a01 * INV_SQRT_P; sr0[2] = a02 * INV_SQRT_P;
        sr1[0] = a10 * INV_SQRT_P; sr1[1] = a11 * INV_SQRT_P; sr1[2] = a12 * INV_SQRT_P;
    }
    __syncthreads();

    // ---- softmax over di (192 rows) ----
    if (t < HH * CC) {
        float* row = sc + t * 25;
        float mx = -1e30f;
#pragma unroll
        for (int d = 0; d < CC; ++d) mx = fmaxf(mx, row[d]);
        float sm = 0.f;
#pragma unroll
        for (int d = 0; d < CC; ++d) { float e = __expf(row[d] - mx); row[d] = e; sm += e; }
        const float inv = 1.f / sm;
#pragma unroll
        for (int d = 0; d < CC; ++d) row[d] *= inv;
    }
    __syncthreads();

    // ---- AV: thread -> 2 items of (h, cc, p-quad) ----
#pragma unroll
    for (int i = 0; i < 2; ++i) {
        const int item = t + i * 768;         // 0..1535
        const int h = item / 192;
        const int rr = item - h * 192;
        const int cc = rr >> 3, p4 = (rr & 7) * 4;
        const float* arow = sc + (h * CC + cc) * 25;
        const float* vb = vs + h * 32 + p4;
        float s0 = 0.f, s1 = 0.f, s2 = 0.f, s3 = 0.f;
#pragma unroll
        for (int d = 0; d < CC; ++d) {
            const float a = arow[d];
            const float4 vv = *(const float4*)(vb + d * SA_P);
            s0 = fmaf(a, vv.x, s0); s1 = fmaf(a, vv.y, s1);
            s2 = fmaf(a, vv.z, s2); s3 = fmaf(a, vv.w, s3);
        }
        const size_t g = gbase + cc * cstride + h * 32 + p4;
        __nv_bfloat16 h0, l0, h1, l1, h2, l2, h3, l3;
        split_bf16(s0, h0, l0); split_bf16(s1, h1, l1);
        split_bf16(s2, h2, l2); split_bf16(s3, h3, l3);
        *(__nv_bfloat162*)(oh + g)     = __halves2bfloat162(h0, h1);
        *(__nv_bfloat162*)(oh + g + 2) = __halves2bfloat162(h2, h3);
        *(__nv_bfloat162*)(ol + g)     = __halves2bfloat162(l0, l1);
        *(__nv_bfloat162*)(ol + g + 2) = __halves2bfloat162(l2, l3);
    }
}

// ---------------------------------------------------------------------------
// Temporal attention (f32x2 packed FMA, R6 body). o -> bf16 pair.
// ---------------------------------------------------------------------------
constexpr int QK_PAD = 132, V_PAD = 36, SC_PAD = 129;
constexpr int TEMP_SMEM_BYTES = (2 * 32 * QK_PAD + SS * V_PAD + SS * SC_PAD) * 4;

__global__ __launch_bounds__(256) void temporal_attn(
    const float* __restrict__ q, const float* __restrict__ k,
    const float* __restrict__ v, __nv_bfloat16* __restrict__ oh,
    __nv_bfloat16* __restrict__ ol)
{
    extern __shared__ float smem[];
    float* qt = smem;
    float* kt = qt + 32 * QK_PAD;
    float* vs = kt + 32 * QK_PAD;
    float* sc = vs + SS * V_PAD;

    const int c = blockIdx.x, h = blockIdx.y, b = blockIdx.z;
    const int tid = threadIdx.x;
    const size_t base = (((size_t)b * CC + c) * SS) * EE + h * PP;

    for (int idx = tid; idx < SS * PP; idx += 256) {
        const int s = idx >> 5, p = idx & 31;
        const size_t g = base + (size_t)s * EE + p;
        qt[p * QK_PAD + s] = q[g];
        kt[p * QK_PAD + s] = k[g];
        vs[s * V_PAD + p]  = v[g];
    }
    __syncthreads();

    {
        const int tx = tid & 15, ty = tid >> 4;
        unsigned long long acc2[8][4];
#pragma unroll
        for (int i = 0; i < 8; ++i)
#pragma unroll
            for (int j = 0; j < 4; ++j) acc2[i][j] = 0ull;

#pragma unroll 4
        for (int p = 0; p < PP; ++p) {
            float4 a0 = *(const float4*)&qt[p * QK_PAD + ty * 8];
            float4 a1 = *(const float4*)&qt[p * QK_PAD + ty * 8 + 4];
            float ar[8] = {a0.x, a0.y, a0.z, a0.w, a1.x, a1.y, a1.z, a1.w};
            ulonglong2 bb01 = *(const ulonglong2*)&kt[p * QK_PAD + tx * 8];
            ulonglong2 bb23 = *(const ulonglong2*)&kt[p * QK_PAD + tx * 8 + 4];
            unsigned long long bb[4] = {bb01.x, bb01.y, bb23.x, bb23.y};
#pragma unroll
            for (int i = 0; i < 8; ++i) {
                const unsigned long long ap = pack2(ar[i]);
#pragma unroll
                for (int j = 0; j < 4; ++j) fma2(acc2[i][j], ap, bb[j]);
            }
        }
#pragma unroll
        for (int i = 0; i < 8; ++i)
#pragma unroll
            for (int j = 0; j < 4; ++j) {
                float2 u = unpack2(acc2[i][j]);
                sc[(ty * 8 + i) * SC_PAD + tx * 8 + j * 2 + 0] = u.x * INV_SQRT_P;
                sc[(ty * 8 + i) * SC_PAD + tx * 8 + j * 2 + 1] = u.y * INV_SQRT_P;
            }
    }
    __syncthreads();

    {
        const int row = tid >> 1, half = tid & 1;
        float* r = sc + row * SC_PAD + half * 64;
        float mx = -1e30f;
#pragma unroll 8
        for (int t2 = 0; t2 < 64; ++t2) mx = fmaxf(mx, r[t2]);
        mx = fmaxf(mx, __shfl_xor_sync(0xffffffffu, mx, 1));
        float ssum = 0.f;
#pragma unroll 8
        for (int t2 = 0; t2 < 64; ++t2) {
            float e = __expf(r[t2] - mx);
            r[t2] = e;
            ssum += e;
        }
        ssum += __shfl_xor_sync(0xffffffffu, ssum, 1);
        const float inv = 1.f / ssum;
#pragma unroll 8
        for (int t2 = 0; t2 < 64; ++t2) r[t2] *= inv;
    }
    __syncthreads();

    {
        const int s0 = (tid >> 3) * 4;
        const int p0 = (tid & 7) * 4;
        unsigned long long acc2[4][2];
#pragma unroll
        for (int i = 0; i < 4; ++i) { acc2[i][0] = 0ull; acc2[i][1] = 0ull; }

#pragma unroll 4
        for (int t2 = 0; t2 < SS; ++t2) {
            ulonglong2 vv = *(const ulonglong2*)&vs[t2 * V_PAD + p0];
#pragma unroll
            for (int i = 0; i < 4; ++i) {
                const unsigned long long ap = pack2(sc[(s0 + i) * SC_PAD + t2]);
                fma2(acc2[i][0], ap, vv.x);
                fma2(acc2[i][1], ap, vv.y);
            }
        }
#pragma unroll
        for (int i = 0; i < 4; ++i) {
            float2 u0 = unpack2(acc2[i][0]);
            float2 u1 = unpack2(acc2[i][1]);
            float vv[4] = {u0.x, u0.y, u1.x, u1.y};
            const size_t g = base + (size_t)(s0 + i) * EE + p0;
            __nv_bfloat16 hh[4], ll[4];
#pragma unroll
            for (int j = 0; j < 4; ++j) split_bf16(vv[j], hh[j], ll[j]);
            *(__nv_bfloat162*)(oh + g)     = __halves2bfloat162(hh[0], hh[1]);
            *(__nv_bfloat162*)(oh + g + 2) = __halves2bfloat162(hh[2], hh[3]);
            *(__nv_bfloat162*)(ol + g)     = __halves2bfloat162(ll[0], ll[1]);
            *(__nv_bfloat162*)(ol + g + 2) = __halves2bfloat162(ll[2], ll[3]);
        }
    }
}

// ---------------------------------------------------------------------------
// LayerNorm kernels — warp-per-row (8 rows per 256-thread block, no barriers).
// Each lane handles 8 elems: [lane*4, lane*4+4) and [128+lane*4, 128+lane*4+4).
// ---------------------------------------------------------------------------
__device__ __forceinline__ float warp_sum(float v) {
#pragma unroll
    for (int off = 16; off > 0; off >>= 1)
        v += __shfl_xor_sync(0xffffffffu, v, off);
    return v;
}

__global__ __launch_bounds__(256) void dual_ln(
    const float* __restrict__ x, const float* __restrict__ a,
    const float* __restrict__ b2, const float* __restrict__ g,
    const float* __restrict__ beta, float* __restrict__ out,
    __nv_bfloat16* __restrict__ oh, __nv_bfloat16* __restrict__ ol)
{
    const int warp = threadIdx.x >> 5, lane = threadIdx.x & 31;
    const int row = blockIdx.x * 8 + warp;
    const size_t base = (size_t)row * EE;
    const int e0 = lane * 4, e1 = 128 + lane * 4;

    float4 x0 = *(const float4*)(x + base + e0);
    float4 x1 = *(const float4*)(x + base + e1);
    float4 a0 = *(const float4*)(a + base + e0);
    float4 a1 = *(const float4*)(a + base + e1);
    float4 b0 = *(const float4*)(b2 + base + e0);
    float4 b1 = *(const float4*)(b2 + base + e1);

    float v1[8] = {x0.x + a0.x, x0.y + a0.y, x0.z + a0.z, x0.w + a0.w,
                   x1.x + a1.x, x1.y + a1.y, x1.z + a1.z, x1.w + a1.w};
    float v2[8] = {x0.x + b0.x, x0.y + b0.y, x0.z + b0.z, x0.w + b0.w,
                   x1.x + b1.x, x1.y + b1.y, x1.z + b1.z, x1.w + b1.w};

    float s1 = 0.f, q1 = 0.f, s2 = 0.f, q2 = 0.f;
#pragma unroll
    for (int j = 0; j < 8; ++j) {
        s1 += v1[j]; q1 = fmaf(v1[j], v1[j], q1);
        s2 += v2[j]; q2 = fmaf(v2[j], v2[j], q2);
    }
    s1 = warp_sum(s1); q1 = warp_sum(q1);
    s2 = warp_sum(s2); q2 = warp_sum(q2);

    const float invE = 1.f / (float)EE;
    const float m1 = s1 * invE, m2 = s2 * invE;
    const float r1 = rsqrtf(fmaxf(q1 * invE - m1 * m1, 0.f) + LN_EPS);
    const float r2 = rsqrtf(fmaxf(q2 * invE - m2 * m2, 0.f) + LN_EPS);

    float4 g0 = *(const float4*)(g + e0);
    float4 g1 = *(const float4*)(g + e1);
    float4 t0 = *(const float4*)(beta + e0);
    float4 t1 = *(const float4*)(beta + e1);
    float gg[8] = {g0.x, g0.y, g0.z, g0.w, g1.x, g1.y, g1.z, g1.w};
    float bt[8] = {t0.x, t0.y, t0.z, t0.w, t1.x, t1.y, t1.z, t1.w};

    float o[8];
#pragma unroll
    for (int j = 0; j < 8; ++j)
        o[j] = (v1[j] - m1) * r1 * gg[j] + bt[j]
             + (v2[j] - m2) * r2 * gg[j] + bt[j];

    *(float4*)(out + base + e0) = make_float4(o[0], o[1], o[2], o[3]);
    *(float4*)(out + base + e1) = make_float4(o[4], o[5], o[6], o[7]);

    __nv_bfloat16 hh[8], ll[8];
#pragma unroll
    for (int j = 0; j < 8; ++j) split_bf16(o[j], hh[j], ll[j]);
    *(__nv_bfloat162*)(oh + base + e0)     = __halves2bfloat162(hh[0], hh[1]);
    *(__nv_bfloat162*)(oh + base + e0 + 2) = __halves2bfloat162(hh[2], hh[3]);
    *(__nv_bfloat162*)(oh + base + e1)     = __halves2bfloat162(hh[4], hh[5]);
    *(__nv_bfloat162*)(oh + base + e1 + 2) = __halves2bfloat162(hh[6], hh[7]);
    *(__nv_bfloat162*)(ol + base + e0)     = __halves2bfloat162(ll[0], ll[1]);
    *(__nv_bfloat162*)(ol + base + e0 + 2) = __halves2bfloat162(ll[2], ll[3]);
    *(__nv_bfloat162*)(ol + base + e1)     = __halves2bfloat162(ll[4], ll[5]);
    *(__nv_bfloat162*)(ol + base + e1 + 2) = __halves2bfloat162(ll[6], ll[7]);
}

__global__ __launch_bounds__(256) void final_ln(
    const float* __restrict__ a, const float* __restrict__ f,
    const float* __restrict__ g, const float* __restrict__ beta,
    float* __restrict__ out)
{
    const int warp = threadIdx.x >> 5, lane = threadIdx.x & 31;
    const int row = blockIdx.x * 8 + warp;
    const size_t base = (size_t)row * EE;
    const int e0 = lane * 4, e1 = 128 + lane * 4;

    float4 a0 = *(const float4*)(a + base + e0);
    float4 a1 = *(const float4*)(a + base + e1);
    float4 f0 = *(const float4*)(f + base + e0);
    float4 f1 = *(const float4*)(f + base + e1);

    float v[8] = {a0.x + f0.x, a0.y + f0.y, a0.z + f0.z, a0.w + f0.w,
                  a1.x + f1.x, a1.y + f1.y, a1.z + f1.z, a1.w + f1.w};

    float s = 0.f, q = 0.f;
#pragma unroll
    for (int j = 0; j < 8; ++j) { s += v[j]; q = fmaf(v[j], v[j], q); }
    s = warp_sum(s); q = warp_sum(q);

    const float invE = 1.f / (float)EE;
    const float m = s * invE;
    const float r = rsqrtf(fmaxf(q * invE - m * m, 0.f) + LN_EPS);

    float4 g0 = *(const float4*)(g + e0);
    float4 g1 = *(const float4*)(g + e1);
    float4 t0 = *(const float4*)(beta + e0);
    float4 t1 = *(const float4*)(beta + e1);
    float gg[8] = {g0.x, g0.y, g0.z, g0.w, g1.x, g1.y, g1.z, g1.w};
    float bt[8] = {t0.x, t0.y, t0.z, t0.w, t1.x, t1.y, t1.z, t1.w};

    float o[8];
#pragma unroll
    for (int j = 0; j < 8; ++j) o[j] = (v[j] - m) * r * gg[j] + bt[j];
    *(float4*)(out + base + e0) = make_float4(o[0], o[1], o[2], o[3]);
    *(float4*)(out + base + e1) = make_float4(o[4], o[5], o[6], o[7]);
}

// ---------------------------------------------------------------------------
// kernel_launch
// ---------------------------------------------------------------------------
extern "C" void kernel_launch(void* const* d_in, const int* in_sizes, int n_in,
                              void* d_out, int out_size)
{
    const float* x    = (const float*)d_in[0];
    const float* ln_g = (const float*)d_in[9];
    const float* ln_b = (const float*)d_in[10];
    const float* ff_b1 = (const float*)d_in[12];
    const float* ff_b2 = (const float*)d_in[14];
    float* out = (float*)d_out;

    float *qs, *ks, *vs, *qt, *kt, *vt, *spat, *temp, *attn, *ffo;
    __nv_bfloat16 *xh, *xl, *ah, *al, *hh, *hl, *wh, *wl;
    cudaGetSymbolAddress((void**)&qs,   g_qs);
    cudaGetSymbolAddress((void**)&ks,   g_ks);
    cudaGetSymbolAddress((void**)&vs,   g_vs);
    cudaGetSymbolAddress((void**)&qt,   g_qt);
    cudaGetSymbolAddress((void**)&kt,   g_kt);
    cudaGetSymbolAddress((void**)&vt,   g_vt);
    cudaGetSymbolAddress((void**)&spat, g_spat);
    cudaGetSymbolAddress((void**)&temp, g_temp);
    cudaGetSymbolAddress((void**)&attn, g_attn);
    cudaGetSymbolAddress((void**)&ffo,  g_ffo);
    cudaGetSymbolAddress((void**)&xh, g_xh);
    cudaGetSymbolAddress((void**)&xl, g_xl);
    cudaGetSymbolAddress((void**)&ah, g_ah);
    cudaGetSymbolAddress((void**)&al, g_al);
    cudaGetSymbolAddress((void**)&hh, g_hh);
    cudaGetSymbolAddress((void**)&hl, g_hl);
    cudaGetSymbolAddress((void**)&wh, g_wh);
    cudaGetSymbolAddress((void**)&wl, g_wl);

    cudaFuncSetAttribute(gemm_qkv6,   cudaFuncAttributeMaxDynamicSharedMemorySize, QKV_SMEM);
    cudaFuncSetAttribute(gemm_mma<1>, cudaFuncAttributeMaxDynamicSharedMemorySize, GEMM_SMEM);
    cudaFuncSetAttribute(gemm_mma<2>, cudaFuncAttributeMaxDynamicSharedMemorySize, GEMM_SMEM);
    cudaFuncSetAttribute(gemm_wo_pair, cudaFuncAttributeMaxDynamicSharedMemorySize, GEMM_SMEM);
    cudaFuncSetAttribute(spatial_attn, cudaFuncAttributeMaxDynamicSharedMemorySize, SA_SMEM);
    cudaFuncSetAttribute(temporal_attn, cudaFuncAttributeMaxDynamicSharedMemorySize, TEMP_SMEM_BYTES);

    // ---- conversions ----
    split_f32_kernel<<<NTOT / 4 / 256, 256>>>(x, xh, xl, NTOT / 4);
    WPtrs wp;
    wp.p[0] = (const float*)d_in[1];
    wp.p[1] = (const float*)d_in[2];
    wp.p[2] = (const float*)d_in[3];
    wp.p[3] = (const float*)d_in[4];
    wp.p[4] = (const float*)d_in[5];
    wp.p[5] = (const float*)d_in[6];
    wp.p[6] = (const float*)d_in[7];
    wp.p[7] = (const float*)d_in[8];
    wp.p[8] = (const float*)d_in[11];
    wp.p[9] = (const float*)d_in[13];
    convert_weights_t<<<dim3(64, CC, NW), 256>>>(wp, wh, wl);

    // ---- fused q/k/v projections (both branches) ----
    Out6 o6;
    o6.y[0] = qs; o6.y[1] = ks; o6.y[2] = vs;
    o6.y[3] = qt; o6.y[4] = kt; o6.y[5] = vt;
    gemm_qkv6<<<dim3(BB, 2, CC), 256, QKV_SMEM>>>(xh, xl, wh, wl, o6);

    // ---- attentions ----
    spatial_attn<<<dim3(SS, BB), 768, SA_SMEM>>>(qs, ks, vs, ah, al);
    temporal_attn<<<dim3(CC, HH, BB), 256, TEMP_SMEM_BYTES>>>(qt, kt, vt, hh, hl);

    // ---- output projections (merged dual launch) ----
    gemm_wo_pair<<<dim3(BB, 2, 2 * CC), 256, GEMM_SMEM>>>(
        ah, al, wh + 3*(size_t)WELEMS, wl + 3*(size_t)WELEMS, spat,
        hh, hl, wh + 7*(size_t)WELEMS, wl + 7*(size_t)WELEMS, temp);

    // ---- residual + dual LN (emits attn fp32 + bf16 pair) ----
    dual_ln<<<NROWS / 8, 256>>>(x, spat, temp, ln_g, ln_b, attn, ah, al);

    // ---- per-joint FF + final LN ----
    gemm_mma<1><<<dim3(BB, 2, CC), 256, GEMM_SMEM>>>(ah, al, wh + 8*(size_t)WELEMS, wl + 8*(size_t)WELEMS, ff_b1, nullptr, hh, hl);
    gemm_mma<2><<<dim3(BB, 2, CC), 256, GEMM_SMEM>>>(hh, hl, wh + 9*(size_t)WELEMS, wl + 9*(size_t)WELEMS, ff_b2, ffo, nullptr, nullptr);
    final_ln<<<NROWS / 8, 256>>>(attn, ffo, ln_g, ln_b, out);
}

// round 10
// speedup vs baseline: 1.5189x; 1.0139x over previous
#include <cuda_runtime.h>
#include <cuda_bf16.h>
#include <cstdint>
#include <cstddef>

// Problem dims
constexpr int BB = 16, CC = 24, SS = 128, EE = 256, HH = 8, PP = 32;
constexpr int NTOT  = BB * CC * SS * EE;     // 12,582,912
constexpr int NROWS = BB * CC * SS;          // 49,152
constexpr int WELEMS = CC * EE * EE;         // 1,572,864 per weight
constexpr int NW = 10;
constexpr float LN_EPS = 1e-6f;
constexpr float INV_SQRT_P = 0.17677669529663687f;

// ---------------------------------------------------------------------------
// Device scratch
// ---------------------------------------------------------------------------
__device__ float g_qs[NTOT], g_ks[NTOT], g_vs[NTOT];
__device__ float g_qt[NTOT], g_kt[NTOT], g_vt[NTOT];
__device__ float g_spat[NTOT], g_temp[NTOT], g_attn[NTOT], g_ffo[NTOT];
__device__ __align__(16) __nv_bfloat16 g_ah[NTOT], g_al[NTOT];   // spatial-out / attn pair
__device__ __align__(16) __nv_bfloat16 g_hh[NTOT], g_hl[NTOT];   // temporal-out / ff hidden pair
__device__ __align__(16) __nv_bfloat16 g_wh[NW * WELEMS], g_wl[NW * WELEMS];

// ---------------------------------------------------------------------------
// PTX helpers (baseline ISA only)
// ---------------------------------------------------------------------------
__device__ __forceinline__ uint32_t smem_u32(const void* p) {
    uint32_t a;
    asm("{ .reg .u64 t; cvta.to.shared.u64 t, %1; cvt.u32.u64 %0, t; }"
        : "=r"(a) : "l"(p));
    return a;
}
__device__ __forceinline__ void cp_async16(uint32_t smem, const void* gmem) {
    asm volatile("cp.async.cg.shared.global [%0], [%1], 16;"
                 :: "r"(smem), "l"(gmem));
}
__device__ __forceinline__ void cp_commit() {
    asm volatile("cp.async.commit_group;");
}
template <int N>
__device__ __forceinline__ void cp_wait() {
    asm volatile("cp.async.wait_group %0;" :: "n"(N) : "memory");
}
__device__ __forceinline__ void ldsm_x4(uint32_t& r0, uint32_t& r1,
                                        uint32_t& r2, uint32_t& r3, uint32_t addr) {
    asm volatile("ldmatrix.sync.aligned.m8n8.x4.shared.b16 {%0,%1,%2,%3}, [%4];"
                 : "=r"(r0), "=r"(r1), "=r"(r2), "=r"(r3) : "r"(addr));
}
__device__ __forceinline__ void mma_bf16(float* d, const uint32_t* a,
                                         uint32_t b0, uint32_t b1) {
    asm volatile(
        "mma.sync.aligned.m16n8k16.row.col.f32.bf16.bf16.f32 "
        "{%0,%1,%2,%3}, {%4,%5,%6,%7}, {%8,%9}, {%0,%1,%2,%3};"
        : "+f"(d[0]), "+f"(d[1]), "+f"(d[2]), "+f"(d[3])
        : "r"(a[0]), "r"(a[1]), "r"(a[2]), "r"(a[3]), "r"(b0), "r"(b1));
}
// packed f32x2
__device__ __forceinline__ unsigned long long pack2(float v) {
    unsigned long long r;
    asm("mov.b64 %0, {%1, %1};" : "=l"(r) : "f"(v));
    return r;
}
__device__ __forceinline__ void fma2(unsigned long long& d,
                                     unsigned long long a, unsigned long long b) {
    asm("fma.rn.f32x2 %0, %1, %2, %0;" : "+l"(d) : "l"(a), "l"(b));
}
__device__ __forceinline__ float2 unpack2(unsigned long long v) {
    float2 f;
    asm("mov.b64 {%0, %1}, %2;" : "=f"(f.x), "=f"(f.y) : "l"(v));
    return f;
}

// ---------------------------------------------------------------------------
// bf16 hi/lo split helpers
// ---------------------------------------------------------------------------
__device__ __forceinline__ void split_bf16(float x, __nv_bfloat16& h, __nv_bfloat16& l) {
    h = __float2bfloat16_rn(x);
    l = __float2bfloat16_rn(x - __bfloat162float(h));
}

// ---------------------------------------------------------------------------
// Weight conversion, coalesced: 32x32 (e,f) tiles via smem transpose.
// ---------------------------------------------------------------------------
struct WPtrs { const float* p[NW]; };

__global__ __launch_bounds__(256) void convert_weights_t(
    WPtrs wp, __nv_bfloat16* __restrict__ wh, __nv_bfloat16* __restrict__ wl)
{
    __shared__ float tile[32][33];
    const int w = blockIdx.z, c = blockIdx.y;
    const int eb = blockIdx.x & 7, fb = blockIdx.x >> 3;
    const int mode = (w == 3 || w >= 7) ? 0 : (w == 0 ? 1 : (w <= 2 ? 2 : 3));
    const int t = threadIdx.x;
    const int col = t & 31, r0 = t >> 5;
    const float* W = wp.p[w];

#pragma unroll
    for (int i = 0; i < 4; ++i) {
        const int row = r0 + i * 8;
        float v;
        if (mode == 0) {
            const int e = eb * 32 + row, f = fb * 32 + col;
            v = W[((size_t)c * EE + e) * EE + f];
        } else if (mode == 1) {
            const int f = fb * 32 + row, e = eb * 32 + col;
            const int h = fb, p = f & 31;
            v = W[(((size_t)h * CC + c) * PP + p) * EE + e];
        } else if (mode == 2) {
            const int e = eb * 32 + row, p = col, h = fb;
            v = W[((size_t)h * EE + e) * PP + p];
        } else {
            const int e = eb * 32 + row, p = col, h = fb;
            v = W[(((size_t)h * CC + c) * EE + e) * PP + p];
        }
        tile[row][col] = v;
    }
    __syncthreads();

#pragma unroll
    for (int i = 0; i < 4; ++i) {
        const int fr = r0 + i * 8;
        const int f = fb * 32 + fr;
        const int e = eb * 32 + col;
        const float v = (mode == 1) ? tile[fr][col] : tile[col][fr];
        __nv_bfloat16 hi, lo;
        split_bf16(v, hi, lo);
        const size_t o = (size_t)w * WELEMS + ((size_t)c << 16) + (size_t)f * EE + e;
        wh[o] = hi;
        wl[o] = lo;
    }
}

// ---------------------------------------------------------------------------
// Fused QKVx6 GEMM. A loaded from fp32 x and split to bf16 hi/lo IN-KERNEL
// (split_f32 kernel eliminated). A resident; 48 streamed B stages.
// ---------------------------------------------------------------------------
constexpr int AP = 528;
constexpr int QA_HI = 0;
constexpr int QA_LO = 128 * AP;
constexpr int QB0   = 2 * 128 * AP;
constexpr int QB_STG = 20480;
constexpr int QKV_SMEM = QB0 + 3 * QB_STG;

constexpr int GP = 80;

struct Out6 { float* y[6]; };

__global__ __launch_bounds__(256) void gemm_qkv6(
    const float* __restrict__ x,
    const __nv_bfloat16* __restrict__ whB, const __nv_bfloat16* __restrict__ wlB,
    Out6 outs)
{
    extern __shared__ __align__(16) char dsm[];
    const uint32_t sbase = smem_u32(dsm);
    const int tid = threadIdx.x;
    const int wid = tid >> 5, lane = tid & 31;
    const int b = blockIdx.x, nb = blockIdx.y, c = blockIdx.z;

    const size_t abase = ((size_t)b * CC + c) * SS * EE;

    auto issueB = [&](int stage) {
        const int w = stage >> 3, kb = (stage & 7) * 32;
        const int wg = w + (w >= 3);
        const __nv_bfloat16* Wh = whB + (size_t)wg * WELEMS + ((size_t)c << 16)
                                + (size_t)nb * 128 * EE;
        const __nv_bfloat16* Wl = wlB + (size_t)wg * WELEMS + ((size_t)c << 16)
                                + (size_t)nb * 128 * EE;
        const uint32_t sb = sbase + QB0 + (stage % 3) * QB_STG;
#pragma unroll
        for (int j = 0; j < 2; ++j) {
            const int t2 = tid + j * 256;
            const int row = t2 >> 2, ch = t2 & 3;
            const size_t goff = (size_t)row * EE + kb + ch * 8;
            const uint32_t so = row * GP + ch * 16;
            cp_async16(sb + so, Wh + goff);
            cp_async16(sb + 10240 + so, Wl + goff);
        }
    };
    issueB(0); cp_commit();
    issueB(1); cp_commit();
    issueB(2); cp_commit();

    // ---- load A from fp32 x, split to bf16 hi/lo in smem ----
#pragma unroll
    for (int i = 0; i < 16; ++i) {
        const int t2 = tid + i * 256;          // 0..4095 = 128 rows x 32 chunks(8)
        const int row = t2 >> 5, ch = t2 & 31;
        const float* src = x + abase + (size_t)row * EE + ch * 8;
        float4 v0 = *(const float4*)src;
        float4 v1 = *(const float4*)(src + 4);
        float vv[8] = {v0.x, v0.y, v0.z, v0.w, v1.x, v1.y, v1.z, v1.w};
        __nv_bfloat16 h[8], l[8];
#pragma unroll
        for (int j = 0; j < 8; ++j) split_bf16(vv[j], h[j], l[j]);
        uint4 hp, lp;
        ((__nv_bfloat162*)&hp)[0] = __halves2bfloat162(h[0], h[1]);
        ((__nv_bfloat162*)&hp)[1] = __halves2bfloat162(h[2], h[3]);
        ((__nv_bfloat162*)&hp)[2] = __halves2bfloat162(h[4], h[5]);
        ((__nv_bfloat162*)&hp)[3] = __halves2bfloat162(h[6], h[7]);
        ((__nv_bfloat162*)&lp)[0] = __halves2bfloat162(l[0], l[1]);
        ((__nv_bfloat162*)&lp)[1] = __halves2bfloat162(l[2], l[3]);
        ((__nv_bfloat162*)&lp)[2] = __halves2bfloat162(l[4], l[5]);
        ((__nv_bfloat162*)&lp)[3] = __halves2bfloat162(l[6], l[7]);
        const uint32_t so = row * AP + ch * 16;
        *(uint4*)(dsm + QA_HI + so) = hp;
        *(uint4*)(dsm + QA_LO + so) = lp;
    }

    const int wm = wid & 3, wn = wid >> 2;
    const int g = lane >> 3, lr = lane & 7;

    for (int w = 0; w < 6; ++w) {
        float acc[2][8][4];
#pragma unroll
        for (int mi = 0; mi < 2; ++mi)
#pragma unroll
            for (int nj = 0; nj < 8; ++nj)
#pragma unroll
                for (int r = 0; r < 4; ++r) acc[mi][nj][r] = 0.f;

        for (int it = 0; it < 8; ++it) {
            const int stage = w * 8 + it;
            cp_wait<2>();
            __syncthreads();
            const uint32_t Bst = sbase + QB0 + (stage % 3) * QB_STG;

#pragma unroll
            for (int pass = 0; pass < 3; ++pass) {
                const uint32_t Ab = sbase + (pass == 2 ? QA_LO : QA_HI);
                const uint32_t Bb = Bst + (pass == 1 ? 10240 : 0);
#pragma unroll
                for (int k16 = 0; k16 < 2; ++k16) {
                    uint32_t afr[2][4];
#pragma unroll
                    for (int mi = 0; mi < 2; ++mi) {
                        const int row = wm * 32 + mi * 16 + ((g & 1) << 3) + lr;
                        const uint32_t addr =
                            Ab + row * AP + (it * 4 + k16 * 2 + (g >> 1)) * 16;
                        ldsm_x4(afr[mi][0], afr[mi][1], afr[mi][2], afr[mi][3], addr);
                    }
                    uint32_t bfr[4][4];
#pragma unroll
                    for (int ni = 0; ni < 4; ++ni) {
                        const int row = wn * 64 + ni * 16 + ((g >> 1) << 3) + lr;
                        const uint32_t addr = Bb + row * GP + (k16 * 2 + (g & 1)) * 16;
                        ldsm_x4(bfr[ni][0], bfr[ni][1], bfr[ni][2], bfr[ni][3], addr);
                    }
#pragma unroll
                    for (int mi = 0; mi < 2; ++mi)
#pragma unroll
                        for (int nj = 0; nj < 8; ++nj)
                            mma_bf16(acc[mi][nj], afr[mi],
                                     bfr[nj >> 1][(nj & 1) * 2],
                                     bfr[nj >> 1][(nj & 1) * 2 + 1]);
                }
            }
            __syncthreads();
            if (stage + 3 < 48) issueB(stage + 3);
            cp_commit();
        }

        float* Yf = outs.y[w];
#pragma unroll
        for (int mi = 0; mi < 2; ++mi)
#pragma unroll
            for (int rr = 0; rr < 2; ++rr) {
                const int m = wm * 32 + mi * 16 + (lane >> 2) + rr * 8;
                const size_t yrow = abase + (size_t)m * EE + nb * 128;
#pragma unroll
                for (int nj = 0; nj < 8; ++nj) {
                    const int colo = wn * 64 + nj * 8 + (lane & 3) * 2;
                    *(float2*)(Yf + yrow + colo) =
                        make_float2(acc[mi][nj][rr * 2 + 0], acc[mi][nj][rr * 2 + 1]);
                }
            }
    }
}

// ---------------------------------------------------------------------------
// Generic HMMA GEMM body v2: 256(M)x128(N) block (2 b-slices), 8 warps with
// 64x64 warp tiles (MMA:LDSM = 4:1), BK=32, 2-stage cp.async, 1 CTA/SM.
// ---------------------------------------------------------------------------
constexpr int T_A_HI = 0;
constexpr int T_A_LO = 256 * GP;              // 20480
constexpr int T_B_HI = 2 * 256 * GP;          // 40960
constexpr int T_B_LO = T_B_HI + 128 * GP;     // 51200
constexpr int STAGE  = T_B_LO + 128 * GP;     // 61440
constexpr int GEMM_SMEM = 2 * STAGE;          // 122880

template <int EPI>
__device__ __forceinline__ void gemm_body(
    const __nv_bfloat16* __restrict__ Ah, const __nv_bfloat16* __restrict__ Al,
    const __nv_bfloat16* __restrict__ Wh, const __nv_bfloat16* __restrict__ Wl,
    const float* __restrict__ bias,
    float* __restrict__ Yf,
    __nv_bfloat16* __restrict__ Yh, __nv_bfloat16* __restrict__ Yl,
    int b0, int nb, int c, uint32_t sbase)
{
    const int tid = threadIdx.x;
    const int wid = tid >> 5, lane = tid & 31;

    const size_t abase0 = ((size_t)b0 * CC + c) * SS * EE;
    const size_t bstride = (size_t)CC * SS * EE;      // b -> b+1
    const size_t wbase = (size_t)c * EE * EE + (size_t)nb * 128 * EE;

    auto issue = [&](int stg) {
        const int kb = stg * 32;
        const uint32_t sb = sbase + (stg & 1) * STAGE;
        // A: 256 rows x 4 chunks (hi & lo)
#pragma unroll
        for (int j = 0; j < 4; ++j) {
            const int t2 = tid + j * 256;             // 0..1023
            const int row = t2 >> 2, ch = t2 & 3;
            const int bo = row >> 7, s = row & 127;
            const size_t goff = abase0 + (size_t)bo * bstride + (size_t)s * EE + kb + ch * 8;
            const uint32_t so = row * GP + ch * 16;
            cp_async16(sb + T_A_HI + so, Ah + goff);
            cp_async16(sb + T_A_LO + so, Al + goff);
        }
        // B: 128 rows x 4 chunks (hi & lo)
#pragma unroll
        for (int j = 0; j < 2; ++j) {
            const int t2 = tid + j * 256;             // 0..511
            const int row = t2 >> 2, ch = t2 & 3;
            const size_t goff = wbase + (size_t)row * EE + kb + ch * 8;
            const uint32_t so = row * GP + ch * 16;
            cp_async16(sb + T_B_HI + so, Wh + goff);
            cp_async16(sb + T_B_LO + so, Wl + goff);
        }
    };
    issue(0); cp_commit();
    issue(1); cp_commit();

    const int wm = wid & 3, wn = wid >> 2;            // 4 m-groups x 2 n-groups (64x64)
    const int g = lane >> 3, lr = lane & 7;

    float acc[4][8][4];
#pragma unroll
    for (int mi = 0; mi < 4; ++mi)
#pragma unroll
        for (int nj = 0; nj < 8; ++nj)
#pragma unroll
            for (int r = 0; r < 4; ++r) acc[mi][nj][r] = 0.f;

    for (int it = 0; it < 8; ++it) {
        cp_wait<1>();
        __syncthreads();
        const uint32_t st = sbase + (it & 1) * STAGE;

#pragma unroll
        for (int pass = 0; pass < 3; ++pass) {
            const uint32_t Ab = st + (pass == 2 ? T_A_LO : T_A_HI);
            const uint32_t Bb = st + (pass == 1 ? T_B_LO : T_B_HI);
#pragma unroll
            for (int k16 = 0; k16 < 2; ++k16) {
                uint32_t afr[4][4];
#pragma unroll
                for (int mi = 0; mi < 4; ++mi) {
                    const int row = wm * 64 + mi * 16 + ((g & 1) << 3) + lr;
                    const uint32_t addr = Ab + row * GP + (k16 * 2 + (g >> 1)) * 16;
                    ldsm_x4(afr[mi][0], afr[mi][1], afr[mi][2], afr[mi][3], addr);
                }
                uint32_t bfr[4][4];
#pragma unroll
                for (int ni = 0; ni < 4; ++ni) {
                    const int row = wn * 64 + ni * 16 + ((g >> 1) << 3) + lr;
                    const uint32_t addr = Bb + row * GP + (k16 * 2 + (g & 1)) * 16;
                    ldsm_x4(bfr[ni][0], bfr[ni][1], bfr[ni][2], bfr[ni][3], addr);
                }
#pragma unroll
                for (int mi = 0; mi < 4; ++mi)
#pragma unroll
                    for (int nj = 0; nj < 8; ++nj)
                        mma_bf16(acc[mi][nj], afr[mi],
                                 bfr[nj >> 1][(nj & 1) * 2],
                                 bfr[nj >> 1][(nj & 1) * 2 + 1]);
            }
        }
        __syncthreads();
        if (it + 2 < 8) issue(it + 2);
        cp_commit();
    }

#pragma unroll
    for (int mi = 0; mi < 4; ++mi) {
#pragma unroll
        for (int rr = 0; rr < 2; ++rr) {
            const int m = wm * 64 + mi * 16 + (lane >> 2) + rr * 8;
            const int bo = m >> 7, s = m & 127;
            const size_t yrow = abase0 + (size_t)bo * bstride + (size_t)s * EE + nb * 128;
#pragma unroll
            for (int nj = 0; nj < 8; ++nj) {
                const int col = wn * 64 + nj * 8 + (lane & 3) * 2;
                float v0 = acc[mi][nj][rr * 2 + 0];
                float v1 = acc[mi][nj][rr * 2 + 1];
                if constexpr (EPI == 0) {
                    *(float2*)(Yf + yrow + col) = make_float2(v0, v1);
                } else {
                    const float* bp = bias + (size_t)c * EE + nb * 128 + col;
                    v0 += bp[0];
                    v1 += bp[1];
                    if constexpr (EPI == 1) {
                        v0 = fmaxf(v0, 0.f);
                        v1 = fmaxf(v1, 0.f);
                        __nv_bfloat16 h0, l0, h1, l1;
                        split_bf16(v0, h0, l0);
                        split_bf16(v1, h1, l1);
                        *(__nv_bfloat162*)(Yh + yrow + col) = __halves2bfloat162(h0, h1);
                        *(__nv_bfloat162*)(Yl + yrow + col) = __halves2bfloat162(l0, l1);
                    } else {
                        *(float2*)(Yf + yrow + col) = make_float2(v0, v1);
                    }
                }
            }
        }
    }
}

template <int EPI>
__global__ __launch_bounds__(256) void gemm_mma(
    const __nv_bfloat16* __restrict__ Ah, const __nv_bfloat16* __restrict__ Al,
    const __nv_bfloat16* __restrict__ Wh, const __nv_bfloat16* __restrict__ Wl,
    const float* __restrict__ bias,
    float* __restrict__ Yf,
    __nv_bfloat16* __restrict__ Yh, __nv_bfloat16* __restrict__ Yl)
{
    extern __shared__ __align__(16) char dsm[];
    gemm_body<EPI>(Ah, Al, Wh, Wl, bias, Yf, Yh, Yl,
                   blockIdx.x * 2, blockIdx.y, blockIdx.z, smem_u32(dsm));
}

// Merged dual output-projection launch (spat and temp branches).
__global__ __launch_bounds__(256) void gemm_wo_pair(
    const __nv_bfloat16* __restrict__ Ah0, const __nv_bfloat16* __restrict__ Al0,
    const __nv_bfloat16* __restrict__ Wh0, const __nv_bfloat16* __restrict__ Wl0,
    float* __restrict__ Y0,
    const __nv_bfloat16* __restrict__ Ah1, const __nv_bfloat16* __restrict__ Al1,
    const __nv_bfloat16* __restrict__ Wh1, const __nv_bfloat16* __restrict__ Wl1,
    float* __restrict__ Y1)
{
    extern __shared__ __align__(16) char dsm[];
    const int zz = blockIdx.z;
    const int br = zz >= CC;
    const int c = br ? zz - CC : zz;
    gemm_body<0>(br ? Ah1 : Ah0, br ? Al1 : Al0,
                 br ? Wh1 : Wh0, br ? Wl1 : Wl0,
                 nullptr, br ? Y1 : Y0, nullptr, nullptr,
                 blockIdx.x * 2, blockIdx.y, c, smem_u32(dsm));
}

// ---------------------------------------------------------------------------
// Spatial attention (R9 winner): one block per (b,s), 8 heads, 768 thr, 2 CTA/SM.
// ---------------------------------------------------------------------------
constexpr int SA_P = 260;
constexpr int SA_SMEM = (3 * CC * SA_P + HH * CC * 25) * 4;  // 94,080 B

__global__ __launch_bounds__(768, 2) void spatial_attn(
    const float* __restrict__ q, const float* __restrict__ k,
    const float* __restrict__ v, __nv_bfloat16* __restrict__ oh,
    __nv_bfloat16* __restrict__ ol)
{
    extern __shared__ float sa[];
    float* qs = sa;
    float* ks = qs + CC * SA_P;
    float* vs = ks + CC * SA_P;
    float* sc = vs + CC * SA_P;   // [192][25]

    const int s = blockIdx.x, b = blockIdx.y;
    const int t = threadIdx.x;
    const size_t gbase = ((size_t)b * CC * SS + s) * EE;
    const size_t cstride = (size_t)SS * EE;

#pragma unroll
    for (int i = 0; i < 2; ++i) {
        const int idx = t + i * 768;
        const int row = idx >> 6, e4 = idx & 63;
        const size_t g = gbase + row * cstride + e4 * 4;
        const int so = row * SA_P + e4 * 4;
        *(float4*)(qs + so) = *(const float4*)(q + g);
        *(float4*)(ks + so) = *(const float4*)(k + g);
        *(float4*)(vs + so) = *(const float4*)(v + g);
    }
    __syncthreads();

    {
        const int h = t / 96;
        const int r = t - h * 96;
        const int cig = r >> 3, dig = r & 7;
        const int ci0 = cig * 2, di0 = dig * 3;
        const float* qb = qs + ci0 * SA_P + h * 32;
        const float* kb = ks + di0 * SA_P + h * 32;
        float a00 = 0.f, a01 = 0.f, a02 = 0.f;
        float a10 = 0.f, a11 = 0.f, a12 = 0.f;
#pragma unroll
        for (int p = 0; p < 32; ++p) {
            const float q0 = qb[p], q1 = qb[SA_P + p];
            const float k0 = kb[p], k1 = kb[SA_P + p], k2 = kb[2 * SA_P + p];
            a00 = fmaf(q0, k0, a00); a01 = fmaf(q0, k1, a01); a02 = fmaf(q0, k2, a02);
            a10 = fmaf(q1, k0, a10); a11 = fmaf(q1, k1, a11); a12 = fmaf(q1, k2, a12);
        }
        float* sr0 = sc + (h * CC + ci0) * 25 + di0;
        float* sr1 = sr0 + 25;
        sr0[0] = a00 * INV_SQRT_P; sr0[1] = a01 * INV_SQRT_P; sr0[2] = a02 * INV_SQRT_P;
        sr1[0] = a10 * INV_SQRT_P; sr1[1] = a11 * INV_SQRT_P; sr1[2] = a12 * INV_SQRT_P;
    }
    __syncthreads();

    if (t < HH * CC) {
        float* row = sc + t * 25;
        float mx = -1e30f;
#pragma unroll
        for (int d = 0; d < CC; ++d) mx = fmaxf(mx, row[d]);
        float sm = 0.f;
#pragma unroll
        for (int d = 0; d < CC; ++d) { float e = __expf(row[d] - mx); row[d] = e; sm += e; }
        const float inv = 1.f / sm;
#pragma unroll
        for (int d = 0; d < CC; ++d) row[d] *= inv;
    }
    __syncthreads();

#pragma unroll
    for (int i = 0; i < 2; ++i) {
        const int item = t + i * 768;
        const int h = item / 192;
        const int rr = item - h * 192;
        const int cc = rr >> 3, p4 = (rr & 7) * 4;
        const float* arow = sc + (h * CC + cc) * 25;
        const float* vb = vs + h * 32 + p4;
        float s0 = 0.f, s1 = 0.f, s2 = 0.f, s3 = 0.f;
#pragma unroll
        for (int d = 0; d < CC; ++d) {
            const float a = arow[d];
            const float4 vv = *(const float4*)(vb + d * SA_P);
            s0 = fmaf(a, vv.x, s0); s1 = fmaf(a, vv.y, s1);
            s2 = fmaf(a, vv.z, s2); s3 = fmaf(a, vv.w, s3);
        }
        const size_t g = gbase + cc * cstride + h * 32 + p4;
        __nv_bfloat16 h0, l0, h1, l1, h2, l2, h3, l3;
        split_bf16(s0, h0, l0); split_bf16(s1, h1, l1);
        split_bf16(s2, h2, l2); split_bf16(s3, h3, l3);
        *(__nv_bfloat162*)(oh + g)     = __halves2bfloat162(h0, h1);
        *(__nv_bfloat162*)(oh + g + 2) = __halves2bfloat162(h2, h3);
        *(__nv_bfloat162*)(ol + g)     = __halves2bfloat162(l0, l1);
        *(__nv_bfloat162*)(ol + g + 2) = __halves2bfloat162(l2, l3);
    }
}

// ---------------------------------------------------------------------------
// Temporal attention (f32x2 packed FMA). o -> bf16 pair.
// ---------------------------------------------------------------------------
constexpr int QK_PAD = 132, V_PAD = 36, SC_PAD = 129;
constexpr int TEMP_SMEM_BYTES = (2 * 32 * QK_PAD + SS * V_PAD + SS * SC_PAD) * 4;

__global__ __launch_bounds__(256) void temporal_attn(
    const float* __restrict__ q, const float* __restrict__ k,
    const float* __restrict__ v, __nv_bfloat16* __restrict__ oh,
    __nv_bfloat16* __restrict__ ol)
{
    extern __shared__ float smem[];
    float* qt = smem;
    float* kt = qt + 32 * QK_PAD;
    float* vs = kt + 32 * QK_PAD;
    float* sc = vs + SS * V_PAD;

    const int c = blockIdx.x, h = blockIdx.y, b = blockIdx.z;
    const int tid = threadIdx.x;
    const size_t base = (((size_t)b * CC + c) * SS) * EE + h * PP;

    for (int idx = tid; idx < SS * PP; idx += 256) {
        const int s = idx >> 5, p = idx & 31;
        const size_t g = base + (size_t)s * EE + p;
        qt[p * QK_PAD + s] = q[g];
        kt[p * QK_PAD + s] = k[g];
        vs[s * V_PAD + p]  = v[g];
    }
    __syncthreads();

    {
        const int tx = tid & 15, ty = tid >> 4;
        unsigned long long acc2[8][4];
#pragma unroll
        for (int i = 0; i < 8; ++i)
#pragma unroll
            for (int j = 0; j < 4; ++j) acc2[i][j] = 0ull;

#pragma unroll 4
        for (int p = 0; p < PP; ++p) {
            float4 a0 = *(const float4*)&qt[p * QK_PAD + ty * 8];
            float4 a1 = *(const float4*)&qt[p * QK_PAD + ty * 8 + 4];
            float ar[8] = {a0.x, a0.y, a0.z, a0.w, a1.x, a1.y, a1.z, a1.w};
            ulonglong2 bb01 = *(const ulonglong2*)&kt[p * QK_PAD + tx * 8];
            ulonglong2 bb23 = *(const ulonglong2*)&kt[p * QK_PAD + tx * 8 + 4];
            unsigned long long bb[4] = {bb01.x, bb01.y, bb23.x, bb23.y};
#pragma unroll
            for (int i = 0; i < 8; ++i) {
                const unsigned long long ap = pack2(ar[i]);
#pragma unroll
                for (int j = 0; j < 4; ++j) fma2(acc2[i][j], ap, bb[j]);
            }
        }
#pragma unroll
        for (int i = 0; i < 8; ++i)
#pragma unroll
            for (int j = 0; j < 4; ++j) {
                float2 u = unpack2(acc2[i][j]);
                sc[(ty * 8 + i) * SC_PAD + tx * 8 + j * 2 + 0] = u.x * INV_SQRT_P;
                sc[(ty * 8 + i) * SC_PAD + tx * 8 + j * 2 + 1] = u.y * INV_SQRT_P;
            }
    }
    __syncthreads();

    {
        const int row = tid >> 1, half = tid & 1;
        float* r = sc + row * SC_PAD + half * 64;
        float mx = -1e30f;
#pragma unroll 8
        for (int t2 = 0; t2 < 64; ++t2) mx = fmaxf(mx, r[t2]);
        mx = fmaxf(mx, __shfl_xor_sync(0xffffffffu, mx, 1));
        float ssum = 0.f;
#pragma unroll 8
        for (int t2 = 0; t2 < 64; ++t2) {
            float e = __expf(r[t2] - mx);
            r[t2] = e;
            ssum += e;
        }
        ssum += __shfl_xor_sync(0xffffffffu, ssum, 1);
        const float inv = 1.f / ssum;
#pragma unroll 8
        for (int t2 = 0; t2 < 64; ++t2) r[t2] *= inv;
    }
    __syncthreads();

    {
        const int s0 = (tid >> 3) * 4;
        const int p0 = (tid & 7) * 4;
        unsigned long long acc2[4][2];
#pragma unroll
        for (int i = 0; i < 4; ++i) { acc2[i][0] = 0ull; acc2[i][1] = 0ull; }

#pragma unroll 4
        for (int t2 = 0; t2 < SS; ++t2) {
            ulonglong2 vv = *(const ulonglong2*)&vs[t2 * V_PAD + p0];
#pragma unroll
            for (int i = 0; i < 4; ++i) {
                const unsigned long long ap = pack2(sc[(s0 + i) * SC_PAD + t2]);
                fma2(acc2[i][0], ap, vv.x);
                fma2(acc2[i][1], ap, vv.y);
            }
        }
#pragma unroll
        for (int i = 0; i < 4; ++i) {
            float2 u0 = unpack2(acc2[i][0]);
            float2 u1 = unpack2(acc2[i][1]);
            float vv[4] = {u0.x, u0.y, u1.x, u1.y};
            const size_t g = base + (size_t)(s0 + i) * EE + p0;
            __nv_bfloat16 hh[4], ll[4];
#pragma unroll
            for (int j = 0; j < 4; ++j) split_bf16(vv[j], hh[j], ll[j]);
            *(__nv_bfloat162*)(oh + g)     = __halves2bfloat162(hh[0], hh[1]);
            *(__nv_bfloat162*)(oh + g + 2) = __halves2bfloat162(hh[2], hh[3]);
            *(__nv_bfloat162*)(ol + g)     = __halves2bfloat162(ll[0], ll[1]);
            *(__nv_bfloat162*)(ol + g + 2) = __halves2bfloat162(ll[2], ll[3]);
        }
    }
}

// ---------------------------------------------------------------------------
// LayerNorm kernels — warp-per-row (R9 winners).
// ---------------------------------------------------------------------------
__device__ __forceinline__ float warp_sum(float v) {
#pragma unroll
    for (int off = 16; off > 0; off >>= 1)
        v += __shfl_xor_sync(0xffffffffu, v, off);
    return v;
}

__global__ __launch_bounds__(256) void dual_ln(
    const float* __restrict__ x, const float* __restrict__ a,
    const float* __restrict__ b2, const float* __restrict__ g,
    const float* __restrict__ beta, float* __restrict__ out,
    __nv_bfloat16* __restrict__ oh, __nv_bfloat16* __restrict__ ol)
{
    const int warp = threadIdx.x >> 5, lane = threadIdx.x & 31;
    const int row = blockIdx.x * 8 + warp;
    const size_t base = (size_t)row * EE;
    const int e0 = lane * 4, e1 = 128 + lane * 4;

    float4 x0 = *(const float4*)(x + base + e0);
    float4 x1 = *(const float4*)(x + base + e1);
    float4 a0 = *(const float4*)(a + base + e0);
    float4 a1 = *(const float4*)(a + base + e1);
    float4 b0 = *(const float4*)(b2 + base + e0);
    float4 b1 = *(const float4*)(b2 + base + e1);

    float v1[8] = {x0.x + a0.x, x0.y + a0.y, x0.z + a0.z, x0.w + a0.w,
                   x1.x + a1.x, x1.y + a1.y, x1.z + a1.z, x1.w + a1.w};
    float v2[8] = {x0.x + b0.x, x0.y + b0.y, x0.z + b0.z, x0.w + b0.w,
                   x1.x + b1.x, x1.y + b1.y, x1.z + b1.z, x1.w + b1.w};

    float s1 = 0.f, q1 = 0.f, s2 = 0.f, q2 = 0.f;
#pragma unroll
    for (int j = 0; j < 8; ++j) {
        s1 += v1[j]; q1 = fmaf(v1[j], v1[j], q1);
        s2 += v2[j]; q2 = fmaf(v2[j], v2[j], q2);
    }
    s1 = warp_sum(s1); q1 = warp_sum(q1);
    s2 = warp_sum(s2); q2 = warp_sum(q2);

    const float invE = 1.f / (float)EE;
    const float m1 = s1 * invE, m2 = s2 * invE;
    const float r1 = rsqrtf(fmaxf(q1 * invE - m1 * m1, 0.f) + LN_EPS);
    const float r2 = rsqrtf(fmaxf(q2 * invE - m2 * m2, 0.f) + LN_EPS);

    float4 g0 = *(const float4*)(g + e0);
    float4 g1 = *(const float4*)(g + e1);
    float4 t0 = *(const float4*)(beta + e0);
    float4 t1 = *(const float4*)(beta + e1);
    float gg[8] = {g0.x, g0.y, g0.z, g0.w, g1.x, g1.y, g1.z, g1.w};
    float bt[8] = {t0.x, t0.y, t0.z, t0.w, t1.x, t1.y, t1.z, t1.w};

    float o[8];
#pragma unroll
    for (int j = 0; j < 8; ++j)
        o[j] = (v1[j] - m1) * r1 * gg[j] + bt[j]
             + (v2[j] - m2) * r2 * gg[j] + bt[j];

    *(float4*)(out + base + e0) = make_float4(o[0], o[1], o[2], o[3]);
    *(float4*)(out + base + e1) = make_float4(o[4], o[5], o[6], o[7]);

    __nv_bfloat16 hh[8], ll[8];
#pragma unroll
    for (int j = 0; j < 8; ++j) split_bf16(o[j], hh[j], ll[j]);
    *(__nv_bfloat162*)(oh + base + e0)     = __halves2bfloat162(hh[0], hh[1]);
    *(__nv_bfloat162*)(oh + base + e0 + 2) = __halves2bfloat162(hh[2], hh[3]);
    *(__nv_bfloat162*)(oh + base + e1)     = __halves2bfloat162(hh[4], hh[5]);
    *(__nv_bfloat162*)(oh + base + e1 + 2) = __halves2bfloat162(hh[6], hh[7]);
    *(__nv_bfloat162*)(ol + base + e0)     = __halves2bfloat162(ll[0], ll[1]);
    *(__nv_bfloat162*)(ol + base + e0 + 2) = __halves2bfloat162(ll[2], ll[3]);
    *(__nv_bfloat162*)(ol + base + e1)     = __halves2bfloat162(ll[4], ll[5]);
    *(__nv_bfloat162*)(ol + base + e1 + 2) = __halves2bfloat162(ll[6], ll[7]);
}

__global__ __launch_bounds__(256) void final_ln(
    const float* __restrict__ a, const float* __restrict__ f,
    const float* __restrict__ g, const float* __restrict__ beta,
    float* __restrict__ out)
{
    const int warp = threadIdx.x >> 5, lane = threadIdx.x & 31;
    const int row = blockIdx.x * 8 + warp;
    const size_t base = (size_t)row * EE;
    const int e0 = lane * 4, e1 = 128 + lane * 4;

    float4 a0 = *(const float4*)(a + base + e0);
    float4 a1 = *(const float4*)(a + base + e1);
    float4 f0 = *(const float4*)(f + base + e0);
    float4 f1 = *(const float4*)(f + base + e1);

    float v[8] = {a0.x + f0.x, a0.y + f0.y, a0.z + f0.z, a0.w + f0.w,
                  a1.x + f1.x, a1.y + f1.y, a1.z + f1.z, a1.w + f1.w};

    float s = 0.f, q = 0.f;
#pragma unroll
    for (int j = 0; j < 8; ++j) { s += v[j]; q = fmaf(v[j], v[j], q); }
    s = warp_sum(s); q = warp_sum(q);

    const float invE = 1.f / (float)EE;
    const float m = s * invE;
    const float r = rsqrtf(fmaxf(q * invE - m * m, 0.f) + LN_EPS);

    float4 g0 = *(const float4*)(g + e0);
    float4 g1 = *(const float4*)(g + e1);
    float4 t0 = *(const float4*)(beta + e0);
    float4 t1 = *(const float4*)(beta + e1);
    float gg[8] = {g0.x, g0.y, g0.z, g0.w, g1.x, g1.y, g1.z, g1.w};
    float bt[8] = {t0.x, t0.y, t0.z, t0.w, t1.x, t1.y, t1.z, t1.w};

    float o[8];
#pragma unroll
    for (int j = 0; j < 8; ++j) o[j] = (v[j] - m) * r * gg[j] + bt[j];
    *(float4*)(out + base + e0) = make_float4(o[0], o[1], o[2], o[3]);
    *(float4*)(out + base + e1) = make_float4(o[4], o[5], o[6], o[7]);
}

// ---------------------------------------------------------------------------
// kernel_launch
// ---------------------------------------------------------------------------
extern "C" void kernel_launch(void* const* d_in, const int* in_sizes, int n_in,
                              void* d_out, int out_size)
{
    const float* x    = (const float*)d_in[0];
    const float* ln_g = (const float*)d_in[9];
    const float* ln_b = (const float*)d_in[10];
    const float* ff_b1 = (const float*)d_in[12];
    const float* ff_b2 = (const float*)d_in[14];
    float* out = (float*)d_out;

    float *qs, *ks, *vs, *qt, *kt, *vt, *spat, *temp, *attn, *ffo;
    __nv_bfloat16 *ah, *al, *hh, *hl, *wh, *wl;
    cudaGetSymbolAddress((void**)&qs,   g_qs);
    cudaGetSymbolAddress((void**)&ks,   g_ks);
    cudaGetSymbolAddress((void**)&vs,   g_vs);
    cudaGetSymbolAddress((void**)&qt,   g_qt);
    cudaGetSymbolAddress((void**)&kt,   g_kt);
    cudaGetSymbolAddress((void**)&vt,   g_vt);
    cudaGetSymbolAddress((void**)&spat, g_spat);
    cudaGetSymbolAddress((void**)&temp, g_temp);
    cudaGetSymbolAddress((void**)&attn, g_attn);
    cudaGetSymbolAddress((void**)&ffo,  g_ffo);
    cudaGetSymbolAddress((void**)&ah, g_ah);
    cudaGetSymbolAddress((void**)&al, g_al);
    cudaGetSymbolAddress((void**)&hh, g_hh);
    cudaGetSymbolAddress((void**)&hl, g_hl);
    cudaGetSymbolAddress((void**)&wh, g_wh);
    cudaGetSymbolAddress((void**)&wl, g_wl);

    cudaFuncSetAttribute(gemm_qkv6,   cudaFuncAttributeMaxDynamicSharedMemorySize, QKV_SMEM);
    cudaFuncSetAttribute(gemm_mma<1>, cudaFuncAttributeMaxDynamicSharedMemorySize, GEMM_SMEM);
    cudaFuncSetAttribute(gemm_mma<2>, cudaFuncAttributeMaxDynamicSharedMemorySize, GEMM_SMEM);
    cudaFuncSetAttribute(gemm_wo_pair, cudaFuncAttributeMaxDynamicSharedMemorySize, GEMM_SMEM);
    cudaFuncSetAttribute(spatial_attn, cudaFuncAttributeMaxDynamicSharedMemorySize, SA_SMEM);
    cudaFuncSetAttribute(temporal_attn, cudaFuncAttributeMaxDynamicSharedMemorySize, TEMP_SMEM_BYTES);

    // ---- weight conversion ----
    WPtrs wp;
    wp.p[0] = (const float*)d_in[1];
    wp.p[1] = (const float*)d_in[2];
    wp.p[2] = (const float*)d_in[3];
    wp.p[3] = (const float*)d_in[4];
    wp.p[4] = (const float*)d_in[5];
    wp.p[5] = (const float*)d_in[6];
    wp.p[6] = (const float*)d_in[7];
    wp.p[7] = (const float*)d_in[8];
    wp.p[8] = (const float*)d_in[11];
    wp.p[9] = (const float*)d_in[13];
    convert_weights_t<<<dim3(64, CC, NW), 256>>>(wp, wh, wl);

    // ---- fused q/k/v projections (x split in-kernel) ----
    Out6 o6;
    o6.y[0] = qs; o6.y[1] = ks; o6.y[2] = vs;
    o6.y[3] = qt; o6.y[4] = kt; o6.y[5] = vt;
    gemm_qkv6<<<dim3(BB, 2, CC), 256, QKV_SMEM>>>(x, wh, wl, o6);

    // ---- attentions ----
    spatial_attn<<<dim3(SS, BB), 768, SA_SMEM>>>(qs, ks, vs, ah, al);
    temporal_attn<<<dim3(CC, HH, BB), 256, TEMP_SMEM_BYTES>>>(qt, kt, vt, hh, hl);

    // ---- output projections (merged dual launch, M=256 blocks) ----
    gemm_wo_pair<<<dim3(BB / 2, 2, 2 * CC), 256, GEMM_SMEM>>>(
        ah, al, wh + 3*(size_t)WELEMS, wl + 3*(size_t)WELEMS, spat,
        hh, hl, wh + 7*(size_t)WELEMS, wl + 7*(size_t)WELEMS, temp);

    // ---- residual + dual LN (emits attn fp32 + bf16 pair) ----
    dual_ln<<<NROWS / 8, 256>>>(x, spat, temp, ln_g, ln_b, attn, ah, al);

    // ---- per-joint FF + final LN ----
    gemm_mma<1><<<dim3(BB / 2, 2, CC), 256, GEMM_SMEM>>>(ah, al, wh + 8*(size_t)WELEMS, wl + 8*(size_t)WELEMS, ff_b1, nullptr, hh, hl);
    gemm_mma<2><<<dim3(BB / 2, 2, CC), 256, GEMM_SMEM>>>(hh, hl, wh + 9*(size_t)WELEMS, wl + 9*(size_t)WELEMS, ff_b2, ffo, nullptr, nullptr);
    final_ln<<<NROWS / 8, 256>>>(attn, ffo, ln_g, ln_b, out);
}

// round 11
// speedup vs baseline: 1.6470x; 1.0843x over previous
#include <cuda_runtime.h>
#include <cuda_bf16.h>
#include <cstdint>
#include <cstddef>

// Problem dims
constexpr int BB = 16, CC = 24, SS = 128, EE = 256, HH = 8, PP = 32;
constexpr int NTOT  = BB * CC * SS * EE;     // 12,582,912
constexpr int NROWS = BB * CC * SS;          // 49,152
constexpr int WELEMS = CC * EE * EE;         // 1,572,864 per weight
constexpr int NW = 10;
constexpr float LN_EPS = 1e-6f;
constexpr float INV_SQRT_P = 0.17677669529663687f;

// ---------------------------------------------------------------------------
// Device scratch
// ---------------------------------------------------------------------------
__device__ float g_qs[NTOT], g_ks[NTOT], g_vs[NTOT];
__device__ float g_qt[NTOT], g_kt[NTOT], g_vt[NTOT];
__device__ float g_spat[NTOT], g_temp[NTOT], g_attn[NTOT], g_ffo[NTOT];
__device__ __align__(16) __nv_bfloat16 g_ah[NTOT], g_al[NTOT];   // spatial-out / attn pair
__device__ __align__(16) __nv_bfloat16 g_hh[NTOT], g_hl[NTOT];   // temporal-out / ff hidden pair
__device__ __align__(16) __nv_bfloat16 g_wh[NW * WELEMS], g_wl[NW * WELEMS];

// ---------------------------------------------------------------------------
// PTX helpers (baseline ISA only)
// ---------------------------------------------------------------------------
__device__ __forceinline__ uint32_t smem_u32(const void* p) {
    uint32_t a;
    asm("{ .reg .u64 t; cvta.to.shared.u64 t, %1; cvt.u32.u64 %0, t; }"
        : "=r"(a) : "l"(p));
    return a;
}
__device__ __forceinline__ void cp_async16(uint32_t smem, const void* gmem) {
    asm volatile("cp.async.cg.shared.global [%0], [%1], 16;"
                 :: "r"(smem), "l"(gmem));
}
__device__ __forceinline__ void cp_commit() {
    asm volatile("cp.async.commit_group;");
}
template <int N>
__device__ __forceinline__ void cp_wait() {
    asm volatile("cp.async.wait_group %0;" :: "n"(N) : "memory");
}
__device__ __forceinline__ void ldsm_x4(uint32_t& r0, uint32_t& r1,
                                        uint32_t& r2, uint32_t& r3, uint32_t addr) {
    asm volatile("ldmatrix.sync.aligned.m8n8.x4.shared.b16 {%0,%1,%2,%3}, [%4];"
                 : "=r"(r0), "=r"(r1), "=r"(r2), "=r"(r3) : "r"(addr));
}
__device__ __forceinline__ void mma_bf16(float* d, const uint32_t* a,
                                         uint32_t b0, uint32_t b1) {
    asm volatile(
        "mma.sync.aligned.m16n8k16.row.col.f32.bf16.bf16.f32 "
        "{%0,%1,%2,%3}, {%4,%5,%6,%7}, {%8,%9}, {%0,%1,%2,%3};"
        : "+f"(d[0]), "+f"(d[1]), "+f"(d[2]), "+f"(d[3])
        : "r"(a[0]), "r"(a[1]), "r"(a[2]), "r"(a[3]), "r"(b0), "r"(b1));
}
// packed f32x2
__device__ __forceinline__ unsigned long long pack2(float v) {
    unsigned long long r;
    asm("mov.b64 %0, {%1, %1};" : "=l"(r) : "f"(v));
    return r;
}
__device__ __forceinline__ void fma2(unsigned long long& d,
                                     unsigned long long a, unsigned long long b) {
    asm("fma.rn.f32x2 %0, %1, %2, %0;" : "+l"(d) : "l"(a), "l"(b));
}
__device__ __forceinline__ float2 unpack2(unsigned long long v) {
    float2 f;
    asm("mov.b64 {%0, %1}, %2;" : "=f"(f.x), "=f"(f.y) : "l"(v));
    return f;
}

// ---------------------------------------------------------------------------
// bf16 hi/lo split helpers
// ---------------------------------------------------------------------------
__device__ __forceinline__ void split_bf16(float x, __nv_bfloat16& h, __nv_bfloat16& l) {
    h = __float2bfloat16_rn(x);
    l = __float2bfloat16_rn(x - __bfloat162float(h));
}

// ---------------------------------------------------------------------------
// Weight conversion, coalesced: 32x32 (e,f) tiles via smem transpose.
// ---------------------------------------------------------------------------
struct WPtrs { const float* p[NW]; };

__global__ __launch_bounds__(256) void convert_weights_t(
    WPtrs wp, __nv_bfloat16* __restrict__ wh, __nv_bfloat16* __restrict__ wl)
{
    __shared__ float tile[32][33];
    const int w = blockIdx.z, c = blockIdx.y;
    const int eb = blockIdx.x & 7, fb = blockIdx.x >> 3;
    const int mode = (w == 3 || w >= 7) ? 0 : (w == 0 ? 1 : (w <= 2 ? 2 : 3));
    const int t = threadIdx.x;
    const int col = t & 31, r0 = t >> 5;
    const float* W = wp.p[w];

#pragma unroll
    for (int i = 0; i < 4; ++i) {
        const int row = r0 + i * 8;
        float v;
        if (mode == 0) {
            const int e = eb * 32 + row, f = fb * 32 + col;
            v = W[((size_t)c * EE + e) * EE + f];
        } else if (mode == 1) {
            const int f = fb * 32 + row, e = eb * 32 + col;
            const int h = fb, p = f & 31;
            v = W[(((size_t)h * CC + c) * PP + p) * EE + e];
        } else if (mode == 2) {
            const int e = eb * 32 + row, p = col, h = fb;
            v = W[((size_t)h * EE + e) * PP + p];
        } else {
            const int e = eb * 32 + row, p = col, h = fb;
            v = W[(((size_t)h * CC + c) * EE + e) * PP + p];
        }
        tile[row][col] = v;
    }
    __syncthreads();

#pragma unroll
    for (int i = 0; i < 4; ++i) {
        const int fr = r0 + i * 8;
        const int f = fb * 32 + fr;
        const int e = eb * 32 + col;
        const float v = (mode == 1) ? tile[fr][col] : tile[col][fr];
        __nv_bfloat16 hi, lo;
        split_bf16(v, hi, lo);
        const size_t o = (size_t)w * WELEMS + ((size_t)c << 16) + (size_t)f * EE + e;
        wh[o] = hi;
        wl[o] = lo;
    }
}

// ---------------------------------------------------------------------------
// Fused QKVx6 GEMM. A loaded from fp32 x and split to bf16 hi/lo IN-KERNEL.
// ---------------------------------------------------------------------------
constexpr int AP = 528;
constexpr int QA_HI = 0;
constexpr int QA_LO = 128 * AP;
constexpr int QB0   = 2 * 128 * AP;
constexpr int QB_STG = 20480;
constexpr int QKV_SMEM = QB0 + 3 * QB_STG;

constexpr int GP = 80;

struct Out6 { float* y[6]; };

__global__ __launch_bounds__(256) void gemm_qkv6(
    const float* __restrict__ x,
    const __nv_bfloat16* __restrict__ whB, const __nv_bfloat16* __restrict__ wlB,
    Out6 outs)
{
    extern __shared__ __align__(16) char dsm[];
    const uint32_t sbase = smem_u32(dsm);
    const int tid = threadIdx.x;
    const int wid = tid >> 5, lane = tid & 31;
    const int b = blockIdx.x, nb = blockIdx.y, c = blockIdx.z;

    const size_t abase = ((size_t)b * CC + c) * SS * EE;

    auto issueB = [&](int stage) {
        const int w = stage >> 3, kb = (stage & 7) * 32;
        const int wg = w + (w >= 3);
        const __nv_bfloat16* Wh = whB + (size_t)wg * WELEMS + ((size_t)c << 16)
                                + (size_t)nb * 128 * EE;
        const __nv_bfloat16* Wl = wlB + (size_t)wg * WELEMS + ((size_t)c << 16)
                                + (size_t)nb * 128 * EE;
        const uint32_t sb = sbase + QB0 + (stage % 3) * QB_STG;
#pragma unroll
        for (int j = 0; j < 2; ++j) {
            const int t2 = tid + j * 256;
            const int row = t2 >> 2, ch = t2 & 3;
            const size_t goff = (size_t)row * EE + kb + ch * 8;
            const uint32_t so = row * GP + ch * 16;
            cp_async16(sb + so, Wh + goff);
            cp_async16(sb + 10240 + so, Wl + goff);
        }
    };
    issueB(0); cp_commit();
    issueB(1); cp_commit();
    issueB(2); cp_commit();

    // ---- load A from fp32 x, split to bf16 hi/lo in smem ----
#pragma unroll
    for (int i = 0; i < 16; ++i) {
        const int t2 = tid + i * 256;
        const int row = t2 >> 5, ch = t2 & 31;
        const float* src = x + abase + (size_t)row * EE + ch * 8;
        float4 v0 = *(const float4*)src;
        float4 v1 = *(const float4*)(src + 4);
        float vv[8] = {v0.x, v0.y, v0.z, v0.w, v1.x, v1.y, v1.z, v1.w};
        __nv_bfloat16 h[8], l[8];
#pragma unroll
        for (int j = 0; j < 8; ++j) split_bf16(vv[j], h[j], l[j]);
        uint4 hp, lp;
        ((__nv_bfloat162*)&hp)[0] = __halves2bfloat162(h[0], h[1]);
        ((__nv_bfloat162*)&hp)[1] = __halves2bfloat162(h[2], h[3]);
        ((__nv_bfloat162*)&hp)[2] = __halves2bfloat162(h[4], h[5]);
        ((__nv_bfloat162*)&hp)[3] = __halves2bfloat162(h[6], h[7]);
        ((__nv_bfloat162*)&lp)[0] = __halves2bfloat162(l[0], l[1]);
        ((__nv_bfloat162*)&lp)[1] = __halves2bfloat162(l[2], l[3]);
        ((__nv_bfloat162*)&lp)[2] = __halves2bfloat162(l[4], l[5]);
        ((__nv_bfloat162*)&lp)[3] = __halves2bfloat162(l[6], l[7]);
        const uint32_t so = row * AP + ch * 16;
        *(uint4*)(dsm + QA_HI + so) = hp;
        *(uint4*)(dsm + QA_LO + so) = lp;
    }

    const int wm = wid & 3, wn = wid >> 2;
    const int g = lane >> 3, lr = lane & 7;

    for (int w = 0; w < 6; ++w) {
        float acc[2][8][4];
#pragma unroll
        for (int mi = 0; mi < 2; ++mi)
#pragma unroll
            for (int nj = 0; nj < 8; ++nj)
#pragma unroll
                for (int r = 0; r < 4; ++r) acc[mi][nj][r] = 0.f;

        for (int it = 0; it < 8; ++it) {
            const int stage = w * 8 + it;
            cp_wait<2>();
            __syncthreads();
            const uint32_t Bst = sbase + QB0 + (stage % 3) * QB_STG;

#pragma unroll
            for (int pass = 0; pass < 3; ++pass) {
                const uint32_t Ab = sbase + (pass == 2 ? QA_LO : QA_HI);
                const uint32_t Bb = Bst + (pass == 1 ? 10240 : 0);
#pragma unroll
                for (int k16 = 0; k16 < 2; ++k16) {
                    uint32_t afr[2][4];
#pragma unroll
                    for (int mi = 0; mi < 2; ++mi) {
                        const int row = wm * 32 + mi * 16 + ((g & 1) << 3) + lr;
                        const uint32_t addr =
                            Ab + row * AP + (it * 4 + k16 * 2 + (g >> 1)) * 16;
                        ldsm_x4(afr[mi][0], afr[mi][1], afr[mi][2], afr[mi][3], addr);
                    }
                    uint32_t bfr[4][4];
#pragma unroll
                    for (int ni = 0; ni < 4; ++ni) {
                        const int row = wn * 64 + ni * 16 + ((g >> 1) << 3) + lr;
                        const uint32_t addr = Bb + row * GP + (k16 * 2 + (g & 1)) * 16;
                        ldsm_x4(bfr[ni][0], bfr[ni][1], bfr[ni][2], bfr[ni][3], addr);
                    }
#pragma unroll
                    for (int mi = 0; mi < 2; ++mi)
#pragma unroll
                        for (int nj = 0; nj < 8; ++nj)
                            mma_bf16(acc[mi][nj], afr[mi],
                                     bfr[nj >> 1][(nj & 1) * 2],
                                     bfr[nj >> 1][(nj & 1) * 2 + 1]);
                }
            }
            __syncthreads();
            if (stage + 3 < 48) issueB(stage + 3);
            cp_commit();
        }

        float* Yf = outs.y[w];
#pragma unroll
        for (int mi = 0; mi < 2; ++mi)
#pragma unroll
            for (int rr = 0; rr < 2; ++rr) {
                const int m = wm * 32 + mi * 16 + (lane >> 2) + rr * 8;
                const size_t yrow = abase + (size_t)m * EE + nb * 128;
#pragma unroll
                for (int nj = 0; nj < 8; ++nj) {
                    const int colo = wn * 64 + nj * 8 + (lane & 3) * 2;
                    *(float2*)(Yf + yrow + colo) =
                        make_float2(acc[mi][nj][rr * 2 + 0], acc[mi][nj][rr * 2 + 1]);
                }
            }
    }
}

// ---------------------------------------------------------------------------
// Generic HMMA GEMM body v2: 256(M)x128(N) block (2 b-slices), 64x64 warp tiles.
// ---------------------------------------------------------------------------
constexpr int T_A_HI = 0;
constexpr int T_A_LO = 256 * GP;              // 20480
constexpr int T_B_HI = 2 * 256 * GP;          // 40960
constexpr int T_B_LO = T_B_HI + 128 * GP;     // 51200
constexpr int STAGE  = T_B_LO + 128 * GP;     // 61440
constexpr int GEMM_SMEM = 2 * STAGE;          // 122880

template <int EPI>
__device__ __forceinline__ void gemm_body(
    const __nv_bfloat16* __restrict__ Ah, const __nv_bfloat16* __restrict__ Al,
    const __nv_bfloat16* __restrict__ Wh, const __nv_bfloat16* __restrict__ Wl,
    const float* __restrict__ bias,
    float* __restrict__ Yf,
    __nv_bfloat16* __restrict__ Yh, __nv_bfloat16* __restrict__ Yl,
    int b0, int nb, int c, uint32_t sbase)
{
    const int tid = threadIdx.x;
    const int wid = tid >> 5, lane = tid & 31;

    const size_t abase0 = ((size_t)b0 * CC + c) * SS * EE;
    const size_t bstride = (size_t)CC * SS * EE;
    const size_t wbase = (size_t)c * EE * EE + (size_t)nb * 128 * EE;

    auto issue = [&](int stg) {
        const int kb = stg * 32;
        const uint32_t sb = sbase + (stg & 1) * STAGE;
#pragma unroll
        for (int j = 0; j < 4; ++j) {
            const int t2 = tid + j * 256;
            const int row = t2 >> 2, ch = t2 & 3;
            const int bo = row >> 7, s = row & 127;
            const size_t goff = abase0 + (size_t)bo * bstride + (size_t)s * EE + kb + ch * 8;
            const uint32_t so = row * GP + ch * 16;
            cp_async16(sb + T_A_HI + so, Ah + goff);
            cp_async16(sb + T_A_LO + so, Al + goff);
        }
#pragma unroll
        for (int j = 0; j < 2; ++j) {
            const int t2 = tid + j * 256;
            const int row = t2 >> 2, ch = t2 & 3;
            const size_t goff = wbase + (size_t)row * EE + kb + ch * 8;
            const uint32_t so = row * GP + ch * 16;
            cp_async16(sb + T_B_HI + so, Wh + goff);
            cp_async16(sb + T_B_LO + so, Wl + goff);
        }
    };
    issue(0); cp_commit();
    issue(1); cp_commit();

    const int wm = wid & 3, wn = wid >> 2;
    const int g = lane >> 3, lr = lane & 7;

    float acc[4][8][4];
#pragma unroll
    for (int mi = 0; mi < 4; ++mi)
#pragma unroll
        for (int nj = 0; nj < 8; ++nj)
#pragma unroll
            for (int r = 0; r < 4; ++r) acc[mi][nj][r] = 0.f;

    for (int it = 0; it < 8; ++it) {
        cp_wait<1>();
        __syncthreads();
        const uint32_t st = sbase + (it & 1) * STAGE;

#pragma unroll
        for (int pass = 0; pass < 3; ++pass) {
            const uint32_t Ab = st + (pass == 2 ? T_A_LO : T_A_HI);
            const uint32_t Bb = st + (pass == 1 ? T_B_LO : T_B_HI);
#pragma unroll
            for (int k16 = 0; k16 < 2; ++k16) {
                uint32_t afr[4][4];
#pragma unroll
                for (int mi = 0; mi < 4; ++mi) {
                    const int row = wm * 64 + mi * 16 + ((g & 1) << 3) + lr;
                    const uint32_t addr = Ab + row * GP + (k16 * 2 + (g >> 1)) * 16;
                    ldsm_x4(afr[mi][0], afr[mi][1], afr[mi][2], afr[mi][3], addr);
                }
                uint32_t bfr[4][4];
#pragma unroll
                for (int ni = 0; ni < 4; ++ni) {
                    const int row = wn * 64 + ni * 16 + ((g >> 1) << 3) + lr;
                    const uint32_t addr = Bb + row * GP + (k16 * 2 + (g & 1)) * 16;
                    ldsm_x4(bfr[ni][0], bfr[ni][1], bfr[ni][2], bfr[ni][3], addr);
                }
#pragma unroll
                for (int mi = 0; mi < 4; ++mi)
#pragma unroll
                    for (int nj = 0; nj < 8; ++nj)
                        mma_bf16(acc[mi][nj], afr[mi],
                                 bfr[nj >> 1][(nj & 1) * 2],
                                 bfr[nj >> 1][(nj & 1) * 2 + 1]);
            }
        }
        __syncthreads();
        if (it + 2 < 8) issue(it + 2);
        cp_commit();
    }

#pragma unroll
    for (int mi = 0; mi < 4; ++mi) {
#pragma unroll
        for (int rr = 0; rr < 2; ++rr) {
            const int m = wm * 64 + mi * 16 + (lane >> 2) + rr * 8;
            const int bo = m >> 7, s = m & 127;
            const size_t yrow = abase0 + (size_t)bo * bstride + (size_t)s * EE + nb * 128;
#pragma unroll
            for (int nj = 0; nj < 8; ++nj) {
                const int col = wn * 64 + nj * 8 + (lane & 3) * 2;
                float v0 = acc[mi][nj][rr * 2 + 0];
                float v1 = acc[mi][nj][rr * 2 + 1];
                if constexpr (EPI == 0) {
                    *(float2*)(Yf + yrow + col) = make_float2(v0, v1);
                } else {
                    const float* bp = bias + (size_t)c * EE + nb * 128 + col;
                    v0 += bp[0];
                    v1 += bp[1];
                    if constexpr (EPI == 1) {
                        v0 = fmaxf(v0, 0.f);
                        v1 = fmaxf(v1, 0.f);
                        __nv_bfloat16 h0, l0, h1, l1;
                        split_bf16(v0, h0, l0);
                        split_bf16(v1, h1, l1);
                        *(__nv_bfloat162*)(Yh + yrow + col) = __halves2bfloat162(h0, h1);
                        *(__nv_bfloat162*)(Yl + yrow + col) = __halves2bfloat162(l0, l1);
                    } else {
                        *(float2*)(Yf + yrow + col) = make_float2(v0, v1);
                    }
                }
            }
        }
    }
}

template <int EPI>
__global__ __launch_bounds__(256) void gemm_mma(
    const __nv_bfloat16* __restrict__ Ah, const __nv_bfloat16* __restrict__ Al,
    const __nv_bfloat16* __restrict__ Wh, const __nv_bfloat16* __restrict__ Wl,
    const float* __restrict__ bias,
    float* __restrict__ Yf,
    __nv_bfloat16* __restrict__ Yh, __nv_bfloat16* __restrict__ Yl)
{
    extern __shared__ __align__(16) char dsm[];
    gemm_body<EPI>(Ah, Al, Wh, Wl, bias, Yf, Yh, Yl,
                   blockIdx.x * 2, blockIdx.y, blockIdx.z, smem_u32(dsm));
}

__global__ __launch_bounds__(256) void gemm_wo_pair(
    const __nv_bfloat16* __restrict__ Ah0, const __nv_bfloat16* __restrict__ Al0,
    const __nv_bfloat16* __restrict__ Wh0, const __nv_bfloat16* __restrict__ Wl0,
    float* __restrict__ Y0,
    const __nv_bfloat16* __restrict__ Ah1, const __nv_bfloat16* __restrict__ Al1,
    const __nv_bfloat16* __restrict__ Wh1, const __nv_bfloat16* __restrict__ Wl1,
    float* __restrict__ Y1)
{
    extern __shared__ __align__(16) char dsm[];
    const int zz = blockIdx.z;
    const int br = zz >= CC;
    const int c = br ? zz - CC : zz;
    gemm_body<0>(br ? Ah1 : Ah0, br ? Al1 : Al0,
                 br ? Wh1 : Wh0, br ? Wl1 : Wl0,
                 nullptr, br ? Y1 : Y0, nullptr, nullptr,
                 blockIdx.x * 2, blockIdx.y, c, smem_u32(dsm));
}

// ---------------------------------------------------------------------------
// Spatial attention (R9 winner): one block per (b,s), 8 heads, 768 thr, 2 CTA/SM.
// ---------------------------------------------------------------------------
constexpr int SA_P = 260;
constexpr int SA_SMEM = (3 * CC * SA_P + HH * CC * 25) * 4;  // 94,080 B

__global__ __launch_bounds__(768, 2) void spatial_attn(
    const float* __restrict__ q, const float* __restrict__ k,
    const float* __restrict__ v, __nv_bfloat16* __restrict__ oh,
    __nv_bfloat16* __restrict__ ol)
{
    extern __shared__ float sa[];
    float* qs = sa;
    float* ks = qs + CC * SA_P;
    float* vs = ks + CC * SA_P;
    float* sc = vs + CC * SA_P;

    const int s = blockIdx.x, b = blockIdx.y;
    const int t = threadIdx.x;
    const size_t gbase = ((size_t)b * CC * SS + s) * EE;
    const size_t cstride = (size_t)SS * EE;

#pragma unroll
    for (int i = 0; i < 2; ++i) {
        const int idx = t + i * 768;
        const int row = idx >> 6, e4 = idx & 63;
        const size_t g = gbase + row * cstride + e4 * 4;
        const int so = row * SA_P + e4 * 4;
        *(float4*)(qs + so) = *(const float4*)(q + g);
        *(float4*)(ks + so) = *(const float4*)(k + g);
        *(float4*)(vs + so) = *(const float4*)(v + g);
    }
    __syncthreads();

    {
        const int h = t / 96;
        const int r = t - h * 96;
        const int cig = r >> 3, dig = r & 7;
        const int ci0 = cig * 2, di0 = dig * 3;
        const float* qb = qs + ci0 * SA_P + h * 32;
        const float* kb = ks + di0 * SA_P + h * 32;
        float a00 = 0.f, a01 = 0.f, a02 = 0.f;
        float a10 = 0.f, a11 = 0.f, a12 = 0.f;
#pragma unroll
        for (int p = 0; p < 32; ++p) {
            const float q0 = qb[p], q1 = qb[SA_P + p];
            const float k0 = kb[p], k1 = kb[SA_P + p], k2 = kb[2 * SA_P + p];
            a00 = fmaf(q0, k0, a00); a01 = fmaf(q0, k1, a01); a02 = fmaf(q0, k2, a02);
            a10 = fmaf(q1, k0, a10); a11 = fmaf(q1, k1, a11); a12 = fmaf(q1, k2, a12);
        }
        float* sr0 = sc + (h * CC + ci0) * 25 + di0;
        float* sr1 = sr0 + 25;
        sr0[0] = a00 * INV_SQRT_P; sr0[1] = a01 * INV_SQRT_P; sr0[2] = a02 * INV_SQRT_P;
        sr1[0] = a10 * INV_SQRT_P; sr1[1] = a11 * INV_SQRT_P; sr1[2] = a12 * INV_SQRT_P;
    }
    __syncthreads();

    if (t < HH * CC) {
        float* row = sc + t * 25;
        float mx = -1e30f;
#pragma unroll
        for (int d = 0; d < CC; ++d) mx = fmaxf(mx, row[d]);
        float sm = 0.f;
#pragma unroll
        for (int d = 0; d < CC; ++d) { float e = __expf(row[d] - mx); row[d] = e; sm += e; }
        const float inv = 1.f / sm;
#pragma unroll
        for (int d = 0; d < CC; ++d) row[d] *= inv;
    }
    __syncthreads();

#pragma unroll
    for (int i = 0; i < 2; ++i) {
        const int item = t + i * 768;
        const int h = item / 192;
        const int rr = item - h * 192;
        const int cc = rr >> 3, p4 = (rr & 7) * 4;
        const float* arow = sc + (h * CC + cc) * 25;
        const float* vb = vs + h * 32 + p4;
        float s0 = 0.f, s1 = 0.f, s2 = 0.f, s3 = 0.f;
#pragma unroll
        for (int d = 0; d < CC; ++d) {
            const float a = arow[d];
            const float4 vv = *(const float4*)(vb + d * SA_P);
            s0 = fmaf(a, vv.x, s0); s1 = fmaf(a, vv.y, s1);
            s2 = fmaf(a, vv.z, s2); s3 = fmaf(a, vv.w, s3);
        }
        const size_t g = gbase + cc * cstride + h * 32 + p4;
        __nv_bfloat16 h0, l0, h1, l1, h2, l2, h3, l3;
        split_bf16(s0, h0, l0); split_bf16(s1, h1, l1);
        split_bf16(s2, h2, l2); split_bf16(s3, h3, l3);
        *(__nv_bfloat162*)(oh + g)     = __halves2bfloat162(h0, h1);
        *(__nv_bfloat162*)(oh + g + 2) = __halves2bfloat162(h2, h3);
        *(__nv_bfloat162*)(ol + g)     = __halves2bfloat162(l0, l1);
        *(__nv_bfloat162*)(ol + g + 2) = __halves2bfloat162(l2, l3);
    }
}

// ---------------------------------------------------------------------------
// Temporal attention v2: split into TWO s-halves per (b,h,c).
// Block = 64 query rows x full 128 keys; smem 77 KB -> 2 CTAs/SM.
// grid (CC, HH, BB*2), 256 threads.
// ---------------------------------------------------------------------------
constexpr int TQ_P = 68;    // qt pitch  (64 s rows stored transposed [32][68])
constexpr int TK_P = 132;   // kt pitch  ([32][132])
constexpr int TV_P = 36;    // vs pitch  ([128][36])
constexpr int TS_P = 130;   // sc pitch  ([64][130])
constexpr int TEMP_SMEM_BYTES =
    (32 * TQ_P + 32 * TK_P + SS * TV_P + 64 * TS_P) * 4;   // 77,312 B

__global__ __launch_bounds__(256) void temporal_attn(
    const float* __restrict__ q, const float* __restrict__ k,
    const float* __restrict__ v, __nv_bfloat16* __restrict__ oh,
    __nv_bfloat16* __restrict__ ol)
{
    extern __shared__ float smem[];
    float* qt = smem;                  // [32][TQ_P]  qt[p][s_local]
    float* kt = qt + 32 * TQ_P;        // [32][TK_P]  kt[p][t]
    float* vs = kt + 32 * TK_P;        // [128][TV_P] vs[t][p]
    float* sc = vs + SS * TV_P;        // [64][TS_P]  sc[s_local][t]

    const int c = blockIdx.x, h = blockIdx.y;
    const int b = blockIdx.z >> 1, sh = blockIdx.z & 1;
    const int tid = threadIdx.x;
    const int s_base = sh * 64;
    const size_t base = (((size_t)b * CC + c) * SS) * EE + h * PP;

    // ---- loads ----
    // q: 64 rows x 32 p (8 elems/thread)
#pragma unroll
    for (int i = 0; i < 8; ++i) {
        const int idx = tid + i * 256;          // 0..2047
        const int s = idx >> 5, p = idx & 31;
        qt[p * TQ_P + s] = q[base + (size_t)(s_base + s) * EE + p];
    }
    // k, v: 128 rows x 32 p (16 elems/thread each)
#pragma unroll
    for (int i = 0; i < 16; ++i) {
        const int idx = tid + i * 256;          // 0..4095
        const int t = idx >> 5, p = idx & 31;
        const size_t g = base + (size_t)t * EE + p;
        kt[p * TK_P + t] = k[g];
        vs[t * TV_P + p] = v[g];
    }
    __syncthreads();

    // ---- scores: 64(s) x 128(t); thread = 4s x 8t via f32x2 ----
    {
        const int ty = tid >> 4;                // 0..15 -> s rows ty*4..+3
        const int tx = tid & 15;                // 0..15 -> t cols tx*8..+7
        unsigned long long acc2[4][4];
#pragma unroll
        for (int i = 0; i < 4; ++i)
#pragma unroll
            for (int j = 0; j < 4; ++j) acc2[i][j] = 0ull;

#pragma unroll 4
        for (int p = 0; p < PP; ++p) {
            float4 aq = *(const float4*)&qt[p * TQ_P + ty * 4];
            float ar[4] = {aq.x, aq.y, aq.z, aq.w};
            ulonglong2 b01 = *(const ulonglong2*)&kt[p * TK_P + tx * 8];
            ulonglong2 b23 = *(const ulonglong2*)&kt[p * TK_P + tx * 8 + 4];
            unsigned long long bb[4] = {b01.x, b01.y, b23.x, b23.y};
#pragma unroll
            for (int i = 0; i < 4; ++i) {
                const unsigned long long ap = pack2(ar[i]);
#pragma unroll
                for (int j = 0; j < 4; ++j) fma2(acc2[i][j], ap, bb[j]);
            }
        }
#pragma unroll
        for (int i = 0; i < 4; ++i)
#pragma unroll
            for (int j = 0; j < 4; ++j) {
                float2 u = unpack2(acc2[i][j]);
                *(float2*)&sc[(ty * 4 + i) * TS_P + tx * 8 + j * 2] =
                    make_float2(u.x * INV_SQRT_P, u.y * INV_SQRT_P);
            }
    }
    __syncthreads();

    // ---- softmax: 4 threads per row, strided access, shuffle reduce ----
    {
        const int row = tid >> 2, q4 = tid & 3;
        float* r = sc + row * TS_P;
        float mx = -1e30f;
#pragma unroll 8
        for (int t2 = 0; t2 < 32; ++t2) mx = fmaxf(mx, r[q4 + t2 * 4]);
        mx = fmaxf(mx, __shfl_xor_sync(0xffffffffu, mx, 1));
        mx = fmaxf(mx, __shfl_xor_sync(0xffffffffu, mx, 2));
        float ssum = 0.f;
#pragma unroll 8
        for (int t2 = 0; t2 < 32; ++t2) {
            float e = __expf(r[q4 + t2 * 4] - mx);
            r[q4 + t2 * 4] = e;
            ssum += e;
        }
        ssum += __shfl_xor_sync(0xffffffffu, ssum, 1);
        ssum += __shfl_xor_sync(0xffffffffu, ssum, 2);
        const float inv = 1.f / ssum;
#pragma unroll 8
        for (int t2 = 0; t2 < 32; ++t2) r[q4 + t2 * 4] *= inv;
    }
    __syncthreads();

    // ---- AV: 64(s) x 32(p); thread = 2s x 4p via f32x2 ----
    {
        const int s0 = (tid >> 3) * 2;          // 0..62
        const int p0 = (tid & 7) * 4;
        unsigned long long acc2[2][2];
        acc2[0][0] = acc2[0][1] = acc2[1][0] = acc2[1][1] = 0ull;

#pragma unroll 4
        for (int t2 = 0; t2 < SS; ++t2) {
            ulonglong2 vv = *(const ulonglong2*)&vs[t2 * TV_P + p0];
#pragma unroll
            for (int i = 0; i < 2; ++i) {
                const unsigned long long ap = pack2(sc[(s0 + i) * TS_P + t2]);
                fma2(acc2[i][0], ap, vv.x);
                fma2(acc2[i][1], ap, vv.y);
            }
        }
#pragma unroll
        for (int i = 0; i < 2; ++i) {
            float2 u0 = unpack2(acc2[i][0]);
            float2 u1 = unpack2(acc2[i][1]);
            float vv[4] = {u0.x, u0.y, u1.x, u1.y};
            const size_t g = base + (size_t)(s_base + s0 + i) * EE + p0;
            __nv_bfloat16 hh[4], ll[4];
#pragma unroll
            for (int j = 0; j < 4; ++j) split_bf16(vv[j], hh[j], ll[j]);
            *(__nv_bfloat162*)(oh + g)     = __halves2bfloat162(hh[0], hh[1]);
            *(__nv_bfloat162*)(oh + g + 2) = __halves2bfloat162(hh[2], hh[3]);
            *(__nv_bfloat162*)(ol + g)     = __halves2bfloat162(ll[0], ll[1]);
            *(__nv_bfloat162*)(ol + g + 2) = __halves2bfloat162(ll[2], ll[3]);
        }
    }
}

// ---------------------------------------------------------------------------
// LayerNorm kernels — warp-per-row.
// ---------------------------------------------------------------------------
__device__ __forceinline__ float warp_sum(float v) {
#pragma unroll
    for (int off = 16; off > 0; off >>= 1)
        v += __shfl_xor_sync(0xffffffffu, v, off);
    return v;
}

__global__ __launch_bounds__(256) void dual_ln(
    const float* __restrict__ x, const float* __restrict__ a,
    const float* __restrict__ b2, const float* __restrict__ g,
    const float* __restrict__ beta, float* __restrict__ out,
    __nv_bfloat16* __restrict__ oh, __nv_bfloat16* __restrict__ ol)
{
    const int warp = threadIdx.x >> 5, lane = threadIdx.x & 31;
    const int row = blockIdx.x * 8 + warp;
    const size_t base = (size_t)row * EE;
    const int e0 = lane * 4, e1 = 128 + lane * 4;

    float4 x0 = *(const float4*)(x + base + e0);
    float4 x1 = *(const float4*)(x + base + e1);
    float4 a0 = *(const float4*)(a + base + e0);
    float4 a1 = *(const float4*)(a + base + e1);
    float4 b0 = *(const float4*)(b2 + base + e0);
    float4 b1 = *(const float4*)(b2 + base + e1);

    float v1[8] = {x0.x + a0.x, x0.y + a0.y, x0.z + a0.z, x0.w + a0.w,
                   x1.x + a1.x, x1.y + a1.y, x1.z + a1.z, x1.w + a1.w};
    float v2[8] = {x0.x + b0.x, x0.y + b0.y, x0.z + b0.z, x0.w + b0.w,
                   x1.x + b1.x, x1.y + b1.y, x1.z + b1.z, x1.w + b1.w};

    float s1 = 0.f, q1 = 0.f, s2 = 0.f, q2 = 0.f;
#pragma unroll
    for (int j = 0; j < 8; ++j) {
        s1 += v1[j]; q1 = fmaf(v1[j], v1[j], q1);
        s2 += v2[j]; q2 = fmaf(v2[j], v2[j], q2);
    }
    s1 = warp_sum(s1); q1 = warp_sum(q1);
    s2 = warp_sum(s2); q2 = warp_sum(q2);

    const float invE = 1.f / (float)EE;
    const float m1 = s1 * invE, m2 = s2 * invE;
    const float r1 = rsqrtf(fmaxf(q1 * invE - m1 * m1, 0.f) + LN_EPS);
    const float r2 = rsqrtf(fmaxf(q2 * invE - m2 * m2, 0.f) + LN_EPS);

    float4 g0 = *(const float4*)(g + e0);
    float4 g1 = *(const float4*)(g + e1);
    float4 t0 = *(const float4*)(beta + e0);
    float4 t1 = *(const float4*)(beta + e1);
    float gg[8] = {g0.x, g0.y, g0.z, g0.w, g1.x, g1.y, g1.z, g1.w};
    float bt[8] = {t0.x, t0.y, t0.z, t0.w, t1.x, t1.y, t1.z, t1.w};

    float o[8];
#pragma unroll
    for (int j = 0; j < 8; ++j)
        o[j] = (v1[j] - m1) * r1 * gg[j] + bt[j]
             + (v2[j] - m2) * r2 * gg[j] + bt[j];

    *(float4*)(out + base + e0) = make_float4(o[0], o[1], o[2], o[3]);
    *(float4*)(out + base + e1) = make_float4(o[4], o[5], o[6], o[7]);

    __nv_bfloat16 hh[8], ll[8];
#pragma unroll
    for (int j = 0; j < 8; ++j) split_bf16(o[j], hh[j], ll[j]);
    *(__nv_bfloat162*)(oh + base + e0)     = __halves2bfloat162(hh[0], hh[1]);
    *(__nv_bfloat162*)(oh + base + e0 + 2) = __halves2bfloat162(hh[2], hh[3]);
    *(__nv_bfloat162*)(oh + base + e1)     = __halves2bfloat162(hh[4], hh[5]);
    *(__nv_bfloat162*)(oh + base + e1 + 2) = __halves2bfloat162(hh[6], hh[7]);
    *(__nv_bfloat162*)(ol + base + e0)     = __halves2bfloat162(ll[0], ll[1]);
    *(__nv_bfloat162*)(ol + base + e0 + 2) = __halves2bfloat162(ll[2], ll[3]);
    *(__nv_bfloat162*)(ol + base + e1)     = __halves2bfloat162(ll[4], ll[5]);
    *(__nv_bfloat162*)(ol + base + e1 + 2) = __halves2bfloat162(ll[6], ll[7]);
}

__global__ __launch_bounds__(256) void final_ln(
    const float* __restrict__ a, const float* __restrict__ f,
    const float* __restrict__ g, const float* __restrict__ beta,
    float* __restrict__ out)
{
    const int warp = threadIdx.x >> 5, lane = threadIdx.x & 31;
    const int row = blockIdx.x * 8 + warp;
    const size_t base = (size_t)row * EE;
    const int e0 = lane * 4, e1 = 128 + lane * 4;

    float4 a0 = *(const float4*)(a + base + e0);
    float4 a1 = *(const float4*)(a + base + e1);
    float4 f0 = *(const float4*)(f + base + e0);
    float4 f1 = *(const float4*)(f + base + e1);

    float v[8] = {a0.x + f0.x, a0.y + f0.y, a0.z + f0.z, a0.w + f0.w,
                  a1.x + f1.x, a1.y + f1.y, a1.z + f1.z, a1.w + f1.w};

    float s = 0.f, q = 0.f;
#pragma unroll
    for (int j = 0; j < 8; ++j) { s += v[j]; q = fmaf(v[j], v[j], q); }
    s = warp_sum(s); q = warp_sum(q);

    const float invE = 1.f / (float)EE;
    const float m = s * invE;
    const float r = rsqrtf(fmaxf(q * invE - m * m, 0.f) + LN_EPS);

    float4 g0 = *(const float4*)(g + e0);
    float4 g1 = *(const float4*)(g + e1);
    float4 t0 = *(const float4*)(beta + e0);
    float4 t1 = *(const float4*)(beta + e1);
    float gg[8] = {g0.x, g0.y, g0.z, g0.w, g1.x, g1.y, g1.z, g1.w};
    float bt[8] = {t0.x, t0.y, t0.z, t0.w, t1.x, t1.y, t1.z, t1.w};

    float o[8];
#pragma unroll
    for (int j = 0; j < 8; ++j) o[j] = (v[j] - m) * r * gg[j] + bt[j];
    *(float4*)(out + base + e0) = make_float4(o[0], o[1], o[2], o[3]);
    *(float4*)(out + base + e1) = make_float4(o[4], o[5], o[6], o[7]);
}

// ---------------------------------------------------------------------------
// kernel_launch
// ---------------------------------------------------------------------------
extern "C" void kernel_launch(void* const* d_in, const int* in_sizes, int n_in,
                              void* d_out, int out_size)
{
    const float* x    = (const float*)d_in[0];
    const float* ln_g = (const float*)d_in[9];
    const float* ln_b = (const float*)d_in[10];
    const float* ff_b1 = (const float*)d_in[12];
    const float* ff_b2 = (const float*)d_in[14];
    float* out = (float*)d_out;

    float *qs, *ks, *vs, *qt, *kt, *vt, *spat, *temp, *attn, *ffo;
    __nv_bfloat16 *ah, *al, *hh, *hl, *wh, *wl;
    cudaGetSymbolAddress((void**)&qs,   g_qs);
    cudaGetSymbolAddress((void**)&ks,   g_ks);
    cudaGetSymbolAddress((void**)&vs,   g_vs);
    cudaGetSymbolAddress((void**)&qt,   g_qt);
    cudaGetSymbolAddress((void**)&kt,   g_kt);
    cudaGetSymbolAddress((void**)&vt,   g_vt);
    cudaGetSymbolAddress((void**)&spat, g_spat);
    cudaGetSymbolAddress((void**)&temp, g_temp);
    cudaGetSymbolAddress((void**)&attn, g_attn);
    cudaGetSymbolAddress((void**)&ffo,  g_ffo);
    cudaGetSymbolAddress((void**)&ah, g_ah);
    cudaGetSymbolAddress((void**)&al, g_al);
    cudaGetSymbolAddress((void**)&hh, g_hh);
    cudaGetSymbolAddress((void**)&hl, g_hl);
    cudaGetSymbolAddress((void**)&wh, g_wh);
    cudaGetSymbolAddress((void**)&wl, g_wl);

    cudaFuncSetAttribute(gemm_qkv6,   cudaFuncAttributeMaxDynamicSharedMemorySize, QKV_SMEM);
    cudaFuncSetAttribute(gemm_mma<1>, cudaFuncAttributeMaxDynamicSharedMemorySize, GEMM_SMEM);
    cudaFuncSetAttribute(gemm_mma<2>, cudaFuncAttributeMaxDynamicSharedMemorySize, GEMM_SMEM);
    cudaFuncSetAttribute(gemm_wo_pair, cudaFuncAttributeMaxDynamicSharedMemorySize, GEMM_SMEM);
    cudaFuncSetAttribute(spatial_attn, cudaFuncAttributeMaxDynamicSharedMemorySize, SA_SMEM);
    cudaFuncSetAttribute(temporal_attn, cudaFuncAttributeMaxDynamicSharedMemorySize, TEMP_SMEM_BYTES);

    // ---- weight conversion ----
    WPtrs wp;
    wp.p[0] = (const float*)d_in[1];
    wp.p[1] = (const float*)d_in[2];
    wp.p[2] = (const float*)d_in[3];
    wp.p[3] = (const float*)d_in[4];
    wp.p[4] = (const float*)d_in[5];
    wp.p[5] = (const float*)d_in[6];
    wp.p[6] = (const float*)d_in[7];
    wp.p[7] = (const float*)d_in[8];
    wp.p[8] = (const float*)d_in[11];
    wp.p[9] = (const float*)d_in[13];
    convert_weights_t<<<dim3(64, CC, NW), 256>>>(wp, wh, wl);

    // ---- fused q/k/v projections (x split in-kernel) ----
    Out6 o6;
    o6.y[0] = qs; o6.y[1] = ks; o6.y[2] = vs;
    o6.y[3] = qt; o6.y[4] = kt; o6.y[5] = vt;
    gemm_qkv6<<<dim3(BB, 2, CC), 256, QKV_SMEM>>>(x, wh, wl, o6);

    // ---- attentions ----
    spatial_attn<<<dim3(SS, BB), 768, SA_SMEM>>>(qs, ks, vs, ah, al);
    temporal_attn<<<dim3(CC, HH, BB * 2), 256, TEMP_SMEM_BYTES>>>(qt, kt, vt, hh, hl);

    // ---- output projections (merged dual launch, M=256 blocks) ----
    gemm_wo_pair<<<dim3(BB / 2, 2, 2 * CC), 256, GEMM_SMEM>>>(
        ah, al, wh + 3*(size_t)WELEMS, wl + 3*(size_t)WELEMS, spat,
        hh, hl, wh + 7*(size_t)WELEMS, wl + 7*(size_t)WELEMS, temp);

    // ---- residual + dual LN (emits attn fp32 + bf16 pair) ----
    dual_ln<<<NROWS / 8, 256>>>(x, spat, temp, ln_g, ln_b, attn, ah, al);

    // ---- per-joint FF + final LN ----
    gemm_mma<1><<<dim3(BB / 2, 2, CC), 256, GEMM_SMEM>>>(ah, al, wh + 8*(size_t)WELEMS, wl + 8*(size_t)WELEMS, ff_b1, nullptr, hh, hl);
    gemm_mma<2><<<dim3(BB / 2, 2, CC), 256, GEMM_SMEM>>>(hh, hl, wh + 9*(size_t)WELEMS, wl + 9*(size_t)WELEMS, ff_b2, ffo, nullptr, nullptr);
    final_ln<<<NROWS / 8, 256>>>(attn, ffo, ln_g, ln_b, out);
}

// round 12
// speedup vs baseline: 1.9213x; 1.1666x over previous
#include <cuda_runtime.h>
#include <cuda_bf16.h>
#include <cstdint>
#include <cstddef>

// Problem dims
constexpr int BB = 16, CC = 24, SS = 128, EE = 256, HH = 8, PP = 32;
constexpr int NTOT  = BB * CC * SS * EE;     // 12,582,912
constexpr int NROWS = BB * CC * SS;          // 49,152
constexpr int WELEMS = CC * EE * EE;         // 1,572,864 per weight
constexpr int NW = 10;
constexpr float LN_EPS = 1e-6f;
constexpr float INV_SQRT_P = 0.17677669529663687f;

// ---------------------------------------------------------------------------
// Device scratch
// ---------------------------------------------------------------------------
__device__ float g_qs[NTOT], g_ks[NTOT], g_vs[NTOT];
__device__ float g_qt[NTOT], g_kt[NTOT], g_vt[NTOT];
__device__ float g_spat[NTOT], g_temp[NTOT], g_attn[NTOT], g_ffo[NTOT];
__device__ __align__(16) __nv_bfloat16 g_ah[NTOT], g_al[NTOT];   // spatial-out / attn pair
__device__ __align__(16) __nv_bfloat16 g_hh[NTOT], g_hl[NTOT];   // temporal-out / ff hidden pair
__device__ __align__(16) __nv_bfloat16 g_wh[NW * WELEMS], g_wl[NW * WELEMS];

// ---------------------------------------------------------------------------
// PTX helpers (baseline ISA only)
// ---------------------------------------------------------------------------
__device__ __forceinline__ uint32_t smem_u32(const void* p) {
    uint32_t a;
    asm("{ .reg .u64 t; cvta.to.shared.u64 t, %1; cvt.u32.u64 %0, t; }"
        : "=r"(a) : "l"(p));
    return a;
}
__device__ __forceinline__ void cp_async16(uint32_t smem, const void* gmem) {
    asm volatile("cp.async.cg.shared.global [%0], [%1], 16;"
                 :: "r"(smem), "l"(gmem));
}
__device__ __forceinline__ void cp_commit() {
    asm volatile("cp.async.commit_group;");
}
template <int N>
__device__ __forceinline__ void cp_wait() {
    asm volatile("cp.async.wait_group %0;" :: "n"(N) : "memory");
}
__device__ __forceinline__ void ldsm_x4(uint32_t& r0, uint32_t& r1,
                                        uint32_t& r2, uint32_t& r3, uint32_t addr) {
    asm volatile("ldmatrix.sync.aligned.m8n8.x4.shared.b16 {%0,%1,%2,%3}, [%4];"
                 : "=r"(r0), "=r"(r1), "=r"(r2), "=r"(r3) : "r"(addr));
}
__device__ __forceinline__ void mma_bf16(float* d, const uint32_t* a,
                                         uint32_t b0, uint32_t b1) {
    asm volatile(
        "mma.sync.aligned.m16n8k16.row.col.f32.bf16.bf16.f32 "
        "{%0,%1,%2,%3}, {%4,%5,%6,%7}, {%8,%9}, {%0,%1,%2,%3};"
        : "+f"(d[0]), "+f"(d[1]), "+f"(d[2]), "+f"(d[3])
        : "r"(a[0]), "r"(a[1]), "r"(a[2]), "r"(a[3]), "r"(b0), "r"(b1));
}
// packed f32x2
__device__ __forceinline__ unsigned long long pack2(float v) {
    unsigned long long r;
    asm("mov.b64 %0, {%1, %1};" : "=l"(r) : "f"(v));
    return r;
}
__device__ __forceinline__ void fma2(unsigned long long& d,
                                     unsigned long long a, unsigned long long b) {
    asm("fma.rn.f32x2 %0, %1, %2, %0;" : "+l"(d) : "l"(a), "l"(b));
}
__device__ __forceinline__ float2 unpack2(unsigned long long v) {
    float2 f;
    asm("mov.b64 {%0, %1}, %2;" : "=f"(f.x), "=f"(f.y) : "l"(v));
    return f;
}

// ---------------------------------------------------------------------------
// bf16 hi/lo split helpers
// ---------------------------------------------------------------------------
__device__ __forceinline__ void split_bf16(float x, __nv_bfloat16& h, __nv_bfloat16& l) {
    h = __float2bfloat16_rn(x);
    l = __float2bfloat16_rn(x - __bfloat162float(h));
}
__device__ __forceinline__ uint32_t pack_bf16x2(float a, float b) {
    __nv_bfloat162 t = __halves2bfloat162(__float2bfloat16_rn(a), __float2bfloat16_rn(b));
    return *(uint32_t*)&t;
}
__device__ __forceinline__ float bf16_lo_res(float x) {
    return x - __bfloat162float(__float2bfloat16_rn(x));
}

// ---------------------------------------------------------------------------
// Weight conversion, coalesced: 32x32 (e,f) tiles via smem transpose.
// ---------------------------------------------------------------------------
struct WPtrs { const float* p[NW]; };

__global__ __launch_bounds__(256) void convert_weights_t(
    WPtrs wp, __nv_bfloat16* __restrict__ wh, __nv_bfloat16* __restrict__ wl)
{
    __shared__ float tile[32][33];
    const int w = blockIdx.z, c = blockIdx.y;
    const int eb = blockIdx.x & 7, fb = blockIdx.x >> 3;
    const int mode = (w == 3 || w >= 7) ? 0 : (w == 0 ? 1 : (w <= 2 ? 2 : 3));
    const int t = threadIdx.x;
    const int col = t & 31, r0 = t >> 5;
    const float* W = wp.p[w];

#pragma unroll
    for (int i = 0; i < 4; ++i) {
        const int row = r0 + i * 8;
        float v;
        if (mode == 0) {
            const int e = eb * 32 + row, f = fb * 32 + col;
            v = W[((size_t)c * EE + e) * EE + f];
        } else if (mode == 1) {
            const int f = fb * 32 + row, e = eb * 32 + col;
            const int h = fb, p = f & 31;
            v = W[(((size_t)h * CC + c) * PP + p) * EE + e];
        } else if (mode == 2) {
            const int e = eb * 32 + row, p = col, h = fb;
            v = W[((size_t)h * EE + e) * PP + p];
        } else {
            const int e = eb * 32 + row, p = col, h = fb;
            v = W[(((size_t)h * CC + c) * EE + e) * PP + p];
        }
        tile[row][col] = v;
    }
    __syncthreads();

#pragma unroll
    for (int i = 0; i < 4; ++i) {
        const int fr = r0 + i * 8;
        const int f = fb * 32 + fr;
        const int e = eb * 32 + col;
        const float v = (mode == 1) ? tile[fr][col] : tile[col][fr];
        __nv_bfloat16 hi, lo;
        split_bf16(v, hi, lo);
        const size_t o = (size_t)w * WELEMS + ((size_t)c << 16) + (size_t)f * EE + e;
        wh[o] = hi;
        wl[o] = lo;
    }
}

// ---------------------------------------------------------------------------
// Fused QKVx6 GEMM. A loaded from fp32 x and split to bf16 hi/lo IN-KERNEL.
// ---------------------------------------------------------------------------
constexpr int AP = 528;
constexpr int QA_HI = 0;
constexpr int QA_LO = 128 * AP;
constexpr int QB0   = 2 * 128 * AP;
constexpr int QB_STG = 20480;
constexpr int QKV_SMEM = QB0 + 3 * QB_STG;

constexpr int GP = 80;

struct Out6 { float* y[6]; };

__global__ __launch_bounds__(256) void gemm_qkv6(
    const float* __restrict__ x,
    const __nv_bfloat16* __restrict__ whB, const __nv_bfloat16* __restrict__ wlB,
    Out6 outs)
{
    extern __shared__ __align__(16) char dsm[];
    const uint32_t sbase = smem_u32(dsm);
    const int tid = threadIdx.x;
    const int wid = tid >> 5, lane = tid & 31;
    const int b = blockIdx.x, nb = blockIdx.y, c = blockIdx.z;

    const size_t abase = ((size_t)b * CC + c) * SS * EE;

    auto issueB = [&](int stage) {
        const int w = stage >> 3, kb = (stage & 7) * 32;
        const int wg = w + (w >= 3);
        const __nv_bfloat16* Wh = whB + (size_t)wg * WELEMS + ((size_t)c << 16)
                                + (size_t)nb * 128 * EE;
        const __nv_bfloat16* Wl = wlB + (size_t)wg * WELEMS + ((size_t)c << 16)
                                + (size_t)nb * 128 * EE;
        const uint32_t sb = sbase + QB0 + (stage % 3) * QB_STG;
#pragma unroll
        for (int j = 0; j < 2; ++j) {
            const int t2 = tid + j * 256;
            const int row = t2 >> 2, ch = t2 & 3;
            const size_t goff = (size_t)row * EE + kb + ch * 8;
            const uint32_t so = row * GP + ch * 16;
            cp_async16(sb + so, Wh + goff);
            cp_async16(sb + 10240 + so, Wl + goff);
        }
    };
    issueB(0); cp_commit();
    issueB(1); cp_commit();
    issueB(2); cp_commit();

    // ---- load A from fp32 x, split to bf16 hi/lo in smem ----
#pragma unroll
    for (int i = 0; i < 16; ++i) {
        const int t2 = tid + i * 256;
        const int row = t2 >> 5, ch = t2 & 31;
        const float* src = x + abase + (size_t)row * EE + ch * 8;
        float4 v0 = *(const float4*)src;
        float4 v1 = *(const float4*)(src + 4);
        float vv[8] = {v0.x, v0.y, v0.z, v0.w, v1.x, v1.y, v1.z, v1.w};
        __nv_bfloat16 h[8], l[8];
#pragma unroll
        for (int j = 0; j < 8; ++j) split_bf16(vv[j], h[j], l[j]);
        uint4 hp, lp;
        ((__nv_bfloat162*)&hp)[0] = __halves2bfloat162(h[0], h[1]);
        ((__nv_bfloat162*)&hp)[1] = __halves2bfloat162(h[2], h[3]);
        ((__nv_bfloat162*)&hp)[2] = __halves2bfloat162(h[4], h[5]);
        ((__nv_bfloat162*)&hp)[3] = __halves2bfloat162(h[6], h[7]);
        ((__nv_bfloat162*)&lp)[0] = __halves2bfloat162(l[0], l[1]);
        ((__nv_bfloat162*)&lp)[1] = __halves2bfloat162(l[2], l[3]);
        ((__nv_bfloat162*)&lp)[2] = __halves2bfloat162(l[4], l[5]);
        ((__nv_bfloat162*)&lp)[3] = __halves2bfloat162(l[6], l[7]);
        const uint32_t so = row * AP + ch * 16;
        *(uint4*)(dsm + QA_HI + so) = hp;
        *(uint4*)(dsm + QA_LO + so) = lp;
    }

    const int wm = wid & 3, wn = wid >> 2;
    const int g = lane >> 3, lr = lane & 7;

    for (int w = 0; w < 6; ++w) {
        float acc[2][8][4];
#pragma unroll
        for (int mi = 0; mi < 2; ++mi)
#pragma unroll
            for (int nj = 0; nj < 8; ++nj)
#pragma unroll
                for (int r = 0; r < 4; ++r) acc[mi][nj][r] = 0.f;

        for (int it = 0; it < 8; ++it) {
            const int stage = w * 8 + it;
            cp_wait<2>();
            __syncthreads();
            const uint32_t Bst = sbase + QB0 + (stage % 3) * QB_STG;

#pragma unroll
            for (int pass = 0; pass < 3; ++pass) {
                const uint32_t Ab = sbase + (pass == 2 ? QA_LO : QA_HI);
                const uint32_t Bb = Bst + (pass == 1 ? 10240 : 0);
#pragma unroll
                for (int k16 = 0; k16 < 2; ++k16) {
                    uint32_t afr[2][4];
#pragma unroll
                    for (int mi = 0; mi < 2; ++mi) {
                        const int row = wm * 32 + mi * 16 + ((g & 1) << 3) + lr;
                        const uint32_t addr =
                            Ab + row * AP + (it * 4 + k16 * 2 + (g >> 1)) * 16;
                        ldsm_x4(afr[mi][0], afr[mi][1], afr[mi][2], afr[mi][3], addr);
                    }
                    uint32_t bfr[4][4];
#pragma unroll
                    for (int ni = 0; ni < 4; ++ni) {
                        const int row = wn * 64 + ni * 16 + ((g >> 1) << 3) + lr;
                        const uint32_t addr = Bb + row * GP + (k16 * 2 + (g & 1)) * 16;
                        ldsm_x4(bfr[ni][0], bfr[ni][1], bfr[ni][2], bfr[ni][3], addr);
                    }
#pragma unroll
                    for (int mi = 0; mi < 2; ++mi)
#pragma unroll
                        for (int nj = 0; nj < 8; ++nj)
                            mma_bf16(acc[mi][nj], afr[mi],
                                     bfr[nj >> 1][(nj & 1) * 2],
                                     bfr[nj >> 1][(nj & 1) * 2 + 1]);
                }
            }
            __syncthreads();
            if (stage + 3 < 48) issueB(stage + 3);
            cp_commit();
        }

        float* Yf = outs.y[w];
#pragma unroll
        for (int mi = 0; mi < 2; ++mi)
#pragma unroll
            for (int rr = 0; rr < 2; ++rr) {
                const int m = wm * 32 + mi * 16 + (lane >> 2) + rr * 8;
                const size_t yrow = abase + (size_t)m * EE + nb * 128;
#pragma unroll
                for (int nj = 0; nj < 8; ++nj) {
                    const int colo = wn * 64 + nj * 8 + (lane & 3) * 2;
                    *(float2*)(Yf + yrow + colo) =
                        make_float2(acc[mi][nj][rr * 2 + 0], acc[mi][nj][rr * 2 + 1]);
                }
            }
    }
}

// ---------------------------------------------------------------------------
// Generic HMMA GEMM body v2: 256(M)x128(N) block (2 b-slices), 64x64 warp tiles.
// ---------------------------------------------------------------------------
constexpr int T_A_HI = 0;
constexpr int T_A_LO = 256 * GP;              // 20480
constexpr int T_B_HI = 2 * 256 * GP;          // 40960
constexpr int T_B_LO = T_B_HI + 128 * GP;     // 51200
constexpr int STAGE  = T_B_LO + 128 * GP;     // 61440
constexpr int GEMM_SMEM = 2 * STAGE;          // 122880

template <int EPI>
__device__ __forceinline__ void gemm_body(
    const __nv_bfloat16* __restrict__ Ah, const __nv_bfloat16* __restrict__ Al,
    const __nv_bfloat16* __restrict__ Wh, const __nv_bfloat16* __restrict__ Wl,
    const float* __restrict__ bias,
    float* __restrict__ Yf,
    __nv_bfloat16* __restrict__ Yh, __nv_bfloat16* __restrict__ Yl,
    int b0, int nb, int c, uint32_t sbase)
{
    const int tid = threadIdx.x;
    const int wid = tid >> 5, lane = tid & 31;

    const size_t abase0 = ((size_t)b0 * CC + c) * SS * EE;
    const size_t bstride = (size_t)CC * SS * EE;
    const size_t wbase = (size_t)c * EE * EE + (size_t)nb * 128 * EE;

    auto issue = [&](int stg) {
        const int kb = stg * 32;
        const uint32_t sb = sbase + (stg & 1) * STAGE;
#pragma unroll
        for (int j = 0; j < 4; ++j) {
            const int t2 = tid + j * 256;
            const int row = t2 >> 2, ch = t2 & 3;
            const int bo = row >> 7, s = row & 127;
            const size_t goff = abase0 + (size_t)bo * bstride + (size_t)s * EE + kb + ch * 8;
            const uint32_t so = row * GP + ch * 16;
            cp_async16(sb + T_A_HI + so, Ah + goff);
            cp_async16(sb + T_A_LO + so, Al + goff);
        }
#pragma unroll
        for (int j = 0; j < 2; ++j) {
            const int t2 = tid + j * 256;
            const int row = t2 >> 2, ch = t2 & 3;
            const size_t goff = wbase + (size_t)row * EE + kb + ch * 8;
            const uint32_t so = row * GP + ch * 16;
            cp_async16(sb + T_B_HI + so, Wh + goff);
            cp_async16(sb + T_B_LO + so, Wl + goff);
        }
    };
    issue(0); cp_commit();
    issue(1); cp_commit();

    const int wm = wid & 3, wn = wid >> 2;
    const int g = lane >> 3, lr = lane & 7;

    float acc[4][8][4];
#pragma unroll
    for (int mi = 0; mi < 4; ++mi)
#pragma unroll
        for (int nj = 0; nj < 8; ++nj)
#pragma unroll
            for (int r = 0; r < 4; ++r) acc[mi][nj][r] = 0.f;

    for (int it = 0; it < 8; ++it) {
        cp_wait<1>();
        __syncthreads();
        const uint32_t st = sbase + (it & 1) * STAGE;

#pragma unroll
        for (int pass = 0; pass < 3; ++pass) {
            const uint32_t Ab = st + (pass == 2 ? T_A_LO : T_A_HI);
            const uint32_t Bb = st + (pass == 1 ? T_B_LO : T_B_HI);
#pragma unroll
            for (int k16 = 0; k16 < 2; ++k16) {
                uint32_t afr[4][4];
#pragma unroll
                for (int mi = 0; mi < 4; ++mi) {
                    const int row = wm * 64 + mi * 16 + ((g & 1) << 3) + lr;
                    const uint32_t addr = Ab + row * GP + (k16 * 2 + (g >> 1)) * 16;
                    ldsm_x4(afr[mi][0], afr[mi][1], afr[mi][2], afr[mi][3], addr);
                }
                uint32_t bfr[4][4];
#pragma unroll
                for (int ni = 0; ni < 4; ++ni) {
                    const int row = wn * 64 + ni * 16 + ((g >> 1) << 3) + lr;
                    const uint32_t addr = Bb + row * GP + (k16 * 2 + (g & 1)) * 16;
                    ldsm_x4(bfr[ni][0], bfr[ni][1], bfr[ni][2], bfr[ni][3], addr);
                }
#pragma unroll
                for (int mi = 0; mi < 4; ++mi)
#pragma unroll
                    for (int nj = 0; nj < 8; ++nj)
                        mma_bf16(acc[mi][nj], afr[mi],
                                 bfr[nj >> 1][(nj & 1) * 2],
                                 bfr[nj >> 1][(nj & 1) * 2 + 1]);
            }
        }
        __syncthreads();
        if (it + 2 < 8) issue(it + 2);
        cp_commit();
    }

#pragma unroll
    for (int mi = 0; mi < 4; ++mi) {
#pragma unroll
        for (int rr = 0; rr < 2; ++rr) {
            const int m = wm * 64 + mi * 16 + (lane >> 2) + rr * 8;
            const int bo = m >> 7, s = m & 127;
            const size_t yrow = abase0 + (size_t)bo * bstride + (size_t)s * EE + nb * 128;
#pragma unroll
            for (int nj = 0; nj < 8; ++nj) {
                const int col = wn * 64 + nj * 8 + (lane & 3) * 2;
                float v0 = acc[mi][nj][rr * 2 + 0];
                float v1 = acc[mi][nj][rr * 2 + 1];
                if constexpr (EPI == 0) {
                    *(float2*)(Yf + yrow + col) = make_float2(v0, v1);
                } else {
                    const float* bp = bias + (size_t)c * EE + nb * 128 + col;
                    v0 += bp[0];
                    v1 += bp[1];
                    if constexpr (EPI == 1) {
                        v0 = fmaxf(v0, 0.f);
                        v1 = fmaxf(v1, 0.f);
                        __nv_bfloat16 h0, l0, h1, l1;
                        split_bf16(v0, h0, l0);
                        split_bf16(v1, h1, l1);
                        *(__nv_bfloat162*)(Yh + yrow + col) = __halves2bfloat162(h0, h1);
                        *(__nv_bfloat162*)(Yl + yrow + col) = __halves2bfloat162(l0, l1);
                    } else {
                        *(float2*)(Yf + yrow + col) = make_float2(v0, v1);
                    }
                }
            }
        }
    }
}

template <int EPI>
__global__ __launch_bounds__(256) void gemm_mma(
    const __nv_bfloat16* __restrict__ Ah, const __nv_bfloat16* __restrict__ Al,
    const __nv_bfloat16* __restrict__ Wh, const __nv_bfloat16* __restrict__ Wl,
    const float* __restrict__ bias,
    float* __restrict__ Yf,
    __nv_bfloat16* __restrict__ Yh, __nv_bfloat16* __restrict__ Yl)
{
    extern __shared__ __align__(16) char dsm[];
    gemm_body<EPI>(Ah, Al, Wh, Wl, bias, Yf, Yh, Yl,
                   blockIdx.x * 2, blockIdx.y, blockIdx.z, smem_u32(dsm));
}

__global__ __launch_bounds__(256) void gemm_wo_pair(
    const __nv_bfloat16* __restrict__ Ah0, const __nv_bfloat16* __restrict__ Al0,
    const __nv_bfloat16* __restrict__ Wh0, const __nv_bfloat16* __restrict__ Wl0,
    float* __restrict__ Y0,
    const __nv_bfloat16* __restrict__ Ah1, const __nv_bfloat16* __restrict__ Al1,
    const __nv_bfloat16* __restrict__ Wh1, const __nv_bfloat16* __restrict__ Wl1,
    float* __restrict__ Y1)
{
    extern __shared__ __align__(16) char dsm[];
    const int zz = blockIdx.z;
    const int br = zz >= CC;
    const int c = br ? zz - CC : zz;
    gemm_body<0>(br ? Ah1 : Ah0, br ? Al1 : Al0,
                 br ? Wh1 : Wh0, br ? Wl1 : Wl0,
                 nullptr, br ? Y1 : Y0, nullptr, nullptr,
                 blockIdx.x * 2, blockIdx.y, c, smem_u32(dsm));
}

// ---------------------------------------------------------------------------
// Spatial attention (R9 winner): one block per (b,s), 8 heads, 768 thr, 2 CTA/SM.
// ---------------------------------------------------------------------------
constexpr int SA_P = 260;
constexpr int SA_SMEM = (3 * CC * SA_P + HH * CC * 25) * 4;  // 94,080 B

__global__ __launch_bounds__(768, 2) void spatial_attn(
    const float* __restrict__ q, const float* __restrict__ k,
    const float* __restrict__ v, __nv_bfloat16* __restrict__ oh,
    __nv_bfloat16* __restrict__ ol)
{
    extern __shared__ float sa[];
    float* qs = sa;
    float* ks = qs + CC * SA_P;
    float* vs = ks + CC * SA_P;
    float* sc = vs + CC * SA_P;

    const int s = blockIdx.x, b = blockIdx.y;
    const int t = threadIdx.x;
    const size_t gbase = ((size_t)b * CC * SS + s) * EE;
    const size_t cstride = (size_t)SS * EE;

#pragma unroll
    for (int i = 0; i < 2; ++i) {
        const int idx = t + i * 768;
        const int row = idx >> 6, e4 = idx & 63;
        const size_t g = gbase + row * cstride + e4 * 4;
        const int so = row * SA_P + e4 * 4;
        *(float4*)(qs + so) = *(const float4*)(q + g);
        *(float4*)(ks + so) = *(const float4*)(k + g);
        *(float4*)(vs + so) = *(const float4*)(v + g);
    }
    __syncthreads();

    {
        const int h = t / 96;
        const int r = t - h * 96;
        const int cig = r >> 3, dig = r & 7;
        const int ci0 = cig * 2, di0 = dig * 3;
        const float* qb = qs + ci0 * SA_P + h * 32;
        const float* kb = ks + di0 * SA_P + h * 32;
        float a00 = 0.f, a01 = 0.f, a02 = 0.f;
        float a10 = 0.f, a11 = 0.f, a12 = 0.f;
#pragma unroll
        for (int p = 0; p < 32; ++p) {
            const float q0 = qb[p], q1 = qb[SA_P + p];
            const float k0 = kb[p], k1 = kb[SA_P + p], k2 = kb[2 * SA_P + p];
            a00 = fmaf(q0, k0, a00); a01 = fmaf(q0, k1, a01); a02 = fmaf(q0, k2, a02);
            a10 = fmaf(q1, k0, a10); a11 = fmaf(q1, k1, a11); a12 = fmaf(q1, k2, a12);
        }
        float* sr0 = sc + (h * CC + ci0) * 25 + di0;
        float* sr1 = sr0 + 25;
        sr0[0] = a00 * INV_SQRT_P; sr0[1] = a01 * INV_SQRT_P; sr0[2] = a02 * INV_SQRT_P;
        sr1[0] = a10 * INV_SQRT_P; sr1[1] = a11 * INV_SQRT_P; sr1[2] = a12 * INV_SQRT_P;
    }
    __syncthreads();

    if (t < HH * CC) {
        float* row = sc + t * 25;
        float mx = -1e30f;
#pragma unroll
        for (int d = 0; d < CC; ++d) mx = fmaxf(mx, row[d]);
        float sm = 0.f;
#pragma unroll
        for (int d = 0; d < CC; ++d) { float e = __expf(row[d] - mx); row[d] = e; sm += e; }
        const float inv = 1.f / sm;
#pragma unroll
        for (int d = 0; d < CC; ++d) row[d] *= inv;
    }
    __syncthreads();

#pragma unroll
    for (int i = 0; i < 2; ++i) {
        const int item = t + i * 768;
        const int h = item / 192;
        const int rr = item - h * 192;
        const int cc = rr >> 3, p4 = (rr & 7) * 4;
        const float* arow = sc + (h * CC + cc) * 25;
        const float* vb = vs + h * 32 + p4;
        float s0 = 0.f, s1 = 0.f, s2 = 0.f, s3 = 0.f;
#pragma unroll
        for (int d = 0; d < CC; ++d) {
            const float a = arow[d];
            const float4 vv = *(const float4*)(vb + d * SA_P);
            s0 = fmaf(a, vv.x, s0); s1 = fmaf(a, vv.y, s1);
            s2 = fmaf(a, vv.z, s2); s3 = fmaf(a, vv.w, s3);
        }
        const size_t g = gbase + cc * cstride + h * 32 + p4;
        __nv_bfloat16 h0, l0, h1, l1, h2, l2, h3, l3;
        split_bf16(s0, h0, l0); split_bf16(s1, h1, l1);
        split_bf16(s2, h2, l2); split_bf16(s3, h3, l3);
        *(__nv_bfloat162*)(oh + g)     = __halves2bfloat162(h0, h1);
        *(__nv_bfloat162*)(oh + g + 2) = __halves2bfloat162(h2, h3);
        *(__nv_bfloat162*)(ol + g)     = __halves2bfloat162(l0, l1);
        *(__nv_bfloat162*)(ol + g + 2) = __halves2bfloat162(l2, l3);
    }
}

// ---------------------------------------------------------------------------
// Temporal attention v3 — tensor-core flash-style.
// One block per (b,h,c): 8 warps x 16 s-rows. S=Q·K^T on HMMA (3-pass bf16
// split), softmax in registers, P passed to O=P·V via C->A fragment repack.
// smem: qt/kt bf16 hi+lo (GP pitch), vs = V^T bf16 hi+lo (272B pitch). 58 KB.
// ---------------------------------------------------------------------------
constexpr int TQT_HI = 0;
constexpr int TQT_LO = 128 * GP;             // 10240
constexpr int TKT_HI = 2 * 128 * GP;         // 20480
constexpr int TKT_LO = 3 * 128 * GP;         // 30720
constexpr int TVS_HI = 4 * 128 * GP;         // 40960
constexpr int TVP = 272;                     // V^T pitch (bytes)
constexpr int TVS_LO = TVS_HI + 32 * TVP;    // 49664
constexpr int TEMP_SMEM_BYTES = TVS_LO + 32 * TVP;  // 58368

__global__ __launch_bounds__(256, 2) void temporal_attn(
    const float* __restrict__ q, const float* __restrict__ k,
    const float* __restrict__ v, __nv_bfloat16* __restrict__ oh,
    __nv_bfloat16* __restrict__ ol)
{
    extern __shared__ __align__(16) char tsm[];
    const uint32_t sb = smem_u32(tsm);
    const int c = blockIdx.x, h = blockIdx.y, b = blockIdx.z;
    const int tid = threadIdx.x;
    const int wid = tid >> 5, lane = tid & 31;
    const size_t base = (((size_t)b * CC + c) * SS) * EE + h * PP;

    // ---- load + convert q,k (rows: [s][p], GP pitch) and v (transposed) ----
#pragma unroll
    for (int i = 0; i < 4; ++i) {
        const int idx = tid + i * 256;           // 0..1023 = 128 rows x 8 chunks
        const int row = idx >> 3, p4 = (idx & 7) * 4;
        const size_t g = base + (size_t)row * EE + p4;
        // q
        {
            float4 vq = *(const float4*)(q + g);
            __nv_bfloat16 hh[4], ll[4];
            split_bf16(vq.x, hh[0], ll[0]); split_bf16(vq.y, hh[1], ll[1]);
            split_bf16(vq.z, hh[2], ll[2]); split_bf16(vq.w, hh[3], ll[3]);
            uint2 hp, lp;
            ((__nv_bfloat162*)&hp)[0] = __halves2bfloat162(hh[0], hh[1]);
            ((__nv_bfloat162*)&hp)[1] = __halves2bfloat162(hh[2], hh[3]);
            ((__nv_bfloat162*)&lp)[0] = __halves2bfloat162(ll[0], ll[1]);
            ((__nv_bfloat162*)&lp)[1] = __halves2bfloat162(ll[2], ll[3]);
            *(uint2*)(tsm + TQT_HI + row * GP + p4 * 2) = hp;
            *(uint2*)(tsm + TQT_LO + row * GP + p4 * 2) = lp;
        }
        // k
        {
            float4 vk = *(const float4*)(k + g);
            __nv_bfloat16 hh[4], ll[4];
            split_bf16(vk.x, hh[0], ll[0]); split_bf16(vk.y, hh[1], ll[1]);
            split_bf16(vk.z, hh[2], ll[2]); split_bf16(vk.w, hh[3], ll[3]);
            uint2 hp, lp;
            ((__nv_bfloat162*)&hp)[0] = __halves2bfloat162(hh[0], hh[1]);
            ((__nv_bfloat162*)&hp)[1] = __halves2bfloat162(hh[2], hh[3]);
            ((__nv_bfloat162*)&lp)[0] = __halves2bfloat162(ll[0], ll[1]);
            ((__nv_bfloat162*)&lp)[1] = __halves2bfloat162(ll[2], ll[3]);
            *(uint2*)(tsm + TKT_HI + row * GP + p4 * 2) = hp;
            *(uint2*)(tsm + TKT_LO + row * GP + p4 * 2) = lp;
        }
        // v -> transposed vs[p][t]
        {
            float4 vv = *(const float4*)(v + g);
            float vf[4] = {vv.x, vv.y, vv.z, vv.w};
#pragma unroll
            for (int j = 0; j < 4; ++j) {
                __nv_bfloat16 hi, lo;
                split_bf16(vf[j], hi, lo);
                *(__nv_bfloat16*)(tsm + TVS_HI + (p4 + j) * TVP + row * 2) = hi;
                *(__nv_bfloat16*)(tsm + TVS_LO + (p4 + j) * TVP + row * 2) = lo;
            }
        }
    }
    __syncthreads();

    const int g2 = lane >> 3, lr = lane & 7;

    // ---- S = Q·K^T : warp computes rows 16*wid..+15 x 128 cols ----
    float sacc[16][4];
#pragma unroll
    for (int nj = 0; nj < 16; ++nj)
#pragma unroll
        for (int r = 0; r < 4; ++r) sacc[nj][r] = 0.f;

#pragma unroll
    for (int pass = 0; pass < 3; ++pass) {
        const uint32_t Ab = sb + (pass == 2 ? TQT_LO : TQT_HI);
        const uint32_t Bb = sb + (pass == 1 ? TKT_LO : TKT_HI);
#pragma unroll
        for (int k16 = 0; k16 < 2; ++k16) {
            uint32_t afr[4];
            {
                const int row = wid * 16 + ((g2 & 1) << 3) + lr;
                const uint32_t addr = Ab + row * GP + (k16 * 2 + (g2 >> 1)) * 16;
                ldsm_x4(afr[0], afr[1], afr[2], afr[3], addr);
            }
#pragma unroll
            for (int ni = 0; ni < 8; ++ni) {
                uint32_t bfr[4];
                const int row = ni * 16 + ((g2 >> 1) << 3) + lr;
                const uint32_t addr = Bb + row * GP + (k16 * 2 + (g2 & 1)) * 16;
                ldsm_x4(bfr[0], bfr[1], bfr[2], bfr[3], addr);
                mma_bf16(sacc[ni * 2 + 0], afr, bfr[0], bfr[1]);
                mma_bf16(sacc[ni * 2 + 1], afr, bfr[2], bfr[3]);
            }
        }
    }

    // ---- softmax in registers ----
    // thread holds: row r0 = wid*16 + (lane>>2): c0,c1 of all 16 tiles
    //               row r1 = r0 + 8:             c2,c3
#pragma unroll
    for (int nj = 0; nj < 16; ++nj)
#pragma unroll
        for (int r = 0; r < 4; ++r) sacc[nj][r] *= INV_SQRT_P;

    float mx0 = -1e30f, mx1 = -1e30f;
#pragma unroll
    for (int nj = 0; nj < 16; ++nj) {
        mx0 = fmaxf(mx0, fmaxf(sacc[nj][0], sacc[nj][1]));
        mx1 = fmaxf(mx1, fmaxf(sacc[nj][2], sacc[nj][3]));
    }
    mx0 = fmaxf(mx0, __shfl_xor_sync(0xffffffffu, mx0, 1));
    mx0 = fmaxf(mx0, __shfl_xor_sync(0xffffffffu, mx0, 2));
    mx1 = fmaxf(mx1, __shfl_xor_sync(0xffffffffu, mx1, 1));
    mx1 = fmaxf(mx1, __shfl_xor_sync(0xffffffffu, mx1, 2));

    float sum0 = 0.f, sum1 = 0.f;
#pragma unroll
    for (int nj = 0; nj < 16; ++nj) {
        sacc[nj][0] = __expf(sacc[nj][0] - mx0);
        sacc[nj][1] = __expf(sacc[nj][1] - mx0);
        sacc[nj][2] = __expf(sacc[nj][2] - mx1);
        sacc[nj][3] = __expf(sacc[nj][3] - mx1);
        sum0 += sacc[nj][0] + sacc[nj][1];
        sum1 += sacc[nj][2] + sacc[nj][3];
    }
    sum0 += __shfl_xor_sync(0xffffffffu, sum0, 1);
    sum0 += __shfl_xor_sync(0xffffffffu, sum0, 2);
    sum1 += __shfl_xor_sync(0xffffffffu, sum1, 1);
    sum1 += __shfl_xor_sync(0xffffffffu, sum1, 2);
    const float inv0 = 1.f / sum0, inv1 = 1.f / sum1;
#pragma unroll
    for (int nj = 0; nj < 16; ++nj) {
        sacc[nj][0] *= inv0;
        sacc[nj][1] *= inv0;
        sacc[nj][2] *= inv1;
        sacc[nj][3] *= inv1;
    }

    // ---- O = P·V : P from registers (C->A repack), V^T from smem ----
    float oacc[4][4];
#pragma unroll
    for (int nj = 0; nj < 4; ++nj)
#pragma unroll
        for (int r = 0; r < 4; ++r) oacc[nj][r] = 0.f;

#pragma unroll
    for (int pass = 0; pass < 3; ++pass) {
        const uint32_t Bb = sb + (pass == 1 ? TVS_LO : TVS_HI);
#pragma unroll
        for (int ki = 0; ki < 8; ++ki) {
            uint32_t a[4];
            if (pass <= 1) {
                a[0] = pack_bf16x2(sacc[2 * ki][0],     sacc[2 * ki][1]);
                a[1] = pack_bf16x2(sacc[2 * ki][2],     sacc[2 * ki][3]);
                a[2] = pack_bf16x2(sacc[2 * ki + 1][0], sacc[2 * ki + 1][1]);
                a[3] = pack_bf16x2(sacc[2 * ki + 1][2], sacc[2 * ki + 1][3]);
            } else {
                a[0] = pack_bf16x2(bf16_lo_res(sacc[2 * ki][0]),     bf16_lo_res(sacc[2 * ki][1]));
                a[1] = pack_bf16x2(bf16_lo_res(sacc[2 * ki][2]),     bf16_lo_res(sacc[2 * ki][3]));
                a[2] = pack_bf16x2(bf16_lo_res(sacc[2 * ki + 1][0]), bf16_lo_res(sacc[2 * ki + 1][1]));
                a[3] = pack_bf16x2(bf16_lo_res(sacc[2 * ki + 1][2]), bf16_lo_res(sacc[2 * ki + 1][3]));
            }
#pragma unroll
            for (int half = 0; half < 2; ++half) {
                uint32_t bfr[4];
                const int row = half * 16 + ((g2 >> 1) << 3) + lr;
                const uint32_t addr = Bb + row * TVP + (ki * 2 + (g2 & 1)) * 16;
                ldsm_x4(bfr[0], bfr[1], bfr[2], bfr[3], addr);
                mma_bf16(oacc[half * 2 + 0], a, bfr[0], bfr[1]);
                mma_bf16(oacc[half * 2 + 1], a, bfr[2], bfr[3]);
            }
        }
    }

    // ---- epilogue: thread writes rows r0 (c0,c1) and r1 (c2,c3) ----
    const int r0 = wid * 16 + (lane >> 2);
    const int r1 = r0 + 8;
#pragma unroll
    for (int nj = 0; nj < 4; ++nj) {
        const int col = nj * 8 + (lane & 3) * 2;
        const size_t g0 = base + (size_t)r0 * EE + col;
        const size_t g1 = base + (size_t)r1 * EE + col;
        __nv_bfloat16 h0, l0, h1, l1;
        split_bf16(oacc[nj][0], h0, l0);
        split_bf16(oacc[nj][1], h1, l1);
        *(__nv_bfloat162*)(oh + g0) = __halves2bfloat162(h0, h1);
        *(__nv_bfloat162*)(ol + g0) = __halves2bfloat162(l0, l1);
        split_bf16(oacc[nj][2], h0, l0);
        split_bf16(oacc[nj][3], h1, l1);
        *(__nv_bfloat162*)(oh + g1) = __halves2bfloat162(h0, h1);
        *(__nv_bfloat162*)(ol + g1) = __halves2bfloat162(l0, l1);
    }
}

// ---------------------------------------------------------------------------
// LayerNorm kernels — warp-per-row.
// ---------------------------------------------------------------------------
__device__ __forceinline__ float warp_sum(float v) {
#pragma unroll
    for (int off = 16; off > 0; off >>= 1)
        v += __shfl_xor_sync(0xffffffffu, v, off);
    return v;
}

__global__ __launch_bounds__(256) void dual_ln(
    const float* __restrict__ x, const float* __restrict__ a,
    const float* __restrict__ b2, const float* __restrict__ g,
    const float* __restrict__ beta, float* __restrict__ out,
    __nv_bfloat16* __restrict__ oh, __nv_bfloat16* __restrict__ ol)
{
    const int warp = threadIdx.x >> 5, lane = threadIdx.x & 31;
    const int row = blockIdx.x * 8 + warp;
    const size_t base = (size_t)row * EE;
    const int e0 = lane * 4, e1 = 128 + lane * 4;

    float4 x0 = *(const float4*)(x + base + e0);
    float4 x1 = *(const float4*)(x + base + e1);
    float4 a0 = *(const float4*)(a + base + e0);
    float4 a1 = *(const float4*)(a + base + e1);
    float4 b0 = *(const float4*)(b2 + base + e0);
    float4 b1 = *(const float4*)(b2 + base + e1);

    float v1[8] = {x0.x + a0.x, x0.y + a0.y, x0.z + a0.z, x0.w + a0.w,
                   x1.x + a1.x, x1.y + a1.y, x1.z + a1.z, x1.w + a1.w};
    float v2[8] = {x0.x + b0.x, x0.y + b0.y, x0.z + b0.z, x0.w + b0.w,
                   x1.x + b1.x, x1.y + b1.y, x1.z + b1.z, x1.w + b1.w};

    float s1 = 0.f, q1 = 0.f, s2 = 0.f, q2 = 0.f;
#pragma unroll
    for (int j = 0; j < 8; ++j) {
        s1 += v1[j]; q1 = fmaf(v1[j], v1[j], q1);
        s2 += v2[j]; q2 = fmaf(v2[j], v2[j], q2);
    }
    s1 = warp_sum(s1); q1 = warp_sum(q1);
    s2 = warp_sum(s2); q2 = warp_sum(q2);

    const float invE = 1.f / (float)EE;
    const float m1 = s1 * invE, m2 = s2 * invE;
    const float r1 = rsqrtf(fmaxf(q1 * invE - m1 * m1, 0.f) + LN_EPS);
    const float r2 = rsqrtf(fmaxf(q2 * invE - m2 * m2, 0.f) + LN_EPS);

    float4 g0 = *(const float4*)(g + e0);
    float4 g1 = *(const float4*)(g + e1);
    float4 t0 = *(const float4*)(beta + e0);
    float4 t1 = *(const float4*)(beta + e1);
    float gg[8] = {g0.x, g0.y, g0.z, g0.w, g1.x, g1.y, g1.z, g1.w};
    float bt[8] = {t0.x, t0.y, t0.z, t0.w, t1.x, t1.y, t1.z, t1.w};

    float o[8];
#pragma unroll
    for (int j = 0; j < 8; ++j)
        o[j] = (v1[j] - m1) * r1 * gg[j] + bt[j]
             + (v2[j] - m2) * r2 * gg[j] + bt[j];

    *(float4*)(out + base + e0) = make_float4(o[0], o[1], o[2], o[3]);
    *(float4*)(out + base + e1) = make_float4(o[4], o[5], o[6], o[7]);

    __nv_bfloat16 hh[8], ll[8];
#pragma unroll
    for (int j = 0; j < 8; ++j) split_bf16(o[j], hh[j], ll[j]);
    *(__nv_bfloat162*)(oh + base + e0)     = __halves2bfloat162(hh[0], hh[1]);
    *(__nv_bfloat162*)(oh + base + e0 + 2) = __halves2bfloat162(hh[2], hh[3]);
    *(__nv_bfloat162*)(oh + base + e1)     = __halves2bfloat162(hh[4], hh[5]);
    *(__nv_bfloat162*)(oh + base + e1 + 2) = __halves2bfloat162(hh[6], hh[7]);
    *(__nv_bfloat162*)(ol + base + e0)     = __halves2bfloat162(ll[0], ll[1]);
    *(__nv_bfloat162*)(ol + base + e0 + 2) = __halves2bfloat162(ll[2], ll[3]);
    *(__nv_bfloat162*)(ol + base + e1)     = __halves2bfloat162(ll[4], ll[5]);
    *(__nv_bfloat162*)(ol + base + e1 + 2) = __halves2bfloat162(ll[6], ll[7]);
}

__global__ __launch_bounds__(256) void final_ln(
    const float* __restrict__ a, const float* __restrict__ f,
    const float* __restrict__ g, const float* __restrict__ beta,
    float* __restrict__ out)
{
    const int warp = threadIdx.x >> 5, lane = threadIdx.x & 31;
    const int row = blockIdx.x * 8 + warp;
    const size_t base = (size_t)row * EE;
    const int e0 = lane * 4, e1 = 128 + lane * 4;

    float4 a0 = *(const float4*)(a + base + e0);
    float4 a1 = *(const float4*)(a + base + e1);
    float4 f0 = *(const float4*)(f + base + e0);
    float4 f1 = *(const float4*)(f + base + e1);

    float v[8] = {a0.x + f0.x, a0.y + f0.y, a0.z + f0.z, a0.w + f0.w,
                  a1.x + f1.x, a1.y + f1.y, a1.z + f1.z, a1.w + f1.w};

    float s = 0.f, q = 0.f;
#pragma unroll
    for (int j = 0; j < 8; ++j) { s += v[j]; q = fmaf(v[j], v[j], q); }
    s = warp_sum(s); q = warp_sum(q);

    const float invE = 1.f / (float)EE;
    const float m = s * invE;
    const float r = rsqrtf(fmaxf(q * invE - m * m, 0.f) + LN_EPS);

    float4 g0 = *(const float4*)(g + e0);
    float4 g1 = *(const float4*)(g + e1);
    float4 t0 = *(const float4*)(beta + e0);
    float4 t1 = *(const float4*)(beta + e1);
    float gg[8] = {g0.x, g0.y, g0.z, g0.w, g1.x, g1.y, g1.z, g1.w};
    float bt[8] = {t0.x, t0.y, t0.z, t0.w, t1.x, t1.y, t1.z, t1.w};

    float o[8];
#pragma unroll
    for (int j = 0; j < 8; ++j) o[j] = (v[j] - m) * r * gg[j] + bt[j];
    *(float4*)(out + base + e0) = make_float4(o[0], o[1], o[2], o[3]);
    *(float4*)(out + base + e1) = make_float4(o[4], o[5], o[6], o[7]);
}

// ---------------------------------------------------------------------------
// kernel_launch
// ---------------------------------------------------------------------------
extern "C" void kernel_launch(void* const* d_in, const int* in_sizes, int n_in,
                              void* d_out, int out_size)
{
    const float* x    = (const float*)d_in[0];
    const float* ln_g = (const float*)d_in[9];
    const float* ln_b = (const float*)d_in[10];
    const float* ff_b1 = (const float*)d_in[12];
    const float* ff_b2 = (const float*)d_in[14];
    float* out = (float*)d_out;

    float *qs, *ks, *vs, *qt, *kt, *vt, *spat, *temp, *attn, *ffo;
    __nv_bfloat16 *ah, *al, *hh, *hl, *wh, *wl;
    cudaGetSymbolAddress((void**)&qs,   g_qs);
    cudaGetSymbolAddress((void**)&ks,   g_ks);
    cudaGetSymbolAddress((void**)&vs,   g_vs);
    cudaGetSymbolAddress((void**)&qt,   g_qt);
    cudaGetSymbolAddress((void**)&kt,   g_kt);
    cudaGetSymbolAddress((void**)&vt,   g_vt);
    cudaGetSymbolAddress((void**)&spat, g_spat);
    cudaGetSymbolAddress((void**)&temp, g_temp);
    cudaGetSymbolAddress((void**)&attn, g_attn);
    cudaGetSymbolAddress((void**)&ffo,  g_ffo);
    cudaGetSymbolAddress((void**)&ah, g_ah);
    cudaGetSymbolAddress((void**)&al, g_al);
    cudaGetSymbolAddress((void**)&hh, g_hh);
    cudaGetSymbolAddress((void**)&hl, g_hl);
    cudaGetSymbolAddress((void**)&wh, g_wh);
    cudaGetSymbolAddress((void**)&wl, g_wl);

    cudaFuncSetAttribute(gemm_qkv6,   cudaFuncAttributeMaxDynamicSharedMemorySize, QKV_SMEM);
    cudaFuncSetAttribute(gemm_mma<1>, cudaFuncAttributeMaxDynamicSharedMemorySize, GEMM_SMEM);
    cudaFuncSetAttribute(gemm_mma<2>, cudaFuncAttributeMaxDynamicSharedMemorySize, GEMM_SMEM);
    cudaFuncSetAttribute(gemm_wo_pair, cudaFuncAttributeMaxDynamicSharedMemorySize, GEMM_SMEM);
    cudaFuncSetAttribute(spatial_attn, cudaFuncAttributeMaxDynamicSharedMemorySize, SA_SMEM);
    cudaFuncSetAttribute(temporal_attn, cudaFuncAttributeMaxDynamicSharedMemorySize, TEMP_SMEM_BYTES);

    // ---- weight conversion ----
    WPtrs wp;
    wp.p[0] = (const float*)d_in[1];
    wp.p[1] = (const float*)d_in[2];
    wp.p[2] = (const float*)d_in[3];
    wp.p[3] = (const float*)d_in[4];
    wp.p[4] = (const float*)d_in[5];
    wp.p[5] = (const float*)d_in[6];
    wp.p[6] = (const float*)d_in[7];
    wp.p[7] = (const float*)d_in[8];
    wp.p[8] = (const float*)d_in[11];
    wp.p[9] = (const float*)d_in[13];
    convert_weights_t<<<dim3(64, CC, NW), 256>>>(wp, wh, wl);

    // ---- fused q/k/v projections (x split in-kernel) ----
    Out6 o6;
    o6.y[0] = qs; o6.y[1] = ks; o6.y[2] = vs;
    o6.y[3] = qt; o6.y[4] = kt; o6.y[5] = vt;
    gemm_qkv6<<<dim3(BB, 2, CC), 256, QKV_SMEM>>>(x, wh, wl, o6);

    // ---- attentions ----
    spatial_attn<<<dim3(SS, BB), 768, SA_SMEM>>>(qs, ks, vs, ah, al);
    temporal_attn<<<dim3(CC, HH, BB), 256, TEMP_SMEM_BYTES>>>(qt, kt, vt, hh, hl);

    // ---- output projections (merged dual launch, M=256 blocks) ----
    gemm_wo_pair<<<dim3(BB / 2, 2, 2 * CC), 256, GEMM_SMEM>>>(
        ah, al, wh + 3*(size_t)WELEMS, wl + 3*(size_t)WELEMS, spat,
        hh, hl, wh + 7*(size_t)WELEMS, wl + 7*(size_t)WELEMS, temp);

    // ---- residual + dual LN (emits attn fp32 + bf16 pair) ----
    dual_ln<<<NROWS / 8, 256>>>(x, spat, temp, ln_g, ln_b, attn, ah, al);

    // ---- per-joint FF + final LN ----
    gemm_mma<1><<<dim3(BB / 2, 2, CC), 256, GEMM_SMEM>>>(ah, al, wh + 8*(size_t)WELEMS, wl + 8*(size_t)WELEMS, ff_b1, nullptr, hh, hl);
    gemm_mma<2><<<dim3(BB / 2, 2, CC), 256, GEMM_SMEM>>>(hh, hl, wh + 9*(size_t)WELEMS, wl + 9*(size_t)WELEMS, ff_b2, ffo, nullptr, nullptr);
    final_ln<<<NROWS / 8, 256>>>(attn, ffo, ln_g, ln_b, out);
}

// round 13
// speedup vs baseline: 1.9805x; 1.0308x over previous
#include <cuda_runtime.h>
#include <cuda_bf16.h>
#include <cstdint>
#include <cstddef>

// Problem dims
constexpr int BB = 16, CC = 24, SS = 128, EE = 256, HH = 8, PP = 32;
constexpr int NTOT  = BB * CC * SS * EE;     // 12,582,912
constexpr int NROWS = BB * CC * SS;          // 49,152
constexpr int WELEMS = CC * EE * EE;         // 1,572,864 per weight
constexpr int NW = 10;
constexpr float LN_EPS = 1e-6f;
constexpr float INV_SQRT_P = 0.17677669529663687f;

// ---------------------------------------------------------------------------
// Device scratch
// ---------------------------------------------------------------------------
__device__ float g_qs[NTOT], g_ks[NTOT], g_vs[NTOT];
__device__ float g_qt[NTOT], g_kt[NTOT], g_vt[NTOT];
__device__ float g_spat[NTOT], g_temp[NTOT], g_attn[NTOT], g_ffo[NTOT];
__device__ __align__(16) __nv_bfloat16 g_ah[NTOT], g_al[NTOT];   // spatial-out / attn pair
__device__ __align__(16) __nv_bfloat16 g_hh[NTOT], g_hl[NTOT];   // temporal-out / ff hidden pair
__device__ __align__(16) __nv_bfloat16 g_wh[NW * WELEMS], g_wl[NW * WELEMS];

// ---------------------------------------------------------------------------
// PTX helpers (baseline ISA only)
// ---------------------------------------------------------------------------
__device__ __forceinline__ uint32_t smem_u32(const void* p) {
    uint32_t a;
    asm("{ .reg .u64 t; cvta.to.shared.u64 t, %1; cvt.u32.u64 %0, t; }"
        : "=r"(a) : "l"(p));
    return a;
}
__device__ __forceinline__ void cp_async16(uint32_t smem, const void* gmem) {
    asm volatile("cp.async.cg.shared.global [%0], [%1], 16;"
                 :: "r"(smem), "l"(gmem));
}
__device__ __forceinline__ void cp_commit() {
    asm volatile("cp.async.commit_group;");
}
template <int N>
__device__ __forceinline__ void cp_wait() {
    asm volatile("cp.async.wait_group %0;" :: "n"(N) : "memory");
}
__device__ __forceinline__ void ldsm_x4(uint32_t& r0, uint32_t& r1,
                                        uint32_t& r2, uint32_t& r3, uint32_t addr) {
    asm volatile("ldmatrix.sync.aligned.m8n8.x4.shared.b16 {%0,%1,%2,%3}, [%4];"
                 : "=r"(r0), "=r"(r1), "=r"(r2), "=r"(r3) : "r"(addr));
}
__device__ __forceinline__ void mma_bf16(float* d, const uint32_t* a,
                                         uint32_t b0, uint32_t b1) {
    asm volatile(
        "mma.sync.aligned.m16n8k16.row.col.f32.bf16.bf16.f32 "
        "{%0,%1,%2,%3}, {%4,%5,%6,%7}, {%8,%9}, {%0,%1,%2,%3};"
        : "+f"(d[0]), "+f"(d[1]), "+f"(d[2]), "+f"(d[3])
        : "r"(a[0]), "r"(a[1]), "r"(a[2]), "r"(a[3]), "r"(b0), "r"(b1));
}
// packed f32x2
__device__ __forceinline__ unsigned long long pack2(float v) {
    unsigned long long r;
    asm("mov.b64 %0, {%1, %1};" : "=l"(r) : "f"(v));
    return r;
}
__device__ __forceinline__ void fma2(unsigned long long& d,
                                     unsigned long long a, unsigned long long b) {
    asm("fma.rn.f32x2 %0, %1, %2, %0;" : "+l"(d) : "l"(a), "l"(b));
}
__device__ __forceinline__ float2 unpack2(unsigned long long v) {
    float2 f;
    asm("mov.b64 {%0, %1}, %2;" : "=f"(f.x), "=f"(f.y) : "l"(v));
    return f;
}

// ---------------------------------------------------------------------------
// bf16 hi/lo split helpers
// ---------------------------------------------------------------------------
__device__ __forceinline__ void split_bf16(float x, __nv_bfloat16& h, __nv_bfloat16& l) {
    h = __float2bfloat16_rn(x);
    l = __float2bfloat16_rn(x - __bfloat162float(h));
}
__device__ __forceinline__ uint32_t pack_bf16x2(float a, float b) {
    __nv_bfloat162 t = __halves2bfloat162(__float2bfloat16_rn(a), __float2bfloat16_rn(b));
    return *(uint32_t*)&t;
}
__device__ __forceinline__ float bf16_lo_res(float x) {
    return x - __bfloat162float(__float2bfloat16_rn(x));
}

// ---------------------------------------------------------------------------
// Weight conversion, coalesced: 32x32 (e,f) tiles via smem transpose.
// ---------------------------------------------------------------------------
struct WPtrs { const float* p[NW]; };

__global__ __launch_bounds__(256) void convert_weights_t(
    WPtrs wp, __nv_bfloat16* __restrict__ wh, __nv_bfloat16* __restrict__ wl)
{
    __shared__ float tile[32][33];
    const int w = blockIdx.z, c = blockIdx.y;
    const int eb = blockIdx.x & 7, fb = blockIdx.x >> 3;
    const int mode = (w == 3 || w >= 7) ? 0 : (w == 0 ? 1 : (w <= 2 ? 2 : 3));
    const int t = threadIdx.x;
    const int col = t & 31, r0 = t >> 5;
    const float* W = wp.p[w];

#pragma unroll
    for (int i = 0; i < 4; ++i) {
        const int row = r0 + i * 8;
        float v;
        if (mode == 0) {
            const int e = eb * 32 + row, f = fb * 32 + col;
            v = W[((size_t)c * EE + e) * EE + f];
        } else if (mode == 1) {
            const int f = fb * 32 + row, e = eb * 32 + col;
            const int h = fb, p = f & 31;
            v = W[(((size_t)h * CC + c) * PP + p) * EE + e];
        } else if (mode == 2) {
            const int e = eb * 32 + row, p = col, h = fb;
            v = W[((size_t)h * EE + e) * PP + p];
        } else {
            const int e = eb * 32 + row, p = col, h = fb;
            v = W[(((size_t)h * CC + c) * EE + e) * PP + p];
        }
        tile[row][col] = v;
    }
    __syncthreads();

#pragma unroll
    for (int i = 0; i < 4; ++i) {
        const int fr = r0 + i * 8;
        const int f = fb * 32 + fr;
        const int e = eb * 32 + col;
        const float v = (mode == 1) ? tile[fr][col] : tile[col][fr];
        __nv_bfloat16 hi, lo;
        split_bf16(v, hi, lo);
        const size_t o = (size_t)w * WELEMS + ((size_t)c << 16) + (size_t)f * EE + e;
        wh[o] = hi;
        wl[o] = lo;
    }
}

// ---------------------------------------------------------------------------
// Fused QKVx6 GEMM v2: A resident (in-kernel split), block M=128 x N=256,
// 8 warps with 64x64 tiles (MMA:LDSM = 4:1), 48 B-stages double-buffered.
// ---------------------------------------------------------------------------
constexpr int AP = 528;
constexpr int QA_HI = 0;
constexpr int QA_LO = 128 * AP;
constexpr int QB0   = 2 * 128 * AP;            // 135168
constexpr int GP = 80;
constexpr int QB_LO  = 256 * GP;               // 20480 (within stage)
constexpr int QB_STG = 2 * 256 * GP;           // 40960
constexpr int QKV_SMEM = QB0 + 2 * QB_STG;     // 217088

struct Out6 { float* y[6]; };

__global__ __launch_bounds__(256) void gemm_qkv6(
    const float* __restrict__ x,
    const __nv_bfloat16* __restrict__ whB, const __nv_bfloat16* __restrict__ wlB,
    Out6 outs)
{
    extern __shared__ __align__(16) char dsm[];
    const uint32_t sbase = smem_u32(dsm);
    const int tid = threadIdx.x;
    const int wid = tid >> 5, lane = tid & 31;
    const int b = blockIdx.x, c = blockIdx.z;

    const size_t abase = ((size_t)b * CC + c) * SS * EE;

    // stage s: weight w = s>>3, K-chunk kc = s&7 (32 wide); B covers all 256 f.
    auto issueB = [&](int stage) {
        const int w = stage >> 3, kb = (stage & 7) * 32;
        const int wg = w + (w >= 3);           // 0,1,2,4,5,6
        const __nv_bfloat16* Wh = whB + (size_t)wg * WELEMS + ((size_t)c << 16);
        const __nv_bfloat16* Wl = wlB + (size_t)wg * WELEMS + ((size_t)c << 16);
        const uint32_t sb = sbase + QB0 + (stage & 1) * QB_STG;
#pragma unroll
        for (int j = 0; j < 4; ++j) {
            const int t2 = tid + j * 256;      // 0..1023 = 256 rows x 4 chunks
            const int row = t2 >> 2, ch = t2 & 3;
            const size_t goff = (size_t)row * EE + kb + ch * 8;
            const uint32_t so = row * GP + ch * 16;
            cp_async16(sb + so, Wh + goff);
            cp_async16(sb + QB_LO + so, Wl + goff);
        }
    };
    issueB(0); cp_commit();
    issueB(1); cp_commit();

    // ---- load A from fp32 x, split to bf16 hi/lo in smem ----
#pragma unroll
    for (int i = 0; i < 16; ++i) {
        const int t2 = tid + i * 256;
        const int row = t2 >> 5, ch = t2 & 31;
        const float* src = x + abase + (size_t)row * EE + ch * 8;
        float4 v0 = *(const float4*)src;
        float4 v1 = *(const float4*)(src + 4);
        float vv[8] = {v0.x, v0.y, v0.z, v0.w, v1.x, v1.y, v1.z, v1.w};
        __nv_bfloat16 h[8], l[8];
#pragma unroll
        for (int j = 0; j < 8; ++j) split_bf16(vv[j], h[j], l[j]);
        uint4 hp, lp;
        ((__nv_bfloat162*)&hp)[0] = __halves2bfloat162(h[0], h[1]);
        ((__nv_bfloat162*)&hp)[1] = __halves2bfloat162(h[2], h[3]);
        ((__nv_bfloat162*)&hp)[2] = __halves2bfloat162(h[4], h[5]);
        ((__nv_bfloat162*)&hp)[3] = __halves2bfloat162(h[6], h[7]);
        ((__nv_bfloat162*)&lp)[0] = __halves2bfloat162(l[0], l[1]);
        ((__nv_bfloat162*)&lp)[1] = __halves2bfloat162(l[2], l[3]);
        ((__nv_bfloat162*)&lp)[2] = __halves2bfloat162(l[4], l[5]);
        ((__nv_bfloat162*)&lp)[3] = __halves2bfloat162(l[6], l[7]);
        const uint32_t so = row * AP + ch * 16;
        *(uint4*)(dsm + QA_HI + so) = hp;
        *(uint4*)(dsm + QA_LO + so) = lp;
    }

    const int wm = wid & 1, wn = wid >> 1;     // 2 m-groups x 4 n-groups (64x64)
    const int g = lane >> 3, lr = lane & 7;

    for (int w = 0; w < 6; ++w) {
        float acc[4][8][4];
#pragma unroll
        for (int mi = 0; mi < 4; ++mi)
#pragma unroll
            for (int nj = 0; nj < 8; ++nj)
#pragma unroll
                for (int r = 0; r < 4; ++r) acc[mi][nj][r] = 0.f;

        for (int kc = 0; kc < 8; ++kc) {
            const int stage = w * 8 + kc;
            cp_wait<1>();
            __syncthreads();
            const uint32_t Bst = sbase + QB0 + (stage & 1) * QB_STG;

#pragma unroll
            for (int pass = 0; pass < 3; ++pass) {
                const uint32_t Ab = sbase + (pass == 2 ? QA_LO : QA_HI);
                const uint32_t Bb = Bst + (pass == 1 ? QB_LO : 0);
#pragma unroll
                for (int k16 = 0; k16 < 2; ++k16) {
                    uint32_t afr[4][4];
#pragma unroll
                    for (int mi = 0; mi < 4; ++mi) {
                        const int row = wm * 64 + mi * 16 + ((g & 1) << 3) + lr;
                        const uint32_t addr =
                            Ab + row * AP + (kc * 4 + k16 * 2 + (g >> 1)) * 16;
                        ldsm_x4(afr[mi][0], afr[mi][1], afr[mi][2], afr[mi][3], addr);
                    }
                    uint32_t bfr[4][4];
#pragma unroll
                    for (int ni = 0; ni < 4; ++ni) {
                        const int row = wn * 64 + ni * 16 + ((g >> 1) << 3) + lr;
                        const uint32_t addr = Bb + row * GP + (k16 * 2 + (g & 1)) * 16;
                        ldsm_x4(bfr[ni][0], bfr[ni][1], bfr[ni][2], bfr[ni][3], addr);
                    }
#pragma unroll
                    for (int mi = 0; mi < 4; ++mi)
#pragma unroll
                        for (int nj = 0; nj < 8; ++nj)
                            mma_bf16(acc[mi][nj], afr[mi],
                                     bfr[nj >> 1][(nj & 1) * 2],
                                     bfr[nj >> 1][(nj & 1) * 2 + 1]);
                }
            }
            __syncthreads();
            if (stage + 2 < 48) issueB(stage + 2);
            cp_commit();
        }

        float* Yf = outs.y[w];
#pragma unroll
        for (int mi = 0; mi < 4; ++mi)
#pragma unroll
            for (int rr = 0; rr < 2; ++rr) {
                const int m = wm * 64 + mi * 16 + (lane >> 2) + rr * 8;
                const size_t yrow = abase + (size_t)m * EE;
#pragma unroll
                for (int nj = 0; nj < 8; ++nj) {
                    const int colo = wn * 64 + nj * 8 + (lane & 3) * 2;
                    *(float2*)(Yf + yrow + colo) =
                        make_float2(acc[mi][nj][rr * 2 + 0], acc[mi][nj][rr * 2 + 1]);
                }
            }
    }
}

// ---------------------------------------------------------------------------
// Generic HMMA GEMM body v2: 256(M)x128(N) block (2 b-slices), 64x64 warp tiles.
// ---------------------------------------------------------------------------
constexpr int T_A_HI = 0;
constexpr int T_A_LO = 256 * GP;              // 20480
constexpr int T_B_HI = 2 * 256 * GP;          // 40960
constexpr int T_B_LO = T_B_HI + 128 * GP;     // 51200
constexpr int STAGE  = T_B_LO + 128 * GP;     // 61440
constexpr int GEMM_SMEM = 2 * STAGE;          // 122880

template <int EPI>
__device__ __forceinline__ void gemm_body(
    const __nv_bfloat16* __restrict__ Ah, const __nv_bfloat16* __restrict__ Al,
    const __nv_bfloat16* __restrict__ Wh, const __nv_bfloat16* __restrict__ Wl,
    const float* __restrict__ bias,
    float* __restrict__ Yf,
    __nv_bfloat16* __restrict__ Yh, __nv_bfloat16* __restrict__ Yl,
    int b0, int nb, int c, uint32_t sbase)
{
    const int tid = threadIdx.x;
    const int wid = tid >> 5, lane = tid & 31;

    const size_t abase0 = ((size_t)b0 * CC + c) * SS * EE;
    const size_t bstride = (size_t)CC * SS * EE;
    const size_t wbase = (size_t)c * EE * EE + (size_t)nb * 128 * EE;

    auto issue = [&](int stg) {
        const int kb = stg * 32;
        const uint32_t sb = sbase + (stg & 1) * STAGE;
#pragma unroll
        for (int j = 0; j < 4; ++j) {
            const int t2 = tid + j * 256;
            const int row = t2 >> 2, ch = t2 & 3;
            const int bo = row >> 7, s = row & 127;
            const size_t goff = abase0 + (size_t)bo * bstride + (size_t)s * EE + kb + ch * 8;
            const uint32_t so = row * GP + ch * 16;
            cp_async16(sb + T_A_HI + so, Ah + goff);
            cp_async16(sb + T_A_LO + so, Al + goff);
        }
#pragma unroll
        for (int j = 0; j < 2; ++j) {
            const int t2 = tid + j * 256;
            const int row = t2 >> 2, ch = t2 & 3;
            const size_t goff = wbase + (size_t)row * EE + kb + ch * 8;
            const uint32_t so = row * GP + ch * 16;
            cp_async16(sb + T_B_HI + so, Wh + goff);
            cp_async16(sb + T_B_LO + so, Wl + goff);
        }
    };
    issue(0); cp_commit();
    issue(1); cp_commit();

    const int wm = wid & 3, wn = wid >> 2;
    const int g = lane >> 3, lr = lane & 7;

    float acc[4][8][4];
#pragma unroll
    for (int mi = 0; mi < 4; ++mi)
#pragma unroll
        for (int nj = 0; nj < 8; ++nj)
#pragma unroll
            for (int r = 0; r < 4; ++r) acc[mi][nj][r] = 0.f;

    for (int it = 0; it < 8; ++it) {
        cp_wait<1>();
        __syncthreads();
        const uint32_t st = sbase + (it & 1) * STAGE;

#pragma unroll
        for (int pass = 0; pass < 3; ++pass) {
            const uint32_t Ab = st + (pass == 2 ? T_A_LO : T_A_HI);
            const uint32_t Bb = st + (pass == 1 ? T_B_LO : T_B_HI);
#pragma unroll
            for (int k16 = 0; k16 < 2; ++k16) {
                uint32_t afr[4][4];
#pragma unroll
                for (int mi = 0; mi < 4; ++mi) {
                    const int row = wm * 64 + mi * 16 + ((g & 1) << 3) + lr;
                    const uint32_t addr = Ab + row * GP + (k16 * 2 + (g >> 1)) * 16;
                    ldsm_x4(afr[mi][0], afr[mi][1], afr[mi][2], afr[mi][3], addr);
                }
                uint32_t bfr[4][4];
#pragma unroll
                for (int ni = 0; ni < 4; ++ni) {
                    const int row = wn * 64 + ni * 16 + ((g >> 1) << 3) + lr;
                    const uint32_t addr = Bb + row * GP + (k16 * 2 + (g & 1)) * 16;
                    ldsm_x4(bfr[ni][0], bfr[ni][1], bfr[ni][2], bfr[ni][3], addr);
                }
#pragma unroll
                for (int mi = 0; mi < 4; ++mi)
#pragma unroll
                    for (int nj = 0; nj < 8; ++nj)
                        mma_bf16(acc[mi][nj], afr[mi],
                                 bfr[nj >> 1][(nj & 1) * 2],
                                 bfr[nj >> 1][(nj & 1) * 2 + 1]);
            }
        }
        __syncthreads();
        if (it + 2 < 8) issue(it + 2);
        cp_commit();
    }

#pragma unroll
    for (int mi = 0; mi < 4; ++mi) {
#pragma unroll
        for (int rr = 0; rr < 2; ++rr) {
            const int m = wm * 64 + mi * 16 + (lane >> 2) + rr * 8;
            const int bo = m >> 7, s = m & 127;
            const size_t yrow = abase0 + (size_t)bo * bstride + (size_t)s * EE + nb * 128;
#pragma unroll
            for (int nj = 0; nj < 8; ++nj) {
                const int col = wn * 64 + nj * 8 + (lane & 3) * 2;
                float v0 = acc[mi][nj][rr * 2 + 0];
                float v1 = acc[mi][nj][rr * 2 + 1];
                if constexpr (EPI == 0) {
                    *(float2*)(Yf + yrow + col) = make_float2(v0, v1);
                } else {
                    const float* bp = bias + (size_t)c * EE + nb * 128 + col;
                    v0 += bp[0];
                    v1 += bp[1];
                    if constexpr (EPI == 1) {
                        v0 = fmaxf(v0, 0.f);
                        v1 = fmaxf(v1, 0.f);
                        __nv_bfloat16 h0, l0, h1, l1;
                        split_bf16(v0, h0, l0);
                        split_bf16(v1, h1, l1);
                        *(__nv_bfloat162*)(Yh + yrow + col) = __halves2bfloat162(h0, h1);
                        *(__nv_bfloat162*)(Yl + yrow + col) = __halves2bfloat162(l0, l1);
                    } else {
                        *(float2*)(Yf + yrow + col) = make_float2(v0, v1);
                    }
                }
            }
        }
    }
}

template <int EPI>
__global__ __launch_bounds__(256) void gemm_mma(
    const __nv_bfloat16* __restrict__ Ah, const __nv_bfloat16* __restrict__ Al,
    const __nv_bfloat16* __restrict__ Wh, const __nv_bfloat16* __restrict__ Wl,
    const float* __restrict__ bias,
    float* __restrict__ Yf,
    __nv_bfloat16* __restrict__ Yh, __nv_bfloat16* __restrict__ Yl)
{
    extern __shared__ __align__(16) char dsm[];
    gemm_body<EPI>(Ah, Al, Wh, Wl, bias, Yf, Yh, Yl,
                   blockIdx.x * 2, blockIdx.y, blockIdx.z, smem_u32(dsm));
}

__global__ __launch_bounds__(256) void gemm_wo_pair(
    const __nv_bfloat16* __restrict__ Ah0, const __nv_bfloat16* __restrict__ Al0,
    const __nv_bfloat16* __restrict__ Wh0, const __nv_bfloat16* __restrict__ Wl0,
    float* __restrict__ Y0,
    const __nv_bfloat16* __restrict__ Ah1, const __nv_bfloat16* __restrict__ Al1,
    const __nv_bfloat16* __restrict__ Wh1, const __nv_bfloat16* __restrict__ Wl1,
    float* __restrict__ Y1)
{
    extern __shared__ __align__(16) char dsm[];
    const int zz = blockIdx.z;
    const int br = zz >= CC;
    const int c = br ? zz - CC : zz;
    gemm_body<0>(br ? Ah1 : Ah0, br ? Al1 : Al0,
                 br ? Wh1 : Wh0, br ? Wl1 : Wl0,
                 nullptr, br ? Y1 : Y0, nullptr, nullptr,
                 blockIdx.x * 2, blockIdx.y, c, smem_u32(dsm));
}

// ---------------------------------------------------------------------------
// Spatial attention (R9 winner): one block per (b,s), 8 heads, 768 thr, 2 CTA/SM.
// ---------------------------------------------------------------------------
constexpr int SA_P = 260;
constexpr int SA_SMEM = (3 * CC * SA_P + HH * CC * 25) * 4;  // 94,080 B

__global__ __launch_bounds__(768, 2) void spatial_attn(
    const float* __restrict__ q, const float* __restrict__ k,
    const float* __restrict__ v, __nv_bfloat16* __restrict__ oh,
    __nv_bfloat16* __restrict__ ol)
{
    extern __shared__ float sa[];
    float* qs = sa;
    float* ks = qs + CC * SA_P;
    float* vs = ks + CC * SA_P;
    float* sc = vs + CC * SA_P;

    const int s = blockIdx.x, b = blockIdx.y;
    const int t = threadIdx.x;
    const size_t gbase = ((size_t)b * CC * SS + s) * EE;
    const size_t cstride = (size_t)SS * EE;

#pragma unroll
    for (int i = 0; i < 2; ++i) {
        const int idx = t + i * 768;
        const int row = idx >> 6, e4 = idx & 63;
        const size_t g = gbase + row * cstride + e4 * 4;
        const int so = row * SA_P + e4 * 4;
        *(float4*)(qs + so) = *(const float4*)(q + g);
        *(float4*)(ks + so) = *(const float4*)(k + g);
        *(float4*)(vs + so) = *(const float4*)(v + g);
    }
    __syncthreads();

    {
        const int h = t / 96;
        const int r = t - h * 96;
        const int cig = r >> 3, dig = r & 7;
        const int ci0 = cig * 2, di0 = dig * 3;
        const float* qb = qs + ci0 * SA_P + h * 32;
        const float* kb = ks + di0 * SA_P + h * 32;
        float a00 = 0.f, a01 = 0.f, a02 = 0.f;
        float a10 = 0.f, a11 = 0.f, a12 = 0.f;
#pragma unroll
        for (int p = 0; p < 32; ++p) {
            const float q0 = qb[p], q1 = qb[SA_P + p];
            const float k0 = kb[p], k1 = kb[SA_P + p], k2 = kb[2 * SA_P + p];
            a00 = fmaf(q0, k0, a00); a01 = fmaf(q0, k1, a01); a02 = fmaf(q0, k2, a02);
            a10 = fmaf(q1, k0, a10); a11 = fmaf(q1, k1, a11); a12 = fmaf(q1, k2, a12);
        }
        float* sr0 = sc + (h * CC + ci0) * 25 + di0;
        float* sr1 = sr0 + 25;
        sr0[0] = a00 * INV_SQRT_P; sr0[1] = a01 * INV_SQRT_P; sr0[2] = a02 * INV_SQRT_P;
        sr1[0] = a10 * INV_SQRT_P; sr1[1] = a11 * INV_SQRT_P; sr1[2] = a12 * INV_SQRT_P;
    }
    __syncthreads();

    if (t < HH * CC) {
        float* row = sc + t * 25;
        float mx = -1e30f;
#pragma unroll
        for (int d = 0; d < CC; ++d) mx = fmaxf(mx, row[d]);
        float sm = 0.f;
#pragma unroll
        for (int d = 0; d < CC; ++d) { float e = __expf(row[d] - mx); row[d] = e; sm += e; }
        const float inv = 1.f / sm;
#pragma unroll
        for (int d = 0; d < CC; ++d) row[d] *= inv;
    }
    __syncthreads();

#pragma unroll
    for (int i = 0; i < 2; ++i) {
        const int item = t + i * 768;
        const int h = item / 192;
        const int rr = item - h * 192;
        const int cc = rr >> 3, p4 = (rr & 7) * 4;
        const float* arow = sc + (h * CC + cc) * 25;
        const float* vb = vs + h * 32 + p4;
        float s0 = 0.f, s1 = 0.f, s2 = 0.f, s3 = 0.f;
#pragma unroll
        for (int d = 0; d < CC; ++d) {
            const float a = arow[d];
            const float4 vv = *(const float4*)(vb + d * SA_P);
            s0 = fmaf(a, vv.x, s0); s1 = fmaf(a, vv.y, s1);
            s2 = fmaf(a, vv.z, s2); s3 = fmaf(a, vv.w, s3);
        }
        const size_t g = gbase + cc * cstride + h * 32 + p4;
        __nv_bfloat16 h0, l0, h1, l1, h2, l2, h3, l3;
        split_bf16(s0, h0, l0); split_bf16(s1, h1, l1);
        split_bf16(s2, h2, l2); split_bf16(s3, h3, l3);
        *(__nv_bfloat162*)(oh + g)     = __halves2bfloat162(h0, h1);
        *(__nv_bfloat162*)(oh + g + 2) = __halves2bfloat162(h2, h3);
        *(__nv_bfloat162*)(ol + g)     = __halves2bfloat162(l0, l1);
        *(__nv_bfloat162*)(ol + g + 2) = __halves2bfloat162(l2, l3);
    }
}

// ---------------------------------------------------------------------------
// Temporal attention v3 — tensor-core flash-style (R12 winner).
// ---------------------------------------------------------------------------
constexpr int TQT_HI = 0;
constexpr int TQT_LO = 128 * GP;             // 10240
constexpr int TKT_HI = 2 * 128 * GP;         // 20480
constexpr int TKT_LO = 3 * 128 * GP;         // 30720
constexpr int TVS_HI = 4 * 128 * GP;         // 40960
constexpr int TVP = 272;                     // V^T pitch (bytes)
constexpr int TVS_LO = TVS_HI + 32 * TVP;    // 49664
constexpr int TEMP_SMEM_BYTES = TVS_LO + 32 * TVP;  // 58368

__global__ __launch_bounds__(256, 2) void temporal_attn(
    const float* __restrict__ q, const float* __restrict__ k,
    const float* __restrict__ v, __nv_bfloat16* __restrict__ oh,
    __nv_bfloat16* __restrict__ ol)
{
    extern __shared__ __align__(16) char tsm[];
    const uint32_t sb = smem_u32(tsm);
    const int c = blockIdx.x, h = blockIdx.y, b = blockIdx.z;
    const int tid = threadIdx.x;
    const int wid = tid >> 5, lane = tid & 31;
    const size_t base = (((size_t)b * CC + c) * SS) * EE + h * PP;

#pragma unroll
    for (int i = 0; i < 4; ++i) {
        const int idx = tid + i * 256;
        const int row = idx >> 3, p4 = (idx & 7) * 4;
        const size_t g = base + (size_t)row * EE + p4;
        {
            float4 vq = *(const float4*)(q + g);
            __nv_bfloat16 hh[4], ll[4];
            split_bf16(vq.x, hh[0], ll[0]); split_bf16(vq.y, hh[1], ll[1]);
            split_bf16(vq.z, hh[2], ll[2]); split_bf16(vq.w, hh[3], ll[3]);
            uint2 hp, lp;
            ((__nv_bfloat162*)&hp)[0] = __halves2bfloat162(hh[0], hh[1]);
            ((__nv_bfloat162*)&hp)[1] = __halves2bfloat162(hh[2], hh[3]);
            ((__nv_bfloat162*)&lp)[0] = __halves2bfloat162(ll[0], ll[1]);
            ((__nv_bfloat162*)&lp)[1] = __halves2bfloat162(ll[2], ll[3]);
            *(uint2*)(tsm + TQT_HI + row * GP + p4 * 2) = hp;
            *(uint2*)(tsm + TQT_LO + row * GP + p4 * 2) = lp;
        }
        {
            float4 vk = *(const float4*)(k + g);
            __nv_bfloat16 hh[4], ll[4];
            split_bf16(vk.x, hh[0], ll[0]); split_bf16(vk.y, hh[1], ll[1]);
            split_bf16(vk.z, hh[2], ll[2]); split_bf16(vk.w, hh[3], ll[3]);
            uint2 hp, lp;
            ((__nv_bfloat162*)&hp)[0] = __halves2bfloat162(hh[0], hh[1]);
            ((__nv_bfloat162*)&hp)[1] = __halves2bfloat162(hh[2], hh[3]);
            ((__nv_bfloat162*)&lp)[0] = __halves2bfloat162(ll[0], ll[1]);
            ((__nv_bfloat162*)&lp)[1] = __halves2bfloat162(ll[2], ll[3]);
            *(uint2*)(tsm + TKT_HI + row * GP + p4 * 2) = hp;
            *(uint2*)(tsm + TKT_LO + row * GP + p4 * 2) = lp;
        }
        {
            float4 vv = *(const float4*)(v + g);
            float vf[4] = {vv.x, vv.y, vv.z, vv.w};
#pragma unroll
            for (int j = 0; j < 4; ++j) {
                __nv_bfloat16 hi, lo;
                split_bf16(vf[j], hi, lo);
                *(__nv_bfloat16*)(tsm + TVS_HI + (p4 + j) * TVP + row * 2) = hi;
                *(__nv_bfloat16*)(tsm + TVS_LO + (p4 + j) * TVP + row * 2) = lo;
            }
        }
    }
    __syncthreads();

    const int g2 = lane >> 3, lr = lane & 7;

    float sacc[16][4];
#pragma unroll
    for (int nj = 0; nj < 16; ++nj)
#pragma unroll
        for (int r = 0; r < 4; ++r) sacc[nj][r] = 0.f;

#pragma unroll
    for (int pass = 0; pass < 3; ++pass) {
        const uint32_t Ab = sb + (pass == 2 ? TQT_LO : TQT_HI);
        const uint32_t Bb = sb + (pass == 1 ? TKT_LO : TKT_HI);
#pragma unroll
        for (int k16 = 0; k16 < 2; ++k16) {
            uint32_t afr[4];
            {
                const int row = wid * 16 + ((g2 & 1) << 3) + lr;
                const uint32_t addr = Ab + row * GP + (k16 * 2 + (g2 >> 1)) * 16;
                ldsm_x4(afr[0], afr[1], afr[2], afr[3], addr);
            }
#pragma unroll
            for (int ni = 0; ni < 8; ++ni) {
                uint32_t bfr[4];
                const int row = ni * 16 + ((g2 >> 1) << 3) + lr;
                const uint32_t addr = Bb + row * GP + (k16 * 2 + (g2 & 1)) * 16;
                ldsm_x4(bfr[0], bfr[1], bfr[2], bfr[3], addr);
                mma_bf16(sacc[ni * 2 + 0], afr, bfr[0], bfr[1]);
                mma_bf16(sacc[ni * 2 + 1], afr, bfr[2], bfr[3]);
            }
        }
    }

#pragma unroll
    for (int nj = 0; nj < 16; ++nj)
#pragma unroll
        for (int r = 0; r < 4; ++r) sacc[nj][r] *= INV_SQRT_P;

    float mx0 = -1e30f, mx1 = -1e30f;
#pragma unroll
    for (int nj = 0; nj < 16; ++nj) {
        mx0 = fmaxf(mx0, fmaxf(sacc[nj][0], sacc[nj][1]));
        mx1 = fmaxf(mx1, fmaxf(sacc[nj][2], sacc[nj][3]));
    }
    mx0 = fmaxf(mx0, __shfl_xor_sync(0xffffffffu, mx0, 1));
    mx0 = fmaxf(mx0, __shfl_xor_sync(0xffffffffu, mx0, 2));
    mx1 = fmaxf(mx1, __shfl_xor_sync(0xffffffffu, mx1, 1));
    mx1 = fmaxf(mx1, __shfl_xor_sync(0xffffffffu, mx1, 2));

    float sum0 = 0.f, sum1 = 0.f;
#pragma unroll
    for (int nj = 0; nj < 16; ++nj) {
        sacc[nj][0] = __expf(sacc[nj][0] - mx0);
        sacc[nj][1] = __expf(sacc[nj][1] - mx0);
        sacc[nj][2] = __expf(sacc[nj][2] - mx1);
        sacc[nj][3] = __expf(sacc[nj][3] - mx1);
        sum0 += sacc[nj][0] + sacc[nj][1];
        sum1 += sacc[nj][2] + sacc[nj][3];
    }
    sum0 += __shfl_xor_sync(0xffffffffu, sum0, 1);
    sum0 += __shfl_xor_sync(0xffffffffu, sum0, 2);
    sum1 += __shfl_xor_sync(0xffffffffu, sum1, 1);
    sum1 += __shfl_xor_sync(0xffffffffu, sum1, 2);
    const float inv0 = 1.f / sum0, inv1 = 1.f / sum1;
#pragma unroll
    for (int nj = 0; nj < 16; ++nj) {
        sacc[nj][0] *= inv0;
        sacc[nj][1] *= inv0;
        sacc[nj][2] *= inv1;
        sacc[nj][3] *= inv1;
    }

    float oacc[4][4];
#pragma unroll
    for (int nj = 0; nj < 4; ++nj)
#pragma unroll
        for (int r = 0; r < 4; ++r) oacc[nj][r] = 0.f;

#pragma unroll
    for (int pass = 0; pass < 3; ++pass) {
        const uint32_t Bb = sb + (pass == 1 ? TVS_LO : TVS_HI);
#pragma unroll
        for (int ki = 0; ki < 8; ++ki) {
            uint32_t a[4];
            if (pass <= 1) {
                a[0] = pack_bf16x2(sacc[2 * ki][0],     sacc[2 * ki][1]);
                a[1] = pack_bf16x2(sacc[2 * ki][2],     sacc[2 * ki][3]);
                a[2] = pack_bf16x2(sacc[2 * ki + 1][0], sacc[2 * ki + 1][1]);
                a[3] = pack_bf16x2(sacc[2 * ki + 1][2], sacc[2 * ki + 1][3]);
            } else {
                a[0] = pack_bf16x2(bf16_lo_res(sacc[2 * ki][0]),     bf16_lo_res(sacc[2 * ki][1]));
                a[1] = pack_bf16x2(bf16_lo_res(sacc[2 * ki][2]),     bf16_lo_res(sacc[2 * ki][3]));
                a[2] = pack_bf16x2(bf16_lo_res(sacc[2 * ki + 1][0]), bf16_lo_res(sacc[2 * ki + 1][1]));
                a[3] = pack_bf16x2(bf16_lo_res(sacc[2 * ki + 1][2]), bf16_lo_res(sacc[2 * ki + 1][3]));
            }
#pragma unroll
            for (int half = 0; half < 2; ++half) {
                uint32_t bfr[4];
                const int row = half * 16 + ((g2 >> 1) << 3) + lr;
                const uint32_t addr = Bb + row * TVP + (ki * 2 + (g2 & 1)) * 16;
                ldsm_x4(bfr[0], bfr[1], bfr[2], bfr[3], addr);
                mma_bf16(oacc[half * 2 + 0], a, bfr[0], bfr[1]);
                mma_bf16(oacc[half * 2 + 1], a, bfr[2], bfr[3]);
            }
        }
    }

    const int r0 = wid * 16 + (lane >> 2);
    const int r1 = r0 + 8;
#pragma unroll
    for (int nj = 0; nj < 4; ++nj) {
        const int col = nj * 8 + (lane & 3) * 2;
        const size_t g0 = base + (size_t)r0 * EE + col;
        const size_t g1 = base + (size_t)r1 * EE + col;
        __nv_bfloat16 h0, l0, h1, l1;
        split_bf16(oacc[nj][0], h0, l0);
        split_bf16(oacc[nj][1], h1, l1);
        *(__nv_bfloat162*)(oh + g0) = __halves2bfloat162(h0, h1);
        *(__nv_bfloat162*)(ol + g0) = __halves2bfloat162(l0, l1);
        split_bf16(oacc[nj][2], h0, l0);
        split_bf16(oacc[nj][3], h1, l1);
        *(__nv_bfloat162*)(oh + g1) = __halves2bfloat162(h0, h1);
        *(__nv_bfloat162*)(ol + g1) = __halves2bfloat162(l0, l1);
    }
}

// ---------------------------------------------------------------------------
// LayerNorm kernels — warp-per-row.
// ---------------------------------------------------------------------------
__device__ __forceinline__ float warp_sum(float v) {
#pragma unroll
    for (int off = 16; off > 0; off >>= 1)
        v += __shfl_xor_sync(0xffffffffu, v, off);
    return v;
}

__global__ __launch_bounds__(256) void dual_ln(
    const float* __restrict__ x, const float* __restrict__ a,
    const float* __restrict__ b2, const float* __restrict__ g,
    const float* __restrict__ beta, float* __restrict__ out,
    __nv_bfloat16* __restrict__ oh, __nv_bfloat16* __restrict__ ol)
{
    const int warp = threadIdx.x >> 5, lane = threadIdx.x & 31;
    const int row = blockIdx.x * 8 + warp;
    const size_t base = (size_t)row * EE;
    const int e0 = lane * 4, e1 = 128 + lane * 4;

    float4 x0 = *(const float4*)(x + base + e0);
    float4 x1 = *(const float4*)(x + base + e1);
    float4 a0 = *(const float4*)(a + base + e0);
    float4 a1 = *(const float4*)(a + base + e1);
    float4 b0 = *(const float4*)(b2 + base + e0);
    float4 b1 = *(const float4*)(b2 + base + e1);

    float v1[8] = {x0.x + a0.x, x0.y + a0.y, x0.z + a0.z, x0.w + a0.w,
                   x1.x + a1.x, x1.y + a1.y, x1.z + a1.z, x1.w + a1.w};
    float v2[8] = {x0.x + b0.x, x0.y + b0.y, x0.z + b0.z, x0.w + b0.w,
                   x1.x + b1.x, x1.y + b1.y, x1.z + b1.z, x1.w + b1.w};

    float s1 = 0.f, q1 = 0.f, s2 = 0.f, q2 = 0.f;
#pragma unroll
    for (int j = 0; j < 8; ++j) {
        s1 += v1[j]; q1 = fmaf(v1[j], v1[j], q1);
        s2 += v2[j]; q2 = fmaf(v2[j], v2[j], q2);
    }
    s1 = warp_sum(s1); q1 = warp_sum(q1);
    s2 = warp_sum(s2); q2 = warp_sum(q2);

    const float invE = 1.f / (float)EE;
    const float m1 = s1 * invE, m2 = s2 * invE;
    const float r1 = rsqrtf(fmaxf(q1 * invE - m1 * m1, 0.f) + LN_EPS);
    const float r2 = rsqrtf(fmaxf(q2 * invE - m2 * m2, 0.f) + LN_EPS);

    float4 g0 = *(const float4*)(g + e0);
    float4 g1 = *(const float4*)(g + e1);
    float4 t0 = *(const float4*)(beta + e0);
    float4 t1 = *(const float4*)(beta + e1);
    float gg[8] = {g0.x, g0.y, g0.z, g0.w, g1.x, g1.y, g1.z, g1.w};
    float bt[8] = {t0.x, t0.y, t0.z, t0.w, t1.x, t1.y, t1.z, t1.w};

    float o[8];
#pragma unroll
    for (int j = 0; j < 8; ++j)
        o[j] = (v1[j] - m1) * r1 * gg[j] + bt[j]
             + (v2[j] - m2) * r2 * gg[j] + bt[j];

    *(float4*)(out + base + e0) = make_float4(o[0], o[1], o[2], o[3]);
    *(float4*)(out + base + e1) = make_float4(o[4], o[5], o[6], o[7]);

    __nv_bfloat16 hh[8], ll[8];
#pragma unroll
    for (int j = 0; j < 8; ++j) split_bf16(o[j], hh[j], ll[j]);
    *(__nv_bfloat162*)(oh + base + e0)     = __halves2bfloat162(hh[0], hh[1]);
    *(__nv_bfloat162*)(oh + base + e0 + 2) = __halves2bfloat162(hh[2], hh[3]);
    *(__nv_bfloat162*)(oh + base + e1)     = __halves2bfloat162(hh[4], hh[5]);
    *(__nv_bfloat162*)(oh + base + e1 + 2) = __halves2bfloat162(hh[6], hh[7]);
    *(__nv_bfloat162*)(ol + base + e0)     = __halves2bfloat162(ll[0], ll[1]);
    *(__nv_bfloat162*)(ol + base + e0 + 2) = __halves2bfloat162(ll[2], ll[3]);
    *(__nv_bfloat162*)(ol + base + e1)     = __halves2bfloat162(ll[4], ll[5]);
    *(__nv_bfloat162*)(ol + base + e1 + 2) = __halves2bfloat162(ll[6], ll[7]);
}

__global__ __launch_bounds__(256) void final_ln(
    const float* __restrict__ a, const float* __restrict__ f,
    const float* __restrict__ g, const float* __restrict__ beta,
    float* __restrict__ out)
{
    const int warp = threadIdx.x >> 5, lane = threadIdx.x & 31;
    const int row = blockIdx.x * 8 + warp;
    const size_t base = (size_t)row * EE;
    const int e0 = lane * 4, e1 = 128 + lane * 4;

    float4 a0 = *(const float4*)(a + base + e0);
    float4 a1 = *(const float4*)(a + base + e1);
    float4 f0 = *(const float4*)(f + base + e0);
    float4 f1 = *(const float4*)(f + base + e1);

    float v[8] = {a0.x + f0.x, a0.y + f0.y, a0.z + f0.z, a0.w + f0.w,
                  a1.x + f1.x, a1.y + f1.y, a1.z + f1.z, a1.w + f1.w};

    float s = 0.f, q = 0.f;
#pragma unroll
    for (int j = 0; j < 8; ++j) { s += v[j]; q = fmaf(v[j], v[j], q); }
    s = warp_sum(s); q = warp_sum(q);

    const float invE = 1.f / (float)EE;
    const float m = s * invE;
    const float r = rsqrtf(fmaxf(q * invE - m * m, 0.f) + LN_EPS);

    float4 g0 = *(const float4*)(g + e0);
    float4 g1 = *(const float4*)(g + e1);
    float4 t0 = *(const float4*)(beta + e0);
    float4 t1 = *(const float4*)(beta + e1);
    float gg[8] = {g0.x, g0.y, g0.z, g0.w, g1.x, g1.y, g1.z, g1.w};
    float bt[8] = {t0.x, t0.y, t0.z, t0.w, t1.x, t1.y, t1.z, t1.w};

    float o[8];
#pragma unroll
    for (int j = 0; j < 8; ++j) o[j] = (v[j] - m) * r * gg[j] + bt[j];
    *(float4*)(out + base + e0) = make_float4(o[0], o[1], o[2], o[3]);
    *(float4*)(out + base + e1) = make_float4(o[4], o[5], o[6], o[7]);
}

// ---------------------------------------------------------------------------
// kernel_launch
// ---------------------------------------------------------------------------
extern "C" void kernel_launch(void* const* d_in, const int* in_sizes, int n_in,
                              void* d_out, int out_size)
{
    const float* x    = (const float*)d_in[0];
    const float* ln_g = (const float*)d_in[9];
    const float* ln_b = (const float*)d_in[10];
    const float* ff_b1 = (const float*)d_in[12];
    const float* ff_b2 = (const float*)d_in[14];
    float* out = (float*)d_out;

    float *qs, *ks, *vs, *qt, *kt, *vt, *spat, *temp, *attn, *ffo;
    __nv_bfloat16 *ah, *al, *hh, *hl, *wh, *wl;
    cudaGetSymbolAddress((void**)&qs,   g_qs);
    cudaGetSymbolAddress((void**)&ks,   g_ks);
    cudaGetSymbolAddress((void**)&vs,   g_vs);
    cudaGetSymbolAddress((void**)&qt,   g_qt);
    cudaGetSymbolAddress((void**)&kt,   g_kt);
    cudaGetSymbolAddress((void**)&vt,   g_vt);
    cudaGetSymbolAddress((void**)&spat, g_spat);
    cudaGetSymbolAddress((void**)&temp, g_temp);
    cudaGetSymbolAddress((void**)&attn, g_attn);
    cudaGetSymbolAddress((void**)&ffo,  g_ffo);
    cudaGetSymbolAddress((void**)&ah, g_ah);
    cudaGetSymbolAddress((void**)&al, g_al);
    cudaGetSymbolAddress((void**)&hh, g_hh);
    cudaGetSymbolAddress((void**)&hl, g_hl);
    cudaGetSymbolAddress((void**)&wh, g_wh);
    cudaGetSymbolAddress((void**)&wl, g_wl);

    cudaFuncSetAttribute(gemm_qkv6,   cudaFuncAttributeMaxDynamicSharedMemorySize, QKV_SMEM);
    cudaFuncSetAttribute(gemm_mma<1>, cudaFuncAttributeMaxDynamicSharedMemorySize, GEMM_SMEM);
    cudaFuncSetAttribute(gemm_mma<2>, cudaFuncAttributeMaxDynamicSharedMemorySize, GEMM_SMEM);
    cudaFuncSetAttribute(gemm_wo_pair, cudaFuncAttributeMaxDynamicSharedMemorySize, GEMM_SMEM);
    cudaFuncSetAttribute(spatial_attn, cudaFuncAttributeMaxDynamicSharedMemorySize, SA_SMEM);
    cudaFuncSetAttribute(temporal_attn, cudaFuncAttributeMaxDynamicSharedMemorySize, TEMP_SMEM_BYTES);

    // ---- weight conversion ----
    WPtrs wp;
    wp.p[0] = (const float*)d_in[1];
    wp.p[1] = (const float*)d_in[2];
    wp.p[2] = (const float*)d_in[3];
    wp.p[3] = (const float*)d_in[4];
    wp.p[4] = (const float*)d_in[5];
    wp.p[5] = (const float*)d_in[6];
    wp.p[6] = (const float*)d_in[7];
    wp.p[7] = (const float*)d_in[8];
    wp.p[8] = (const float*)d_in[11];
    wp.p[9] = (const float*)d_in[13];
    convert_weights_t<<<dim3(64, CC, NW), 256>>>(wp, wh, wl);

    // ---- fused q/k/v projections (x split in-kernel; N=256 blocks) ----
    Out6 o6;
    o6.y[0] = qs; o6.y[1] = ks; o6.y[2] = vs;
    o6.y[3] = qt; o6.y[4] = kt; o6.y[5] = vt;
    gemm_qkv6<<<dim3(BB, 1, CC), 256, QKV_SMEM>>>(x, wh, wl, o6);

    // ---- attentions ----
    spatial_attn<<<dim3(SS, BB), 768, SA_SMEM>>>(qs, ks, vs, ah, al);
    temporal_attn<<<dim3(CC, HH, BB), 256, TEMP_SMEM_BYTES>>>(qt, kt, vt, hh, hl);

    // ---- output projections (merged dual launch, M=256 blocks) ----
    gemm_wo_pair<<<dim3(BB / 2, 2, 2 * CC), 256, GEMM_SMEM>>>(
        ah, al, wh + 3*(size_t)WELEMS, wl + 3*(size_t)WELEMS, spat,
        hh, hl, wh + 7*(size_t)WELEMS, wl + 7*(size_t)WELEMS, temp);

    // ---- residual + dual LN (emits attn fp32 + bf16 pair) ----
    dual_ln<<<NROWS / 8, 256>>>(x, spat, temp, ln_g, ln_b, attn, ah, al);

    // ---- per-joint FF + final LN ----
    gemm_mma<1><<<dim3(BB / 2, 2, CC), 256, GEMM_SMEM>>>(ah, al, wh + 8*(size_t)WELEMS, wl + 8*(size_t)WELEMS, ff_b1, nullptr, hh, hl);
    gemm_mma<2><<<dim3(BB / 2, 2, CC), 256, GEMM_SMEM>>>(hh, hl, wh + 9*(size_t)WELEMS, wl + 9*(size_t)WELEMS, ff_b2, ffo, nullptr, nullptr);
    final_ln<<<NROWS / 8, 256>>>(attn, ffo, ln_g, ln_b, out);
}